// round 1
// baseline (speedup 1.0000x reference)
#include <cuda_runtime.h>

#define BATCH 8
#define C 128
#define H 128
#define W 128
#define HW (H*W)
#define K3 1152   // 9 * C, K-order: k = r*128 + c_in, r = ki*3+kj

typedef unsigned long long ull;

// ---------------- scratch (device globals; no allocation allowed) ----------
__device__ float g_y1  [BATCH*C*HW];   // raw conv1 output (pre-norm)
__device__ float g_out1[BATCH*C*HW];   // conv2(t)+b
__device__ float g_m   [BATCH*C*HW];   // sigmoid(mask conv)
__device__ float g_q   [BATCH*C*HW];
__device__ float g_k   [BATCH*C*HW];
__device__ float g_v   [BATCH*C*HW];
__device__ float g_mu  [BATCH*C];
__device__ float g_rsig[BATCH*C];
__device__ float g_wT3 [3][K3*C];      // transposed 3x3 weights [k][m]
__device__ float g_wT1 [3][C*C];       // transposed 1x1 weights [k][m]

#define FMA2(d,a,b) asm("fma.rn.f32x2 %0, %1, %2, %0;" : "+l"(d) : "l"(a), "l"(b))

// ---------------- weight transpose -----------------------------------------
__global__ void transpose_weights(const float* __restrict__ w1,
                                  const float* __restrict__ w2,
                                  const float* __restrict__ wm,
                                  const float* __restrict__ wq,
                                  const float* __restrict__ wk,
                                  const float* __restrict__ wv)
{
    int i = blockIdx.x * blockDim.x + threadIdx.x;
    if (i < K3*C) {
        int k = i / C, m = i % C;          // dest index i = k*C + m
        int r = k >> 7, c = k & 127;       // k = r*128 + c
        int src = m*K3 + c*9 + r;          // w[m][c][ki][kj]
        g_wT3[0][i] = w1[src];
        g_wT3[1][i] = w2[src];
        g_wT3[2][i] = wm[src];
    }
    if (i < C*C) {
        int k = i / C, m = i % C;
        g_wT1[0][i] = wq[m*C + k];
        g_wT1[1][i] = wk[m*C + k];
        g_wT1[2][i] = wv[m*C + k];
    }
}

// ---------------- per-(b,c) instance-norm stats -----------------------------
__global__ void stats_kernel()
{
    int bc = blockIdx.x;
    const float4* p = (const float4*)(g_y1 + (size_t)bc * HW);
    float s = 0.f, sq = 0.f;
    for (int i = threadIdx.x; i < HW/4; i += blockDim.x) {
        float4 v = p[i];
        s  += (v.x + v.y) + (v.z + v.w);
        sq += v.x*v.x + v.y*v.y + v.z*v.z + v.w*v.w;
    }
    #pragma unroll
    for (int o = 16; o; o >>= 1) {
        s  += __shfl_xor_sync(0xffffffffu, s,  o);
        sq += __shfl_xor_sync(0xffffffffu, sq, o);
    }
    __shared__ float ss[8], sqq[8];
    int wrp = threadIdx.x >> 5;
    if ((threadIdx.x & 31) == 0) { ss[wrp] = s; sqq[wrp] = sq; }
    __syncthreads();
    if (threadIdx.x == 0) {
        float S = 0.f, Q = 0.f;
        #pragma unroll
        for (int i = 0; i < 8; i++) { S += ss[i]; Q += sqq[i]; }
        float mu  = S / (float)HW;
        float var = Q / (float)HW - mu*mu;
        g_mu[bc]   = mu;
        g_rsig[bc] = rsqrtf(var + 1e-5f);
    }
}

// ---------------- 3x3 conv as implicit GEMM (f32x2 core) -------------------
// Block: 128 c_out x 128-pixel tile (4 rows x 32 cols), K = 1152, BK = 8.
// NORM: input is g_y1, apply (v - mu)*rsig then LeakyReLU(0.2) on the fly.
// SIGM: apply sigmoid in epilogue (mask conv).
template<bool NORM, bool SIGM>
__global__ void __launch_bounds__(256, 2)
conv3x3_kernel(const float* __restrict__ xin, int wsel,
               const float* __restrict__ bias, int osel)
{
    const float* in  = NORM ? (const float*)g_y1 : xin;
    float* out = (osel == 0) ? g_y1 : ((osel == 1) ? g_out1 : g_m);
    const float* wT  = g_wT3[wsel];

    const int b  = blockIdx.y;
    const int h0 = (blockIdx.x >> 2) * 4;
    const int w0 = (blockIdx.x & 3) * 32;

    __shared__ float As[2][8][256];   // duplicated pairs for f32x2
    __shared__ float Bs[2][8][128];

    const int tid = threadIdx.x;
    const int tm  = tid >> 4, tn = tid & 15;
    const int lr  = tid >> 5;            // load row 0..7 (k within chunk)
    const int lc  = (tid & 31) * 4;      // load col 0..124
    const int dh  = lc >> 5, dwp = lc & 31;

    const float* mup = g_mu   + b*C;
    const float* rsp = g_rsig + b*C;

    ull acc[8][4];
    #pragma unroll
    for (int i = 0; i < 8; i++)
        #pragma unroll
        for (int j = 0; j < 4; j++) acc[i][j] = 0ull;

    float4 aReg;
    float  bReg[4];

    auto loadg = [&](int kt) {
        int kk = kt*8 + lr;
        aReg = *(const float4*)(wT + kk*C + lc);
        int r = kk >> 7, c = kk & 127;
        int hh  = h0 + dh  + (r/3) - 1;
        int wwb = w0 + dwp + (r%3) - 1;
        const float* src = in + ((size_t)b*C + c)*HW + (size_t)hh*W;
        float mu = NORM ? mup[c] : 0.f;
        float rs = NORM ? rsp[c] : 0.f;
        bool hok = (hh >= 0) && (hh < H);
        #pragma unroll
        for (int j = 0; j < 4; j++) {
            int wj = wwb + j;
            float v = 0.f;
            if (hok && wj >= 0 && wj < W) {
                v = src[wj];
                if (NORM) { v = (v - mu)*rs; v = (v < 0.f) ? 0.2f*v : v; }
            }
            bReg[j] = v;
        }
    };
    auto store_s = [&](int bi) {
        *(float4*)&As[bi][lr][lc*2]     = make_float4(aReg.x, aReg.x, aReg.y, aReg.y);
        *(float4*)&As[bi][lr][lc*2 + 4] = make_float4(aReg.z, aReg.z, aReg.w, aReg.w);
        *(float4*)&Bs[bi][lr][lc]       = make_float4(bReg[0], bReg[1], bReg[2], bReg[3]);
    };

    loadg(0); store_s(0);
    __syncthreads();

    const int NKT = K3 / 8;   // 144
    int buf = 0;
    for (int kt = 0; kt < NKT; kt++) {
        if (kt + 1 < NKT) loadg(kt + 1);
        #pragma unroll
        for (int kk = 0; kk < 8; kk++) {
            const float* ar = &As[buf][kk][tm*16];
            const float* br = &Bs[buf][kk][tn*8];
            ulonglong2 A0 = *(const ulonglong2*)(ar);
            ulonglong2 A1 = *(const ulonglong2*)(ar + 4);
            ulonglong2 A2 = *(const ulonglong2*)(ar + 8);
            ulonglong2 A3 = *(const ulonglong2*)(ar + 12);
            ulonglong2 B0 = *(const ulonglong2*)(br);
            ulonglong2 B1 = *(const ulonglong2*)(br + 4);
            ull av[8] = {A0.x, A0.y, A1.x, A1.y, A2.x, A2.y, A3.x, A3.y};
            ull bv[4] = {B0.x, B0.y, B1.x, B1.y};
            #pragma unroll
            for (int i = 0; i < 8; i++)
                #pragma unroll
                for (int j = 0; j < 4; j++)
                    FMA2(acc[i][j], av[i], bv[j]);
        }
        if (kt + 1 < NKT) {
            buf ^= 1;
            store_s(buf);
            __syncthreads();
        }
    }

    const int n0 = tn*8;
    float* dbase = out + ((size_t)b*C)*HW + (size_t)(h0 + (n0 >> 5))*W + (w0 + (n0 & 31));
    #pragma unroll
    for (int i = 0; i < 8; i++) {
        int m = tm*8 + i;
        float bb = bias[m];
        float* dst = dbase + (size_t)m*HW;
        #pragma unroll
        for (int j = 0; j < 4; j++) {
            ull a = acc[i][j];
            float v0 = __uint_as_float((unsigned)a)          + bb;
            float v1 = __uint_as_float((unsigned)(a >> 32))  + bb;
            if (SIGM) {
                v0 = 1.f / (1.f + __expf(-v0));
                v1 = 1.f / (1.f + __expf(-v1));
            }
            dst[2*j]     = v0;
            dst[2*j + 1] = v1;
        }
    }
}

// ---------------- 1x1 q/k/v GEMM (input xm = leaky(norm(y1)) * m) ----------
__global__ void __launch_bounds__(256, 2)
qkv_kernel(const float* __restrict__ qb, const float* __restrict__ kb,
           const float* __restrict__ vb)
{
    const int b    = blockIdx.y;
    const int set  = blockIdx.z;
    const int pix0 = blockIdx.x * 128;
    const float* wT   = g_wT1[set];
    const float* bias = (set == 0) ? qb : ((set == 1) ? kb : vb);
    float* out  = (set == 0) ? g_q : ((set == 1) ? g_k : g_v);

    __shared__ float As[2][8][256];
    __shared__ float Bs[2][8][128];

    const int tid = threadIdx.x;
    const int tm = tid >> 4, tn = tid & 15;
    const int lr = tid >> 5;
    const int lc = (tid & 31) * 4;

    const float* mup = g_mu   + b*C;
    const float* rsp = g_rsig + b*C;

    ull acc[8][4];
    #pragma unroll
    for (int i = 0; i < 8; i++)
        #pragma unroll
        for (int j = 0; j < 4; j++) acc[i][j] = 0ull;

    float4 aReg;
    float  bReg[4];

    auto loadg = [&](int kt) {
        int c = kt*8 + lr;
        aReg = *(const float4*)(wT + c*C + lc);
        size_t base = ((size_t)b*C + c)*HW + pix0 + lc;
        float4 y  = *(const float4*)(g_y1 + base);
        float4 mm = *(const float4*)(g_m  + base);
        float mu = mup[c], rs = rsp[c];
        float t0 = (y.x - mu)*rs; t0 = (t0 < 0.f) ? 0.2f*t0 : t0;
        float t1 = (y.y - mu)*rs; t1 = (t1 < 0.f) ? 0.2f*t1 : t1;
        float t2 = (y.z - mu)*rs; t2 = (t2 < 0.f) ? 0.2f*t2 : t2;
        float t3 = (y.w - mu)*rs; t3 = (t3 < 0.f) ? 0.2f*t3 : t3;
        bReg[0] = t0*mm.x; bReg[1] = t1*mm.y; bReg[2] = t2*mm.z; bReg[3] = t3*mm.w;
    };
    auto store_s = [&](int bi) {
        *(float4*)&As[bi][lr][lc*2]     = make_float4(aReg.x, aReg.x, aReg.y, aReg.y);
        *(float4*)&As[bi][lr][lc*2 + 4] = make_float4(aReg.z, aReg.z, aReg.w, aReg.w);
        *(float4*)&Bs[bi][lr][lc]       = make_float4(bReg[0], bReg[1], bReg[2], bReg[3]);
    };

    loadg(0); store_s(0);
    __syncthreads();

    const int NKT = C / 8;   // 16
    int buf = 0;
    for (int kt = 0; kt < NKT; kt++) {
        if (kt + 1 < NKT) loadg(kt + 1);
        #pragma unroll
        for (int kk = 0; kk < 8; kk++) {
            const float* ar = &As[buf][kk][tm*16];
            const float* br = &Bs[buf][kk][tn*8];
            ulonglong2 A0 = *(const ulonglong2*)(ar);
            ulonglong2 A1 = *(const ulonglong2*)(ar + 4);
            ulonglong2 A2 = *(const ulonglong2*)(ar + 8);
            ulonglong2 A3 = *(const ulonglong2*)(ar + 12);
            ulonglong2 B0 = *(const ulonglong2*)(br);
            ulonglong2 B1 = *(const ulonglong2*)(br + 4);
            ull av[8] = {A0.x, A0.y, A1.x, A1.y, A2.x, A2.y, A3.x, A3.y};
            ull bv[4] = {B0.x, B0.y, B1.x, B1.y};
            #pragma unroll
            for (int i = 0; i < 8; i++)
                #pragma unroll
                for (int j = 0; j < 4; j++)
                    FMA2(acc[i][j], av[i], bv[j]);
        }
        if (kt + 1 < NKT) {
            buf ^= 1;
            store_s(buf);
            __syncthreads();
        }
    }

    const int n0 = tn*8;
    float* dbase = out + ((size_t)b*C)*HW + pix0 + n0;
    #pragma unroll
    for (int i = 0; i < 8; i++) {
        int m = tm*8 + i;
        float bb = bias[m];
        float* dst = dbase + (size_t)m*HW;
        #pragma unroll
        for (int j = 0; j < 4; j++) {
            ull a = acc[i][j];
            dst[2*j]     = __uint_as_float((unsigned)a)         + bb;
            dst[2*j + 1] = __uint_as_float((unsigned)(a >> 32)) + bb;
        }
    }
}

// ---------------- local 3x3 attention + blend + residual -------------------
// Padded-region k/v values equal their biases (1x1 conv of zero input),
// so halo borders are filled with k_b[c] / v_b[c].
__global__ void __launch_bounds__(256)
attn_kernel(const float* __restrict__ x, const float* __restrict__ k_b,
            const float* __restrict__ v_b, float* __restrict__ out)
{
    const int b  = blockIdx.z;
    const int h0 = blockIdx.y * 16;
    const int w0 = blockIdx.x * 16;
    const int tid = threadIdx.x;
    const int ty = tid >> 4, tx = tid & 15;

    __shared__ float sh[18][19];

    float sims[9];
    #pragma unroll
    for (int o = 0; o < 9; o++) sims[o] = 0.f;

    const size_t pixoff = (size_t)(h0 + ty)*W + (w0 + tx);
    const size_t bbase  = (size_t)b*C*HW;

    // pass 1: similarity logits
    for (int c = 0; c < C; c++) {
        float kbv = k_b[c];
        const float* kp = g_k + bbase + (size_t)c*HW;
        for (int i = tid; i < 324; i += 256) {
            int hh = i / 18, ww = i % 18;
            int gh = h0 + hh - 1, gw = w0 + ww - 1;
            sh[hh][ww] = (gh >= 0 && gh < H && gw >= 0 && gw < W) ? kp[(size_t)gh*W + gw] : kbv;
        }
        __syncthreads();
        float qv = g_q[bbase + (size_t)c*HW + pixoff];
        #pragma unroll
        for (int o = 0; o < 9; o++)
            sims[o] += qv * sh[ty + o/3][tx + o%3];
        __syncthreads();
    }

    // softmax over 9
    float mx = sims[0];
    #pragma unroll
    for (int o = 1; o < 9; o++) mx = fmaxf(mx, sims[o]);
    float se = 0.f;
    #pragma unroll
    for (int o = 0; o < 9; o++) { sims[o] = __expf(sims[o] - mx); se += sims[o]; }
    float inv = 1.f / se;
    #pragma unroll
    for (int o = 0; o < 9; o++) sims[o] *= inv;

    // pass 2: weighted V + blend + residual
    for (int c = 0; c < C; c++) {
        float vbv = v_b[c];
        const float* vp = g_v + bbase + (size_t)c*HW;
        for (int i = tid; i < 324; i += 256) {
            int hh = i / 18, ww = i % 18;
            int gh = h0 + hh - 1, gw = w0 + ww - 1;
            sh[hh][ww] = (gh >= 0 && gh < H && gw >= 0 && gw < W) ? vp[(size_t)gh*W + gw] : vbv;
        }
        __syncthreads();
        float o2 = 0.f;
        #pragma unroll
        for (int o = 0; o < 9; o++)
            o2 += sims[o] * sh[ty + o/3][tx + o%3];
        size_t idx = bbase + (size_t)c*HW + pixoff;
        float mv = g_m[idx];
        out[idx] = x[idx] + g_out1[idx]*mv + (1.f - mv)*o2;
        __syncthreads();
    }
}

// ---------------- launch ----------------------------------------------------
extern "C" void kernel_launch(void* const* d_in, const int* in_sizes, int n_in,
                              void* d_out, int out_size)
{
    const float* x  = (const float*)d_in[0];
    const float* w1 = (const float*)d_in[1];
    const float* b1 = (const float*)d_in[2];
    const float* w2 = (const float*)d_in[3];
    const float* b2 = (const float*)d_in[4];
    const float* wm = (const float*)d_in[5];
    const float* bm = (const float*)d_in[6];
    const float* bq = (const float*)d_in[8];
    const float* bk = (const float*)d_in[10];
    const float* bv = (const float*)d_in[12];
    float* out = (float*)d_out;

    transpose_weights<<<(K3*C + 255)/256, 256>>>(
        w1, w2, wm,
        (const float*)d_in[7], (const float*)d_in[9], (const float*)d_in[11]);

    dim3 gc(128, BATCH);
    conv3x3_kernel<false, false><<<gc, 256>>>(x, 0, b1, 0);        // y1 = conv1(x)+b1
    stats_kernel<<<BATCH*C, 256>>>();                               // mu, rsig
    conv3x3_kernel<true,  false><<<gc, 256>>>(nullptr, 1, b2, 1);  // out1 = conv2(t)+b2
    conv3x3_kernel<true,  true ><<<gc, 256>>>(nullptr, 2, bm, 2);  // m = sigmoid(mask(t))

    dim3 gq(HW/128, BATCH, 3);
    qkv_kernel<<<gq, 256>>>(bq, bk, bv);                            // q,k,v

    dim3 ga(W/16, H/16, BATCH);
    attn_kernel<<<ga, 256>>>(x, bk, bv, out);                       // attn + blend + residual
}

// round 3
// speedup vs baseline: 2.2629x; 2.2629x over previous
#include <cuda_runtime.h>
#include <cstdint>

#define BATCH 8
#define C 128
#define H 128
#define W 128
#define HW (H*W)

// ---------------- scratch (device globals; no allocation allowed) ----------
__device__ float g_y1  [BATCH*C*HW];
__device__ float g_out1[BATCH*C*HW];
__device__ float g_m   [BATCH*C*HW];
__device__ float g_q   [BATCH*C*HW];
__device__ float g_k   [BATCH*C*HW];
__device__ float g_v   [BATCH*C*HW];
__device__ float g_mu  [BATCH*C];
__device__ float g_rsig[BATCH*C];
// weights packed in per-thread mma-fragment order, tf32-converted
__device__ float4 g_wA3[3][144*8*32];   // 3x3 convs: [conv][(ks*8+fr)*32+lane]
__device__ float4 g_wA1[3][16*8*32];    // 1x1 convs

__device__ __forceinline__ uint32_t f2tf32(float f) {
    uint32_t r;
    asm("cvt.rna.tf32.f32 %0, %1;" : "=r"(r) : "f"(f));
    return r;
}

__device__ __forceinline__ void mma_tf32(float* d, const uint32_t* a, const uint32_t* b) {
    asm volatile(
        "mma.sync.aligned.m16n8k8.row.col.f32.tf32.tf32.f32 "
        "{%0,%1,%2,%3}, {%4,%5,%6,%7}, {%8,%9}, {%0,%1,%2,%3};"
        : "+f"(d[0]), "+f"(d[1]), "+f"(d[2]), "+f"(d[3])
        : "r"(a[0]), "r"(a[1]), "r"(a[2]), "r"(a[3]), "r"(b[0]), "r"(b[1]));
}

// ---------------- weight packing --------------------------------------------
// K order: k_global = tap*128 + c (3x3), k = c (1x1).
// Fragment: a0=(g,tk) a1=(g+8,tk) a2=(g,tk+4) a3=(g+8,tk+4); g=lane/4, tk=lane%4.
__global__ void pack_weights(const float* __restrict__ w1, const float* __restrict__ w2,
                             const float* __restrict__ wm, const float* __restrict__ wq,
                             const float* __restrict__ wk, const float* __restrict__ wv)
{
    int idx = blockIdx.x * blockDim.x + threadIdx.x;
    {
        int lane = idx & 31;
        int fr   = (idx >> 5) & 7;
        int t3   = idx >> 8;
        int ks   = t3 % 144;
        int conv = t3 / 144;
        if (conv < 3) {
            const float* w = (conv == 0) ? w1 : (conv == 1) ? w2 : wm;
            int m0  = fr*16 + (lane >> 2);
            int tap = ks >> 4;
            int c   = ((ks & 15) << 3) + (lane & 3);
            float4 o;
            o.x = __uint_as_float(f2tf32(w[ m0   *1152 +  c   *9 + tap]));
            o.y = __uint_as_float(f2tf32(w[(m0+8)*1152 +  c   *9 + tap]));
            o.z = __uint_as_float(f2tf32(w[ m0   *1152 + (c+4)*9 + tap]));
            o.w = __uint_as_float(f2tf32(w[(m0+8)*1152 + (c+4)*9 + tap]));
            g_wA3[conv][(ks*8 + fr)*32 + lane] = o;
        }
    }
    if (idx < 3*16*8*32) {
        int lane = idx & 31;
        int fr   = (idx >> 5) & 7;
        int t3   = idx >> 8;
        int ks   = t3 % 16;
        int set  = t3 / 16;
        const float* w = (set == 0) ? wq : (set == 1) ? wk : wv;
        int m0 = fr*16 + (lane >> 2);
        int c  = ks*8 + (lane & 3);
        float4 o;
        o.x = __uint_as_float(f2tf32(w[ m0   *128 + c  ]));
        o.y = __uint_as_float(f2tf32(w[(m0+8)*128 + c  ]));
        o.z = __uint_as_float(f2tf32(w[ m0   *128 + c+4]));
        o.w = __uint_as_float(f2tf32(w[(m0+8)*128 + c+4]));
        g_wA1[set][(ks*8 + fr)*32 + lane] = o;
    }
}

// ---------------- instance-norm stats ---------------------------------------
__global__ void stats_kernel()
{
    int bc = blockIdx.x;
    const float4* p = (const float4*)(g_y1 + (size_t)bc * HW);
    float s = 0.f, sq = 0.f;
    for (int i = threadIdx.x; i < HW/4; i += blockDim.x) {
        float4 v = p[i];
        s  += (v.x + v.y) + (v.z + v.w);
        sq += v.x*v.x + v.y*v.y + v.z*v.z + v.w*v.w;
    }
    #pragma unroll
    for (int o = 16; o; o >>= 1) {
        s  += __shfl_xor_sync(0xffffffffu, s,  o);
        sq += __shfl_xor_sync(0xffffffffu, sq, o);
    }
    __shared__ float ss[8], sqq[8];
    int wrp = threadIdx.x >> 5;
    if ((threadIdx.x & 31) == 0) { ss[wrp] = s; sqq[wrp] = sq; }
    __syncthreads();
    if (threadIdx.x == 0) {
        float S = 0.f, Q = 0.f;
        #pragma unroll
        for (int i = 0; i < 8; i++) { S += ss[i]; Q += sqq[i]; }
        float mu  = S / (float)HW;
        float var = Q / (float)HW - mu*mu;
        g_mu[bc]   = mu;
        g_rsig[bc] = rsqrtf(var + 1e-5f);
    }
}

// ---------------- tf32 mma.sync conv / GEMM ---------------------------------
// CTA: 128 cout (M) x 128 px (N). Warps 2(M)x4(N): warp tile 64x32.
// XFORM: 0 = raw xin, 1 = leaky(norm(g_y1)), 2 = leaky(norm(g_y1)) * g_m.
// TAPS: 9 (3x3, pad 1) or 1 (1x1). For TAPS==1, set = blockIdx.z (q/k/v).
template<int TAPS, int XFORM, bool SIGM>
__global__ void __launch_bounds__(256, 2)
conv_mma(const float* __restrict__ xin, int wsel,
         const float* __restrict__ bq, const float* __restrict__ bk,
         const float* __restrict__ bv_, int osel)
{
    __shared__ float4 Asm[2][512];    // [buf][sub*256 + fr*32 + lane]
    __shared__ float  Bsm[2][2048];   // [buf][sub*1024 + n*8 + pos]

    const int tid  = threadIdx.x;
    const int lane = tid & 31, wid = tid >> 5;
    const int mw = wid >> 2, nw = wid & 3;
    const int b  = blockIdx.y;
    const int h0 = (blockIdx.x >> 2) << 2;
    const int w0 = (blockIdx.x & 3) << 5;

    int set = (TAPS == 1) ? blockIdx.z : wsel;
    const float4* wA = (TAPS == 9) ? g_wA3[set] : g_wA1[set];
    const float* bias = (TAPS == 9) ? bq : ((set == 0) ? bq : (set == 1) ? bk : bv_);
    float* out;
    if (TAPS == 9) out = (osel == 0) ? g_y1 : (osel == 1) ? g_out1 : g_m;
    else           out = (set == 0) ? g_q : (set == 1) ? g_k : g_v;
    const float* in = (XFORM == 0) ? xin : (const float*)g_y1;

    const float* mup = g_mu   + b*C;
    const float* rsp = g_rsig + b*C;

    // producer mapping
    const int sub  = tid >> 7;          // kstep within round
    const int nn   = tid & 127;         // pixel within tile
    const int prow = nn >> 5, pcol = nn & 31;

    float acc[4][4][4];
    #pragma unroll
    for (int i = 0; i < 4; i++)
        #pragma unroll
        for (int j = 0; j < 4; j++)
            #pragma unroll
            for (int r = 0; r < 4; r++) acc[i][j][r] = 0.f;

    float4 aP0, aP1;
    uint32_t bvr[8];

    auto ldg = [&](int r) {
        const float4* ws = wA + (size_t)r*512;
        aP0 = ws[tid]; aP1 = ws[tid + 256];
        int ks  = r*2 + sub;
        int tap = (TAPS == 9) ? (ks >> 4) : 4;
        int c0  = (TAPS == 9) ? ((ks & 15) << 3) : (ks << 3);
        int ih  = h0 + prow + tap/3 - 1;
        int iw  = w0 + pcol + tap%3 - 1;
        bool ok = ((unsigned)ih < (unsigned)H) && ((unsigned)iw < (unsigned)W);
        #pragma unroll
        for (int j = 0; j < 8; j++) {
            int c = c0 + j;
            float x = 0.f;
            if (ok) {
                size_t gi = ((size_t)(b*C + c) << 14) + (size_t)ih*W + iw;
                x = in[gi];
                if (XFORM >= 1) {
                    float t = (x - mup[c]) * rsp[c];
                    x = (t < 0.f) ? 0.2f*t : t;
                }
                if (XFORM == 2) x *= g_m[gi];
            }
            bvr[j] = f2tf32(x);
        }
    };
    auto sts = [&](int buf) {
        Asm[buf][tid]       = aP0;
        Asm[buf][tid + 256] = aP1;
        float* bd = &Bsm[buf][sub*1024 + nn*8];
        // pos(k) = 2*(k&3) + (k>>2): row = [v0,v4,v1,v5,v2,v6,v3,v7]
        *(float4*)(bd) = make_float4(__uint_as_float(bvr[0]), __uint_as_float(bvr[4]),
                                     __uint_as_float(bvr[1]), __uint_as_float(bvr[5]));
        *(float4*)(bd + 4) = make_float4(__uint_as_float(bvr[2]), __uint_as_float(bvr[6]),
                                         __uint_as_float(bvr[3]), __uint_as_float(bvr[7]));
    };

    const int NR = (TAPS == 9) ? 72 : 8;

    ldg(0);
    sts(0);
    __syncthreads();

    for (int r = 0; r < NR; r++) {
        int buf = r & 1;
        if (r + 1 < NR) ldg(r + 1);
        #pragma unroll
        for (int s2 = 0; s2 < 2; s2++) {
            uint4 af[4];
            #pragma unroll
            for (int i = 0; i < 4; i++)
                af[i] = *(const uint4*)&Asm[buf][s2*256 + (mw*4 + i)*32 + lane];
            uint32_t bf[4][2];
            #pragma unroll
            for (int j = 0; j < 4; j++) {
                float2 t = *(const float2*)&Bsm[buf][s2*1024 +
                            (nw*32 + j*8 + (lane >> 2))*8 + (lane & 3)*2];
                bf[j][0] = __float_as_uint(t.x);
                bf[j][1] = __float_as_uint(t.y);
            }
            #pragma unroll
            for (int i = 0; i < 4; i++)
                #pragma unroll
                for (int j = 0; j < 4; j++)
                    mma_tf32(acc[i][j], (const uint32_t*)&af[i], bf[j]);
        }
        if (r + 1 < NR) {
            sts(buf ^ 1);
            __syncthreads();
        }
    }

    // epilogue: direct float2 stores (d0,d1 row g; d2,d3 row g+8)
    #pragma unroll
    for (int i = 0; i < 4; i++) {
        int m0 = mw*64 + i*16 + (lane >> 2);
        float bb0 = bias[m0], bb1 = bias[m0 + 8];
        size_t ob = ((size_t)(b*C + m0) << 14) + (size_t)(h0 + nw)*W + w0;
        #pragma unroll
        for (int j = 0; j < 4; j++) {
            int co = j*8 + (lane & 3)*2;
            float v0 = acc[i][j][0] + bb0, v1 = acc[i][j][1] + bb0;
            float v2 = acc[i][j][2] + bb1, v3 = acc[i][j][3] + bb1;
            if (SIGM) {
                v0 = 1.f/(1.f + __expf(-v0)); v1 = 1.f/(1.f + __expf(-v1));
                v2 = 1.f/(1.f + __expf(-v2)); v3 = 1.f/(1.f + __expf(-v3));
            }
            *(float2*)(out + ob + co)             = make_float2(v0, v1);
            *(float2*)(out + ob + (8 << 14) + co) = make_float2(v2, v3);
        }
    }
}

// ---------------- local 3x3 attention + blend + residual --------------------
__global__ void __launch_bounds__(256)
attn_kernel(const float* __restrict__ x, const float* __restrict__ k_b,
            const float* __restrict__ v_b, float* __restrict__ out)
{
    const int b  = blockIdx.z;
    const int h0 = blockIdx.y * 16;
    const int w0 = blockIdx.x * 16;
    const int tid = threadIdx.x;
    const int ty = tid >> 4, tx = tid & 15;

    __shared__ float sh[18][19];

    float sims[9];
    #pragma unroll
    for (int o = 0; o < 9; o++) sims[o] = 0.f;

    const size_t pixoff = (size_t)(h0 + ty)*W + (w0 + tx);
    const size_t bbase  = (size_t)b*C*HW;

    for (int c = 0; c < C; c++) {
        float kbv = k_b[c];
        const float* kp = g_k + bbase + (size_t)c*HW;
        for (int i = tid; i < 324; i += 256) {
            int hh = i / 18, ww = i % 18;
            int gh = h0 + hh - 1, gw = w0 + ww - 1;
            sh[hh][ww] = (gh >= 0 && gh < H && gw >= 0 && gw < W) ? kp[(size_t)gh*W + gw] : kbv;
        }
        __syncthreads();
        float qv = g_q[bbase + (size_t)c*HW + pixoff];
        #pragma unroll
        for (int o = 0; o < 9; o++)
            sims[o] += qv * sh[ty + o/3][tx + o%3];
        __syncthreads();
    }

    float mx = sims[0];
    #pragma unroll
    for (int o = 1; o < 9; o++) mx = fmaxf(mx, sims[o]);
    float se = 0.f;
    #pragma unroll
    for (int o = 0; o < 9; o++) { sims[o] = __expf(sims[o] - mx); se += sims[o]; }
    float inv = 1.f / se;
    #pragma unroll
    for (int o = 0; o < 9; o++) sims[o] *= inv;

    for (int c = 0; c < C; c++) {
        float vbv = v_b[c];
        const float* vp = g_v + bbase + (size_t)c*HW;
        for (int i = tid; i < 324; i += 256) {
            int hh = i / 18, ww = i % 18;
            int gh = h0 + hh - 1, gw = w0 + ww - 1;
            sh[hh][ww] = (gh >= 0 && gh < H && gw >= 0 && gw < W) ? vp[(size_t)gh*W + gw] : vbv;
        }
        __syncthreads();
        float o2 = 0.f;
        #pragma unroll
        for (int o = 0; o < 9; o++)
            o2 += sims[o] * sh[ty + o/3][tx + o%3];
        size_t idx = bbase + (size_t)c*HW + pixoff;
        float mv = g_m[idx];
        out[idx] = x[idx] + g_out1[idx]*mv + (1.f - mv)*o2;
        __syncthreads();
    }
}

// ---------------- launch ----------------------------------------------------
extern "C" void kernel_launch(void* const* d_in, const int* in_sizes, int n_in,
                              void* d_out, int out_size)
{
    const float* x  = (const float*)d_in[0];
    const float* w1 = (const float*)d_in[1];
    const float* b1 = (const float*)d_in[2];
    const float* w2 = (const float*)d_in[3];
    const float* b2 = (const float*)d_in[4];
    const float* wm = (const float*)d_in[5];
    const float* bm = (const float*)d_in[6];
    const float* wq = (const float*)d_in[7];
    const float* bq = (const float*)d_in[8];
    const float* wk = (const float*)d_in[9];
    const float* bk = (const float*)d_in[10];
    const float* wv = (const float*)d_in[11];
    const float* bv = (const float*)d_in[12];
    float* out = (float*)d_out;

    pack_weights<<<432, 256>>>(w1, w2, wm, wq, wk, wv);

    dim3 gc(128, BATCH);
    conv_mma<9,0,false><<<gc, 256>>>(x, 0, b1, nullptr, nullptr, 0);       // y1
    stats_kernel<<<BATCH*C, 256>>>();
    conv_mma<9,1,false><<<gc, 256>>>(nullptr, 1, b2, nullptr, nullptr, 1); // out1
    conv_mma<9,1,true ><<<gc, 256>>>(nullptr, 2, bm, nullptr, nullptr, 2); // mask
    dim3 gq(128, BATCH, 3);
    conv_mma<1,2,false><<<gq, 256>>>(nullptr, 0, bq, bk, bv, 0);           // q,k,v

    dim3 ga(W/16, H/16, BATCH);
    attn_kernel<<<ga, 256>>>(x, bk, bv, out);
}

// round 5
// speedup vs baseline: 3.2574x; 1.4395x over previous
#include <cuda_runtime.h>
#include <cstdint>

#define BATCH 8
#define C 128
#define H 128
#define W 128
#define HW (H*W)

// ---------------- scratch (device globals; no allocation allowed) ----------
__device__ float g_y1  [BATCH*C*HW];   // conv1 raw output
__device__ float g_t   [BATCH*C*HW];   // leaky(norm(y1))
__device__ float g_out1[BATCH*C*HW];
__device__ float g_m   [BATCH*C*HW];
__device__ float g_xm  [BATCH*C*HW];   // t * m
__device__ float g_q   [BATCH*C*HW];
__device__ float g_k   [BATCH*C*HW];
__device__ float g_v   [BATCH*C*HW];
__device__ float g_mu  [BATCH*C];
__device__ float g_rsig[BATCH*C];
// weights packed in per-thread mma-fragment order, tf32-converted
__device__ float4 g_wA3[3][144*8*32];
__device__ float4 g_wA1[3][16*8*32];

__device__ __forceinline__ uint32_t f2tf32(float f) {
    uint32_t r;
    asm("cvt.rna.tf32.f32 %0, %1;" : "=r"(r) : "f"(f));
    return r;
}
__device__ __forceinline__ void mma_tf32(float* d, const uint32_t* a, const uint32_t* b) {
    asm volatile(
        "mma.sync.aligned.m16n8k8.row.col.f32.tf32.tf32.f32 "
        "{%0,%1,%2,%3}, {%4,%5,%6,%7}, {%8,%9}, {%0,%1,%2,%3};"
        : "+f"(d[0]), "+f"(d[1]), "+f"(d[2]), "+f"(d[3])
        : "r"(a[0]), "r"(a[1]), "r"(a[2]), "r"(a[3]), "r"(b[0]), "r"(b[1]));
}
__device__ __forceinline__ uint32_t smem_u32(const void* p) {
    uint32_t a;
    asm("{ .reg .u64 t; cvta.to.shared.u64 t, %1; cvt.u32.u64 %0, t; }"
        : "=r"(a) : "l"(p));
    return a;
}
#define CP_ASYNC16(dst, src) \
    asm volatile("cp.async.ca.shared.global [%0], [%1], 16;" :: "r"(dst), "l"(src))
#define CP_COMMIT() asm volatile("cp.async.commit_group;")
#define CP_WAIT0()  asm volatile("cp.async.wait_group 0;" ::: "memory")

// ---------------- weight packing --------------------------------------------
__global__ void pack_weights(const float* __restrict__ w1, const float* __restrict__ w2,
                             const float* __restrict__ wm, const float* __restrict__ wq,
                             const float* __restrict__ wk, const float* __restrict__ wv)
{
    int idx = blockIdx.x * blockDim.x + threadIdx.x;
    {
        int lane = idx & 31;
        int fr   = (idx >> 5) & 7;
        int t3   = idx >> 8;
        int ks   = t3 % 144;
        int conv = t3 / 144;
        if (conv < 3) {
            const float* w = (conv == 0) ? w1 : (conv == 1) ? w2 : wm;
            int m0  = fr*16 + (lane >> 2);
            int tap = ks >> 4;
            int c   = ((ks & 15) << 3) + (lane & 3);
            float4 o;
            o.x = __uint_as_float(f2tf32(w[ m0   *1152 +  c   *9 + tap]));
            o.y = __uint_as_float(f2tf32(w[(m0+8)*1152 +  c   *9 + tap]));
            o.z = __uint_as_float(f2tf32(w[ m0   *1152 + (c+4)*9 + tap]));
            o.w = __uint_as_float(f2tf32(w[(m0+8)*1152 + (c+4)*9 + tap]));
            g_wA3[conv][(ks*8 + fr)*32 + lane] = o;
        }
    }
    if (idx < 3*16*8*32) {
        int lane = idx & 31;
        int fr   = (idx >> 5) & 7;
        int t3   = idx >> 8;
        int ks   = t3 % 16;
        int set  = t3 / 16;
        const float* w = (set == 0) ? wq : (set == 1) ? wk : wv;
        int m0 = fr*16 + (lane >> 2);
        int c  = ks*8 + (lane & 3);
        float4 o;
        o.x = __uint_as_float(f2tf32(w[ m0   *128 + c  ]));
        o.y = __uint_as_float(f2tf32(w[(m0+8)*128 + c  ]));
        o.z = __uint_as_float(f2tf32(w[ m0   *128 + c+4]));
        o.w = __uint_as_float(f2tf32(w[(m0+8)*128 + c+4]));
        g_wA1[set][(ks*8 + fr)*32 + lane] = o;
    }
}

// ---------------- fused stats + normalize (y1 -> t), full coverage ----------
__global__ void __launch_bounds__(512)
stats_norm_kernel()
{
    int bc = blockIdx.x;
    const float4* p = (const float4*)(g_y1 + (size_t)bc * HW);
    float4* d = (float4*)(g_t + (size_t)bc * HW);
    float4 vals[8];                       // 512 threads * 8 = 4096 = HW/4
    float s = 0.f, sq = 0.f;
    #pragma unroll
    for (int i = 0; i < 8; i++) {
        float4 v = p[threadIdx.x + 512*i];
        vals[i] = v;
        s  += (v.x + v.y) + (v.z + v.w);
        sq += v.x*v.x + v.y*v.y + v.z*v.z + v.w*v.w;
    }
    #pragma unroll
    for (int o = 16; o; o >>= 1) {
        s  += __shfl_xor_sync(0xffffffffu, s,  o);
        sq += __shfl_xor_sync(0xffffffffu, sq, o);
    }
    __shared__ float ss[16], sqq[16];
    __shared__ float s_mu, s_rs;
    int wrp = threadIdx.x >> 5;
    if ((threadIdx.x & 31) == 0) { ss[wrp] = s; sqq[wrp] = sq; }
    __syncthreads();
    if (threadIdx.x == 0) {
        float S = 0.f, Q = 0.f;
        #pragma unroll
        for (int i = 0; i < 16; i++) { S += ss[i]; Q += sqq[i]; }
        float mu  = S / (float)HW;
        float var = Q / (float)HW - mu*mu;
        float rs  = rsqrtf(var + 1e-5f);
        g_mu[bc] = mu; g_rsig[bc] = rs;
        s_mu = mu; s_rs = rs;
    }
    __syncthreads();
    float mu = s_mu, rs = s_rs;
    #pragma unroll
    for (int i = 0; i < 8; i++) {
        float4 v = vals[i];
        float t0 = (v.x - mu)*rs; t0 = (t0 < 0.f) ? 0.2f*t0 : t0;
        float t1 = (v.y - mu)*rs; t1 = (t1 < 0.f) ? 0.2f*t1 : t1;
        float t2 = (v.z - mu)*rs; t2 = (t2 < 0.f) ? 0.2f*t2 : t2;
        float t3 = (v.w - mu)*rs; t3 = (t3 < 0.f) ? 0.2f*t3 : t3;
        d[threadIdx.x + 512*i] = make_float4(t0, t1, t2, t3);
    }
}

// ---------------- tf32 mma.sync conv / GEMM ---------------------------------
// CTA: 128 cout (M) x 128 px (N). Warps 2(M)x4(N): warp tile 64x32.
// TAPS: 9 (3x3, pad 1) or 1 (1x1). SIGM: sigmoid epilogue. WXM: also write
// xm = t*out (mask conv). For TAPS==1, set = blockIdx.z selects q/k/v.
template<int TAPS, bool SIGM, bool WXM>
__global__ void __launch_bounds__(256, 2)
conv_mma(const float* __restrict__ in, int wsel, float* __restrict__ outp,
         const float* __restrict__ bq, const float* __restrict__ bk,
         const float* __restrict__ bv_)
{
    __shared__ float4 Asm[2][512];
    __shared__ float  Bsm[2][2048];

    const int tid  = threadIdx.x;
    const int lane = tid & 31, wid = tid >> 5;
    const int mw = wid >> 2, nw = wid & 3;
    const int b  = blockIdx.y;
    const int h0 = (blockIdx.x >> 2) << 2;
    const int w0 = (blockIdx.x & 3) << 5;

    int set = (TAPS == 1) ? blockIdx.z : wsel;
    const float4* wA = (TAPS == 9) ? g_wA3[set] : g_wA1[set];
    const float* bias = (TAPS == 9) ? bq : ((set == 0) ? bq : (set == 1) ? bk : bv_);
    float* out = (TAPS == 9) ? outp : ((set == 0) ? g_q : (set == 1) ? g_k : g_v);

    const int sub  = tid >> 7;
    const int nn   = tid & 127;
    const int prow = nn >> 5, pcol = nn & 31;

    float acc[4][4][4];
    #pragma unroll
    for (int i = 0; i < 4; i++)
        #pragma unroll
        for (int j = 0; j < 4; j++)
            #pragma unroll
            for (int r = 0; r < 4; r++) acc[i][j][r] = 0.f;

    const uint32_t aBase = smem_u32(&Asm[0][0]);
    uint32_t bvr[8];

    auto cpA = [&](int r, int buf) {
        const float4* src = wA + (size_t)r*512;
        uint32_t d0 = aBase + ((buf*512 + tid) << 4);
        CP_ASYNC16(d0,               src + tid);
        CP_ASYNC16(d0 + (256 << 4),  src + tid + 256);
        CP_COMMIT();
    };
    auto ldgB = [&](int r) {
        int ks  = r*2 + sub;
        int tap = (TAPS == 9) ? (ks >> 4) : 4;
        int c0  = (TAPS == 9) ? ((ks & 15) << 3) : (ks << 3);
        int ih  = h0 + prow + tap/3 - 1;
        int iw  = w0 + pcol + tap%3 - 1;
        bool ok = ((unsigned)ih < (unsigned)H) && ((unsigned)iw < (unsigned)W);
        const float* src = in + ((size_t)(b*C + c0) << 14) + (size_t)ih*W + iw;
        #pragma unroll
        for (int j = 0; j < 8; j++)
            bvr[j] = f2tf32(ok ? src[(size_t)j << 14] : 0.f);
    };
    auto stsB = [&](int buf) {
        float* bd = &Bsm[buf][sub*1024 + nn*8];
        *(float4*)(bd) = make_float4(__uint_as_float(bvr[0]), __uint_as_float(bvr[4]),
                                     __uint_as_float(bvr[1]), __uint_as_float(bvr[5]));
        *(float4*)(bd + 4) = make_float4(__uint_as_float(bvr[2]), __uint_as_float(bvr[6]),
                                         __uint_as_float(bvr[3]), __uint_as_float(bvr[7]));
    };

    const int NR = (TAPS == 9) ? 72 : 8;

    cpA(0, 0);
    ldgB(0);
    stsB(0);
    CP_WAIT0();
    __syncthreads();

    for (int r = 0; r < NR; r++) {
        int buf = r & 1;
        if (r + 1 < NR) { cpA(r + 1, buf ^ 1); ldgB(r + 1); }
        #pragma unroll
        for (int s2 = 0; s2 < 2; s2++) {
            uint4 af[4];
            #pragma unroll
            for (int i = 0; i < 4; i++)
                af[i] = *(const uint4*)&Asm[buf][s2*256 + (mw*4 + i)*32 + lane];
            uint32_t bf[4][2];
            #pragma unroll
            for (int j = 0; j < 4; j++) {
                float2 t = *(const float2*)&Bsm[buf][s2*1024 +
                            (nw*32 + j*8 + (lane >> 2))*8 + (lane & 3)*2];
                bf[j][0] = __float_as_uint(t.x);
                bf[j][1] = __float_as_uint(t.y);
            }
            #pragma unroll
            for (int i = 0; i < 4; i++)
                #pragma unroll
                for (int j = 0; j < 4; j++)
                    mma_tf32(acc[i][j], (const uint32_t*)&af[i], bf[j]);
        }
        if (r + 1 < NR) {
            stsB(buf ^ 1);
            CP_WAIT0();
            __syncthreads();
        }
    }

    // epilogue
    #pragma unroll
    for (int i = 0; i < 4; i++) {
        int m0 = mw*64 + i*16 + (lane >> 2);
        float bb0 = bias[m0], bb1 = bias[m0 + 8];
        size_t ob = ((size_t)(b*C + m0) << 14) + (size_t)(h0 + nw)*W + w0;
        #pragma unroll
        for (int j = 0; j < 4; j++) {
            int co = j*8 + (lane & 3)*2;
            float v0 = acc[i][j][0] + bb0, v1 = acc[i][j][1] + bb0;
            float v2 = acc[i][j][2] + bb1, v3 = acc[i][j][3] + bb1;
            if (SIGM) {
                v0 = 1.f/(1.f + __expf(-v0)); v1 = 1.f/(1.f + __expf(-v1));
                v2 = 1.f/(1.f + __expf(-v2)); v3 = 1.f/(1.f + __expf(-v3));
            }
            *(float2*)(out + ob + co)             = make_float2(v0, v1);
            *(float2*)(out + ob + (8 << 14) + co) = make_float2(v2, v3);
            if (WXM) {
                float2 t0 = *(const float2*)(g_t + ob + co);
                float2 t1 = *(const float2*)(g_t + ob + (8 << 14) + co);
                *(float2*)(g_xm + ob + co)             = make_float2(v0*t0.x, v1*t0.y);
                *(float2*)(g_xm + ob + (8 << 14) + co) = make_float2(v2*t1.x, v3*t1.y);
            }
        }
    }
}

// ---------------- local 3x3 attention + blend + residual --------------------
// Thread-per-pixel, no smem, no syncs. Halo k/v values equal their conv biases.
__global__ void __launch_bounds__(256)
attn_kernel(const float* __restrict__ x, const float* __restrict__ k_b,
            const float* __restrict__ v_b, float* __restrict__ out)
{
    const int b   = blockIdx.y;
    const int tid = threadIdx.x;
    const int h   = blockIdx.x*2 + (tid >> 7);
    const int w   = tid & 127;
    const size_t bbase = (size_t)b*C*HW;
    const int poff = h*W + w;

    float sims[9];
    #pragma unroll
    for (int o = 0; o < 9; o++) sims[o] = 0.f;

    for (int c = 0; c < C; c++) {
        const float* kp = g_k + bbase + ((size_t)c << 14);
        float kbv = __ldg(k_b + c);
        float qv  = g_q[bbase + ((size_t)c << 14) + poff];
        #pragma unroll
        for (int o = 0; o < 9; o++) {
            int hh = h + o/3 - 1, ww = w + o%3 - 1;
            bool ok = ((unsigned)hh < (unsigned)H) && ((unsigned)ww < (unsigned)W);
            float kv = ok ? kp[hh*W + ww] : kbv;
            sims[o] = fmaf(qv, kv, sims[o]);
        }
    }

    float mx = sims[0];
    #pragma unroll
    for (int o = 1; o < 9; o++) mx = fmaxf(mx, sims[o]);
    float se = 0.f;
    #pragma unroll
    for (int o = 0; o < 9; o++) { sims[o] = __expf(sims[o] - mx); se += sims[o]; }
    float inv = 1.f / se;
    #pragma unroll
    for (int o = 0; o < 9; o++) sims[o] *= inv;

    for (int c = 0; c < C; c++) {
        const float* vp = g_v + bbase + ((size_t)c << 14);
        float vbv = __ldg(v_b + c);
        float o2 = 0.f;
        #pragma unroll
        for (int o = 0; o < 9; o++) {
            int hh = h + o/3 - 1, ww = w + o%3 - 1;
            bool ok = ((unsigned)hh < (unsigned)H) && ((unsigned)ww < (unsigned)W);
            float vv = ok ? vp[hh*W + ww] : vbv;
            o2 = fmaf(sims[o], vv, o2);
        }
        size_t idx = bbase + ((size_t)c << 14) + poff;
        float mv = g_m[idx];
        out[idx] = x[idx] + g_out1[idx]*mv + (1.f - mv)*o2;
    }
}

// ---------------- launch ----------------------------------------------------
extern "C" void kernel_launch(void* const* d_in, const int* in_sizes, int n_in,
                              void* d_out, int out_size)
{
    const float* x  = (const float*)d_in[0];
    const float* w1 = (const float*)d_in[1];
    const float* b1 = (const float*)d_in[2];
    const float* w2 = (const float*)d_in[3];
    const float* b2 = (const float*)d_in[4];
    const float* wm = (const float*)d_in[5];
    const float* bm = (const float*)d_in[6];
    const float* wq = (const float*)d_in[7];
    const float* bq = (const float*)d_in[8];
    const float* wk = (const float*)d_in[9];
    const float* bk = (const float*)d_in[10];
    const float* wv = (const float*)d_in[11];
    const float* bv = (const float*)d_in[12];
    float* out = (float*)d_out;

    float* y1p;   cudaGetSymbolAddress((void**)&y1p,   g_y1);
    float* tp;    cudaGetSymbolAddress((void**)&tp,    g_t);
    float* out1p; cudaGetSymbolAddress((void**)&out1p, g_out1);
    float* mp;    cudaGetSymbolAddress((void**)&mp,    g_m);
    float* xmp;   cudaGetSymbolAddress((void**)&xmp,   g_xm);

    pack_weights<<<432, 256>>>(w1, w2, wm, wq, wk, wv);

    dim3 gc(128, BATCH);
    conv_mma<9,false,false><<<gc, 256>>>(x,  0, y1p,   b1, nullptr, nullptr);
    stats_norm_kernel<<<BATCH*C, 512>>>();
    conv_mma<9,false,false><<<gc, 256>>>(tp, 1, out1p, b2, nullptr, nullptr);
    conv_mma<9,true, true ><<<gc, 256>>>(tp, 2, mp,    bm, nullptr, nullptr);
    dim3 gq(128, BATCH, 3);
    conv_mma<1,false,false><<<gq, 256>>>(xmp, 0, nullptr, bq, bk, bv);

    dim3 ga(H/2, BATCH);
    attn_kernel<<<ga, 256>>>(x, bk, bv, out);
}

// round 6
// speedup vs baseline: 3.3256x; 1.0210x over previous
#include <cuda_runtime.h>
#include <cstdint>

#define BATCH 8
#define C 128
#define H 128
#define W 128
#define HW (H*W)

// ---------------- scratch (device globals; no allocation allowed) ----------
__device__ float g_y1  [BATCH*C*HW];   // conv1 raw output
__device__ float g_t   [BATCH*C*HW];   // leaky(norm(y1))
__device__ float g_out1[BATCH*C*HW];
__device__ float g_m   [BATCH*C*HW];
__device__ float g_xm  [BATCH*C*HW];   // t * m
__device__ float g_q   [BATCH*C*HW];
__device__ float g_k   [BATCH*C*HW];
__device__ float g_v   [BATCH*C*HW];
__device__ float g_mu  [BATCH*C];
__device__ float g_rsig[BATCH*C];
// weights packed in per-thread mma-fragment order, tf32-converted
__device__ float4 g_wA3[3][144*8*32];
__device__ float4 g_wA1[3][16*8*32];

__constant__ int c_di[9] = {-1,-1,-1, 0,0,0, 1,1,1};
__constant__ int c_dj[9] = {-1, 0, 1,-1,0,1,-1,0,1};

__device__ __forceinline__ uint32_t f2tf32(float f) {
    uint32_t r;
    asm("cvt.rna.tf32.f32 %0, %1;" : "=r"(r) : "f"(f));
    return r;
}
__device__ __forceinline__ void mma_tf32(float* d, const uint32_t* a, const uint32_t* b) {
    asm volatile(
        "mma.sync.aligned.m16n8k8.row.col.f32.tf32.tf32.f32 "
        "{%0,%1,%2,%3}, {%4,%5,%6,%7}, {%8,%9}, {%0,%1,%2,%3};"
        : "+f"(d[0]), "+f"(d[1]), "+f"(d[2]), "+f"(d[3])
        : "r"(a[0]), "r"(a[1]), "r"(a[2]), "r"(a[3]), "r"(b[0]), "r"(b[1]));
}
__device__ __forceinline__ uint32_t smem_u32(const void* p) {
    uint32_t a;
    asm("{ .reg .u64 t; cvta.to.shared.u64 t, %1; cvt.u32.u64 %0, t; }"
        : "=r"(a) : "l"(p));
    return a;
}
#define CP_ASYNC16(dst, src) \
    asm volatile("cp.async.ca.shared.global [%0], [%1], 16;" :: "r"(dst), "l"(src))
#define CP_COMMIT() asm volatile("cp.async.commit_group;")
#define CP_WAIT0()  asm volatile("cp.async.wait_group 0;" ::: "memory")

// ---------------- weight packing --------------------------------------------
__global__ void pack_weights(const float* __restrict__ w1, const float* __restrict__ w2,
                             const float* __restrict__ wm, const float* __restrict__ wq,
                             const float* __restrict__ wk, const float* __restrict__ wv)
{
    int idx = blockIdx.x * blockDim.x + threadIdx.x;
    {
        int lane = idx & 31;
        int fr   = (idx >> 5) & 7;
        int t3   = idx >> 8;
        int ks   = t3 % 144;
        int conv = t3 / 144;
        if (conv < 3) {
            const float* w = (conv == 0) ? w1 : (conv == 1) ? w2 : wm;
            int m0  = fr*16 + (lane >> 2);
            int tap = ks >> 4;
            int c   = ((ks & 15) << 3) + (lane & 3);
            float4 o;
            o.x = __uint_as_float(f2tf32(w[ m0   *1152 +  c   *9 + tap]));
            o.y = __uint_as_float(f2tf32(w[(m0+8)*1152 +  c   *9 + tap]));
            o.z = __uint_as_float(f2tf32(w[ m0   *1152 + (c+4)*9 + tap]));
            o.w = __uint_as_float(f2tf32(w[(m0+8)*1152 + (c+4)*9 + tap]));
            g_wA3[conv][(ks*8 + fr)*32 + lane] = o;
        }
    }
    if (idx < 3*16*8*32) {
        int lane = idx & 31;
        int fr   = (idx >> 5) & 7;
        int t3   = idx >> 8;
        int ks   = t3 % 16;
        int set  = t3 / 16;
        const float* w = (set == 0) ? wq : (set == 1) ? wk : wv;
        int m0 = fr*16 + (lane >> 2);
        int c  = ks*8 + (lane & 3);
        float4 o;
        o.x = __uint_as_float(f2tf32(w[ m0   *128 + c  ]));
        o.y = __uint_as_float(f2tf32(w[(m0+8)*128 + c  ]));
        o.z = __uint_as_float(f2tf32(w[ m0   *128 + c+4]));
        o.w = __uint_as_float(f2tf32(w[(m0+8)*128 + c+4]));
        g_wA1[set][(ks*8 + fr)*32 + lane] = o;
    }
}

// ---------------- fused stats + normalize (y1 -> t), full coverage ----------
__global__ void __launch_bounds__(512)
stats_norm_kernel()
{
    int bc = blockIdx.x;
    const float4* p = (const float4*)(g_y1 + (size_t)bc * HW);
    float4* d = (float4*)(g_t + (size_t)bc * HW);
    float4 vals[8];                       // 512 threads * 8 = 4096 = HW/4
    float s = 0.f, sq = 0.f;
    #pragma unroll
    for (int i = 0; i < 8; i++) {
        float4 v = p[threadIdx.x + 512*i];
        vals[i] = v;
        s  += (v.x + v.y) + (v.z + v.w);
        sq += v.x*v.x + v.y*v.y + v.z*v.z + v.w*v.w;
    }
    #pragma unroll
    for (int o = 16; o; o >>= 1) {
        s  += __shfl_xor_sync(0xffffffffu, s,  o);
        sq += __shfl_xor_sync(0xffffffffu, sq, o);
    }
    __shared__ float ss[16], sqq[16];
    __shared__ float s_mu, s_rs;
    int wrp = threadIdx.x >> 5;
    if ((threadIdx.x & 31) == 0) { ss[wrp] = s; sqq[wrp] = sq; }
    __syncthreads();
    if (threadIdx.x == 0) {
        float S = 0.f, Q = 0.f;
        #pragma unroll
        for (int i = 0; i < 16; i++) { S += ss[i]; Q += sqq[i]; }
        float mu  = S / (float)HW;
        float var = Q / (float)HW - mu*mu;
        float rs  = rsqrtf(var + 1e-5f);
        g_mu[bc] = mu; g_rsig[bc] = rs;
        s_mu = mu; s_rs = rs;
    }
    __syncthreads();
    float mu = s_mu, rs = s_rs;
    #pragma unroll
    for (int i = 0; i < 8; i++) {
        float4 v = vals[i];
        float t0 = (v.x - mu)*rs; t0 = (t0 < 0.f) ? 0.2f*t0 : t0;
        float t1 = (v.y - mu)*rs; t1 = (t1 < 0.f) ? 0.2f*t1 : t1;
        float t2 = (v.z - mu)*rs; t2 = (t2 < 0.f) ? 0.2f*t2 : t2;
        float t3 = (v.w - mu)*rs; t3 = (t3 < 0.f) ? 0.2f*t3 : t3;
        d[threadIdx.x + 512*i] = make_float4(t0, t1, t2, t3);
    }
}

// ---------------- tf32 mma.sync 3x3 conv ------------------------------------
// CTA: 128 cout (M) x 128 px (N). Warps 2(M)x4(N): warp tile 64x32.
// SIGM: sigmoid epilogue. WXM: also write xm = t*out (mask conv).
template<bool SIGM, bool WXM>
__global__ void __launch_bounds__(256, 2)
conv_mma(const float* __restrict__ in, int wsel, float* __restrict__ outp,
         const float* __restrict__ bias)
{
    __shared__ float4 Asm[2][512];
    __shared__ float  Bsm[2][2048];

    const int tid  = threadIdx.x;
    const int lane = tid & 31, wid = tid >> 5;
    const int mw = wid >> 2, nw = wid & 3;
    const int b  = blockIdx.y;
    const int h0 = (blockIdx.x >> 2) << 2;
    const int w0 = (blockIdx.x & 3) << 5;

    const float4* wA = g_wA3[wsel];
    float* out = outp;

    const int sub  = tid >> 7;
    const int nn   = tid & 127;
    const int prow = nn >> 5, pcol = nn & 31;

    float acc[4][4][4];
    #pragma unroll
    for (int i = 0; i < 4; i++)
        #pragma unroll
        for (int j = 0; j < 4; j++)
            #pragma unroll
            for (int r = 0; r < 4; r++) acc[i][j][r] = 0.f;

    const uint32_t aBase = smem_u32(&Asm[0][0]);
    uint32_t bvr[8];

    auto cpA = [&](int r, int buf) {
        const float4* src = wA + (size_t)r*512;
        uint32_t d0 = aBase + ((buf*512 + tid) << 4);
        CP_ASYNC16(d0,               src + tid);
        CP_ASYNC16(d0 + (256 << 4),  src + tid + 256);
        CP_COMMIT();
    };
    auto ldgB = [&](int r) {
        int ks  = r*2 + sub;
        int tap = ks >> 4;
        int c0  = (ks & 15) << 3;
        int ih  = h0 + prow + c_di[tap];
        int iw  = w0 + pcol + c_dj[tap];
        bool ok = ((unsigned)ih < (unsigned)H) && ((unsigned)iw < (unsigned)W);
        const float* src = in + ((size_t)(b*C + c0) << 14) + (size_t)ih*W + iw;
        #pragma unroll
        for (int j = 0; j < 8; j++)
            bvr[j] = f2tf32(ok ? src[(size_t)j << 14] : 0.f);
    };
    auto stsB = [&](int buf) {
        float* bd = &Bsm[buf][sub*1024 + nn*8];
        *(float4*)(bd) = make_float4(__uint_as_float(bvr[0]), __uint_as_float(bvr[4]),
                                     __uint_as_float(bvr[1]), __uint_as_float(bvr[5]));
        *(float4*)(bd + 4) = make_float4(__uint_as_float(bvr[2]), __uint_as_float(bvr[6]),
                                         __uint_as_float(bvr[3]), __uint_as_float(bvr[7]));
    };

    const int NR = 72;

    cpA(0, 0);
    ldgB(0);
    stsB(0);
    CP_WAIT0();
    __syncthreads();

    for (int r = 0; r < NR; r++) {
        int buf = r & 1;
        if (r + 1 < NR) { cpA(r + 1, buf ^ 1); ldgB(r + 1); }
        #pragma unroll
        for (int s2 = 0; s2 < 2; s2++) {
            uint4 af[4];
            #pragma unroll
            for (int i = 0; i < 4; i++)
                af[i] = *(const uint4*)&Asm[buf][s2*256 + (mw*4 + i)*32 + lane];
            uint32_t bf[4][2];
            #pragma unroll
            for (int j = 0; j < 4; j++) {
                float2 t = *(const float2*)&Bsm[buf][s2*1024 +
                            (nw*32 + j*8 + (lane >> 2))*8 + (lane & 3)*2];
                bf[j][0] = __float_as_uint(t.x);
                bf[j][1] = __float_as_uint(t.y);
            }
            #pragma unroll
            for (int i = 0; i < 4; i++)
                #pragma unroll
                for (int j = 0; j < 4; j++)
                    mma_tf32(acc[i][j], (const uint32_t*)&af[i], bf[j]);
        }
        if (r + 1 < NR) {
            stsB(buf ^ 1);
            CP_WAIT0();
            __syncthreads();
        }
    }

    // epilogue
    #pragma unroll
    for (int i = 0; i < 4; i++) {
        int m0 = mw*64 + i*16 + (lane >> 2);
        float bb0 = bias[m0], bb1 = bias[m0 + 8];
        size_t ob = ((size_t)(b*C + m0) << 14) + (size_t)(h0 + nw)*W + w0;
        #pragma unroll
        for (int j = 0; j < 4; j++) {
            int co = j*8 + (lane & 3)*2;
            float v0 = acc[i][j][0] + bb0, v1 = acc[i][j][1] + bb0;
            float v2 = acc[i][j][2] + bb1, v3 = acc[i][j][3] + bb1;
            if (SIGM) {
                v0 = 1.f/(1.f + __expf(-v0)); v1 = 1.f/(1.f + __expf(-v1));
                v2 = 1.f/(1.f + __expf(-v2)); v3 = 1.f/(1.f + __expf(-v3));
            }
            *(float2*)(out + ob + co)             = make_float2(v0, v1);
            *(float2*)(out + ob + (8 << 14) + co) = make_float2(v2, v3);
            if (WXM) {
                float2 t0 = *(const float2*)(g_t + ob + co);
                float2 t1 = *(const float2*)(g_t + ob + (8 << 14) + co);
                *(float2*)(g_xm + ob + co)             = make_float2(v0*t0.x, v1*t0.y);
                *(float2*)(g_xm + ob + (8 << 14) + co) = make_float2(v2*t1.x, v3*t1.y);
            }
        }
    }
}

// ---------------- merged q/k/v 1x1 GEMM (shared B staging) ------------------
// B (im2col of xm, K=128) staged once in smem (64KB), then 3 weight sets.
__global__ void __launch_bounds__(256, 2)
conv_qkv(const float* __restrict__ bq, const float* __restrict__ bk,
         const float* __restrict__ bv_)
{
    extern __shared__ float sm[];
    float*  Bs  = sm;                       // 16 subs * 1024 floats = 64KB
    float4* Asm = (float4*)(sm + 16384);    // 2 * 512 float4 = 16KB

    const int tid  = threadIdx.x;
    const int lane = tid & 31, wid = tid >> 5;
    const int mw = wid >> 2, nw = wid & 3;
    const int b  = blockIdx.y;
    const int h0 = (blockIdx.x >> 2) << 2;
    const int w0 = (blockIdx.x & 3) << 5;

    const int sub  = tid >> 7;
    const int nn   = tid & 127;
    const int prow = nn >> 5, pcol = nn & 31;

    const uint32_t aBase = smem_u32(Asm);
    auto cpA = [&](const float4* wA, int r, int buf) {
        const float4* src = wA + (size_t)r*512;
        uint32_t d0 = aBase + ((buf*512 + tid) << 4);
        CP_ASYNC16(d0,               src + tid);
        CP_ASYNC16(d0 + (256 << 4),  src + tid + 256);
        CP_COMMIT();
    };

    // stage whole B (K=128): 8 iterations of 2 k8-groups
    {
        const float* src0 = (const float*)g_xm + ((size_t)(b*C) << 14)
                          + (size_t)(h0 + prow)*W + (w0 + pcol);
        #pragma unroll
        for (int it = 0; it < 8; it++) {
            int ks = it*2 + sub;
            const float* src = src0 + ((size_t)(ks*8) << 14);
            uint32_t bvr[8];
            #pragma unroll
            for (int j = 0; j < 8; j++)
                bvr[j] = f2tf32(src[(size_t)j << 14]);
            float* bd = &Bs[ks*1024 + nn*8];
            *(float4*)(bd) = make_float4(__uint_as_float(bvr[0]), __uint_as_float(bvr[4]),
                                         __uint_as_float(bvr[1]), __uint_as_float(bvr[5]));
            *(float4*)(bd + 4) = make_float4(__uint_as_float(bvr[2]), __uint_as_float(bvr[6]),
                                             __uint_as_float(bvr[3]), __uint_as_float(bvr[7]));
        }
    }

    for (int set = 0; set < 3; set++) {
        const float4* wA = g_wA1[set];
        const float* bias = (set == 0) ? bq : (set == 1) ? bk : bv_;
        float* out = (set == 0) ? g_q : (set == 1) ? g_k : g_v;

        float acc[4][4][4];
        #pragma unroll
        for (int i = 0; i < 4; i++)
            #pragma unroll
            for (int j = 0; j < 4; j++)
                #pragma unroll
                for (int r = 0; r < 4; r++) acc[i][j][r] = 0.f;

        cpA(wA, 0, 0);
        CP_WAIT0();
        __syncthreads();   // covers B staging on set 0, Asm visibility on all

        for (int r = 0; r < 8; r++) {
            int buf = r & 1;
            if (r + 1 < 8) cpA(wA, r + 1, buf ^ 1);
            #pragma unroll
            for (int s2 = 0; s2 < 2; s2++) {
                int ks = r*2 + s2;
                uint4 af[4];
                #pragma unroll
                for (int i = 0; i < 4; i++)
                    af[i] = *(const uint4*)&Asm[buf*512 + s2*256 + (mw*4 + i)*32 + lane];
                uint32_t bf[4][2];
                #pragma unroll
                for (int j = 0; j < 4; j++) {
                    float2 t = *(const float2*)&Bs[ks*1024 +
                                (nw*32 + j*8 + (lane >> 2))*8 + (lane & 3)*2];
                    bf[j][0] = __float_as_uint(t.x);
                    bf[j][1] = __float_as_uint(t.y);
                }
                #pragma unroll
                for (int i = 0; i < 4; i++)
                    #pragma unroll
                    for (int j = 0; j < 4; j++)
                        mma_tf32(acc[i][j], (const uint32_t*)&af[i], bf[j]);
            }
            if (r + 1 < 8) {
                CP_WAIT0();
                __syncthreads();
            }
        }

        #pragma unroll
        for (int i = 0; i < 4; i++) {
            int m0 = mw*64 + i*16 + (lane >> 2);
            float bb0 = bias[m0], bb1 = bias[m0 + 8];
            size_t ob = ((size_t)(b*C + m0) << 14) + (size_t)(h0 + nw)*W + w0;
            #pragma unroll
            for (int j = 0; j < 4; j++) {
                int co = j*8 + (lane & 3)*2;
                *(float2*)(out + ob + co) =
                    make_float2(acc[i][j][0] + bb0, acc[i][j][1] + bb0);
                *(float2*)(out + ob + (8 << 14) + co) =
                    make_float2(acc[i][j][2] + bb1, acc[i][j][3] + bb1);
            }
        }
        __syncthreads();   // protect Asm before next set's prologue cpA
    }
}

// ---------------- local 3x3 attention + blend + residual --------------------
// 4 px/thread, float4 window loads. Halo k/v equal their conv biases.
__global__ void __launch_bounds__(256)
attn_kernel(const float* __restrict__ x, const float* __restrict__ k_b,
            const float* __restrict__ v_b, float* __restrict__ out)
{
    const int b    = blockIdx.y;
    const int tid  = threadIdx.x;
    const int row  = tid >> 5;
    const int lane = tid & 31;
    const int h    = blockIdx.x*8 + row;
    const int wq   = lane*4;
    const size_t bbase = (size_t)b*C*HW;
    const int poff = h*W + wq;

    float sims[9][4];
    #pragma unroll
    for (int o = 0; o < 9; o++)
        #pragma unroll
        for (int p = 0; p < 4; p++) sims[o][p] = 0.f;

    for (int c = 0; c < C; c++) {
        const float* kp = g_k + bbase + ((size_t)c << 14);
        float kbv = __ldg(k_b + c);
        float4 qv = *(const float4*)(g_q + bbase + ((size_t)c << 14) + poff);
        float q[4] = {qv.x, qv.y, qv.z, qv.w};
        #pragma unroll
        for (int dr = 0; dr < 3; dr++) {
            int hh = h + dr - 1;
            bool rok = ((unsigned)hh < (unsigned)H);
            const float* rp = kp + hh*W;
            float4 mid = rok ? *(const float4*)(rp + wq)
                             : make_float4(kbv, kbv, kbv, kbv);
            float lf = (rok && wq > 0)   ? rp[wq - 1] : kbv;
            float rt = (rok && wq < 124) ? rp[wq + 4] : kbv;
            float val[6] = {lf, mid.x, mid.y, mid.z, mid.w, rt};
            #pragma unroll
            for (int dj = 0; dj < 3; dj++)
                #pragma unroll
                for (int p = 0; p < 4; p++)
                    sims[dr*3 + dj][p] = fmaf(q[p], val[p + dj], sims[dr*3 + dj][p]);
        }
    }

    #pragma unroll
    for (int p = 0; p < 4; p++) {
        float mx = sims[0][p];
        #pragma unroll
        for (int o = 1; o < 9; o++) mx = fmaxf(mx, sims[o][p]);
        float se = 0.f;
        #pragma unroll
        for (int o = 0; o < 9; o++) { sims[o][p] = __expf(sims[o][p] - mx); se += sims[o][p]; }
        float inv = 1.f / se;
        #pragma unroll
        for (int o = 0; o < 9; o++) sims[o][p] *= inv;
    }

    for (int c = 0; c < C; c++) {
        const float* vp = g_v + bbase + ((size_t)c << 14);
        float vbv = __ldg(v_b + c);
        float o2[4] = {0.f, 0.f, 0.f, 0.f};
        #pragma unroll
        for (int dr = 0; dr < 3; dr++) {
            int hh = h + dr - 1;
            bool rok = ((unsigned)hh < (unsigned)H);
            const float* rp = vp + hh*W;
            float4 mid = rok ? *(const float4*)(rp + wq)
                             : make_float4(vbv, vbv, vbv, vbv);
            float lf = (rok && wq > 0)   ? rp[wq - 1] : vbv;
            float rt = (rok && wq < 124) ? rp[wq + 4] : vbv;
            float val[6] = {lf, mid.x, mid.y, mid.z, mid.w, rt};
            #pragma unroll
            for (int dj = 0; dj < 3; dj++)
                #pragma unroll
                for (int p = 0; p < 4; p++)
                    o2[p] = fmaf(sims[dr*3 + dj][p], val[p + dj], o2[p]);
        }
        size_t idx = bbase + ((size_t)c << 14) + poff;
        float4 mv = *(const float4*)(g_m    + idx);
        float4 o1 = *(const float4*)(g_out1 + idx);
        float4 xv = *(const float4*)(x      + idx);
        float4 ov;
        ov.x = xv.x + o1.x*mv.x + (1.f - mv.x)*o2[0];
        ov.y = xv.y + o1.y*mv.y + (1.f - mv.y)*o2[1];
        ov.z = xv.z + o1.z*mv.z + (1.f - mv.z)*o2[2];
        ov.w = xv.w + o1.w*mv.w + (1.f - mv.w)*o2[3];
        *(float4*)(out + idx) = ov;
    }
}

// ---------------- launch ----------------------------------------------------
#define QKV_SMEM (65536 + 16384)

extern "C" void kernel_launch(void* const* d_in, const int* in_sizes, int n_in,
                              void* d_out, int out_size)
{
    const float* x  = (const float*)d_in[0];
    const float* w1 = (const float*)d_in[1];
    const float* b1 = (const float*)d_in[2];
    const float* w2 = (const float*)d_in[3];
    const float* b2 = (const float*)d_in[4];
    const float* wm = (const float*)d_in[5];
    const float* bm = (const float*)d_in[6];
    const float* wq = (const float*)d_in[7];
    const float* bq = (const float*)d_in[8];
    const float* wk = (const float*)d_in[9];
    const float* bk = (const float*)d_in[10];
    const float* wv = (const float*)d_in[11];
    const float* bv = (const float*)d_in[12];
    float* out = (float*)d_out;

    float* y1p;   cudaGetSymbolAddress((void**)&y1p,   g_y1);
    float* tp;    cudaGetSymbolAddress((void**)&tp,    g_t);
    float* out1p; cudaGetSymbolAddress((void**)&out1p, g_out1);
    float* mp;    cudaGetSymbolAddress((void**)&mp,    g_m);

    cudaFuncSetAttribute(conv_qkv, cudaFuncAttributeMaxDynamicSharedMemorySize, QKV_SMEM);

    pack_weights<<<432, 256>>>(w1, w2, wm, wq, wk, wv);

    dim3 gc(128, BATCH);
    conv_mma<false,false><<<gc, 256>>>(x,  0, y1p,   b1);
    stats_norm_kernel<<<BATCH*C, 512>>>();
    conv_mma<false,false><<<gc, 256>>>(tp, 1, out1p, b2);
    conv_mma<true, true ><<<gc, 256>>>(tp, 2, mp,    bm);
    conv_qkv<<<gc, 256, QKV_SMEM>>>(bq, bk, bv);

    dim3 ga(H/8, BATCH);
    attn_kernel<<<ga, 256>>>(x, bk, bv, out);
}

// round 7
// speedup vs baseline: 3.6758x; 1.1053x over previous
#include <cuda_runtime.h>
#include <cstdint>

#define BATCH 8
#define C 128
#define H 128
#define W 128
#define HW (H*W)

// ---------------- scratch (device globals; no allocation allowed) ----------
__device__ float g_y1  [BATCH*C*HW];   // conv1 raw output
__device__ float g_t   [BATCH*C*HW];   // leaky(norm(y1))
__device__ float g_out1[BATCH*C*HW];
__device__ float g_m   [BATCH*C*HW];
__device__ float g_xm  [BATCH*C*HW];   // t * m
__device__ float g_q   [BATCH*C*HW];
__device__ float g_k   [BATCH*C*HW];
__device__ float g_v   [BATCH*C*HW];
__device__ float g_mu  [BATCH*C];
__device__ float g_rsig[BATCH*C];
// weights packed in per-thread mma-fragment order, tf32-converted (rna)
__device__ float4 g_wA3[3][144*8*32];
__device__ float4 g_wA1[3][16*8*32];

__constant__ int c_di[9] = {-1,-1,-1, 0,0,0, 1,1,1};
__constant__ int c_dj[9] = {-1, 0, 1,-1,0,1,-1,0,1};

__device__ __forceinline__ uint32_t f2tf32(float f) {
    uint32_t r;
    asm("cvt.rna.tf32.f32 %0, %1;" : "=r"(r) : "f"(f));
    return r;
}
__device__ __forceinline__ void mma_tf32(float* d, const uint32_t* a, const uint32_t* b) {
    asm volatile(
        "mma.sync.aligned.m16n8k8.row.col.f32.tf32.tf32.f32 "
        "{%0,%1,%2,%3}, {%4,%5,%6,%7}, {%8,%9}, {%0,%1,%2,%3};"
        : "+f"(d[0]), "+f"(d[1]), "+f"(d[2]), "+f"(d[3])
        : "r"(a[0]), "r"(a[1]), "r"(a[2]), "r"(a[3]), "r"(b[0]), "r"(b[1]));
}
__device__ __forceinline__ uint32_t smem_u32(const void* p) {
    uint32_t a;
    asm("{ .reg .u64 t; cvta.to.shared.u64 t, %1; cvt.u32.u64 %0, t; }"
        : "=r"(a) : "l"(p));
    return a;
}
#define CP_ASYNC16(dst, src) \
    asm volatile("cp.async.ca.shared.global [%0], [%1], 16;" :: "r"(dst), "l"(src))
#define CP_ASYNC4Z(dst, src, ss) \
    asm volatile("cp.async.ca.shared.global [%0], [%1], 4, %2;" :: "r"(dst), "l"(src), "r"(ss))
#define CP_COMMIT() asm volatile("cp.async.commit_group;")
#define CP_WAIT0()  asm volatile("cp.async.wait_group 0;" ::: "memory")
#define CP_WAIT1()  asm volatile("cp.async.wait_group 1;" ::: "memory")
#define CP_WAIT2()  asm volatile("cp.async.wait_group 2;" ::: "memory")

// ---------------- weight packing --------------------------------------------
__global__ void pack_weights(const float* __restrict__ w1, const float* __restrict__ w2,
                             const float* __restrict__ wm, const float* __restrict__ wq,
                             const float* __restrict__ wk, const float* __restrict__ wv)
{
    int idx = blockIdx.x * blockDim.x + threadIdx.x;
    {
        int lane = idx & 31;
        int fr   = (idx >> 5) & 7;
        int t3   = idx >> 8;
        int ks   = t3 % 144;
        int conv = t3 / 144;
        if (conv < 3) {
            const float* w = (conv == 0) ? w1 : (conv == 1) ? w2 : wm;
            int m0  = fr*16 + (lane >> 2);
            int tap = ks >> 4;
            int c   = ((ks & 15) << 3) + (lane & 3);
            float4 o;
            o.x = __uint_as_float(f2tf32(w[ m0   *1152 +  c   *9 + tap]));
            o.y = __uint_as_float(f2tf32(w[(m0+8)*1152 +  c   *9 + tap]));
            o.z = __uint_as_float(f2tf32(w[ m0   *1152 + (c+4)*9 + tap]));
            o.w = __uint_as_float(f2tf32(w[(m0+8)*1152 + (c+4)*9 + tap]));
            g_wA3[conv][(ks*8 + fr)*32 + lane] = o;
        }
    }
    if (idx < 3*16*8*32) {
        int lane = idx & 31;
        int fr   = (idx >> 5) & 7;
        int t3   = idx >> 8;
        int ks   = t3 % 16;
        int set  = t3 / 16;
        const float* w = (set == 0) ? wq : (set == 1) ? wk : wv;
        int m0 = fr*16 + (lane >> 2);
        int c  = ks*8 + (lane & 3);
        float4 o;
        o.x = __uint_as_float(f2tf32(w[ m0   *128 + c  ]));
        o.y = __uint_as_float(f2tf32(w[(m0+8)*128 + c  ]));
        o.z = __uint_as_float(f2tf32(w[ m0   *128 + c+4]));
        o.w = __uint_as_float(f2tf32(w[(m0+8)*128 + c+4]));
        g_wA1[set][(ks*8 + fr)*32 + lane] = o;
    }
}

// ---------------- fused stats + normalize (y1 -> t), full coverage ----------
__global__ void __launch_bounds__(512)
stats_norm_kernel()
{
    int bc = blockIdx.x;
    const float4* p = (const float4*)(g_y1 + (size_t)bc * HW);
    float4* d = (float4*)(g_t + (size_t)bc * HW);
    float4 vals[8];
    float s = 0.f, sq = 0.f;
    #pragma unroll
    for (int i = 0; i < 8; i++) {
        float4 v = p[threadIdx.x + 512*i];
        vals[i] = v;
        s  += (v.x + v.y) + (v.z + v.w);
        sq += v.x*v.x + v.y*v.y + v.z*v.z + v.w*v.w;
    }
    #pragma unroll
    for (int o = 16; o; o >>= 1) {
        s  += __shfl_xor_sync(0xffffffffu, s,  o);
        sq += __shfl_xor_sync(0xffffffffu, sq, o);
    }
    __shared__ float ss[16], sqq[16];
    __shared__ float s_mu, s_rs;
    int wrp = threadIdx.x >> 5;
    if ((threadIdx.x & 31) == 0) { ss[wrp] = s; sqq[wrp] = sq; }
    __syncthreads();
    if (threadIdx.x == 0) {
        float S = 0.f, Q = 0.f;
        #pragma unroll
        for (int i = 0; i < 16; i++) { S += ss[i]; Q += sqq[i]; }
        float mu  = S / (float)HW;
        float var = Q / (float)HW - mu*mu;
        float rs  = rsqrtf(var + 1e-5f);
        g_mu[bc] = mu; g_rsig[bc] = rs;
        s_mu = mu; s_rs = rs;
    }
    __syncthreads();
    float mu = s_mu, rs = s_rs;
    #pragma unroll
    for (int i = 0; i < 8; i++) {
        float4 v = vals[i];
        float t0 = (v.x - mu)*rs; t0 = (t0 < 0.f) ? 0.2f*t0 : t0;
        float t1 = (v.y - mu)*rs; t1 = (t1 < 0.f) ? 0.2f*t1 : t1;
        float t2 = (v.z - mu)*rs; t2 = (t2 < 0.f) ? 0.2f*t2 : t2;
        float t3 = (v.w - mu)*rs; t3 = (t3 < 0.f) ? 0.2f*t3 : t3;
        d[threadIdx.x + 512*i] = make_float4(t0, t1, t2, t3);
    }
}

// ---------------- tf32 mma.sync 3x3 conv, 4-stage cp.async pipeline ---------
// CTA: 128 cout (M) x 128 px (N). Warps 2(M)x4(N): warp tile 64x32.
// B is cp.async'd raw-bit fp32 (HW truncates to tf32). Zero-fill halo via
// src-size=0. B smem layout: [stage][sub][pos(8), stride 132][n(128)].
#define CV_STAGES 4
#define CV_BSTRIDE 132
#define CV_BSUB   (8*CV_BSTRIDE)        // 1056
#define CV_BSTG   (2*CV_BSUB)           // 2112
#define CV_AFLOATS (CV_STAGES*512*4)    // 8192 floats of A (float4[4][512])
#define CONV_SMEM ((CV_AFLOATS + CV_STAGES*CV_BSTG) * 4)

template<bool SIGM, bool WXM>
__global__ void __launch_bounds__(256, 2)
conv_mma(const float* __restrict__ in, int wsel, float* __restrict__ outp,
         const float* __restrict__ bias)
{
    extern __shared__ float sm[];
    float4* Asm = (float4*)sm;                 // [stage*512 + idx]
    float*  Bs  = sm + CV_AFLOATS;

    const int tid  = threadIdx.x;
    const int lane = tid & 31, wid = tid >> 5;
    const int mw = wid >> 2, nw = wid & 3;
    const int b  = blockIdx.y;
    const int h0 = (blockIdx.x >> 2) << 2;
    const int w0 = (blockIdx.x & 3) << 5;

    const float4* wA = g_wA3[wsel];

    const int sub  = tid >> 7;
    const int nn   = tid & 127;
    const int prow = nn >> 5, pcol = nn & 31;

    float acc[4][4][4];
    #pragma unroll
    for (int i = 0; i < 4; i++)
        #pragma unroll
        for (int j = 0; j < 4; j++)
            #pragma unroll
            for (int r = 0; r < 4; r++) acc[i][j][r] = 0.f;

    const uint32_t aBase = smem_u32(Asm);
    const uint32_t bBase = smem_u32(Bs);

    auto issue = [&](int r, int st) {
        const float4* srcA = wA + (size_t)r*512;
        uint32_t dA = aBase + ((st*512 + tid) << 4);
        CP_ASYNC16(dA,              srcA + tid);
        CP_ASYNC16(dA + (256 << 4), srcA + tid + 256);
        int ks  = r*2 + sub;
        int tap = ks >> 4;
        int c0  = (ks & 15) << 3;
        int ih  = h0 + prow + c_di[tap];
        int iw  = w0 + pcol + c_dj[tap];
        bool ok = ((unsigned)ih < (unsigned)H) && ((unsigned)iw < (unsigned)W);
        uint32_t ss = ok ? 4u : 0u;
        const float* src = in + ((size_t)(b*C + c0) << 14)
                         + (ok ? (size_t)(ih*W + iw) : 0);
        uint32_t dB = bBase + ((st*CV_BSTG + sub*CV_BSUB + nn) << 2);
        #pragma unroll
        for (int j = 0; j < 8; j++) {
            int pos = (j < 4) ? (2*j) : (2*(j - 4) + 1);
            CP_ASYNC4Z(dB + (uint32_t)(pos*CV_BSTRIDE*4), src + ((size_t)j << 14), ss);
        }
        CP_COMMIT();
    };

    const int NR = 72;
    issue(0, 0); issue(1, 1); issue(2, 2);

    for (int r = 0; r < NR; r++) {
        if (r <= NR - 3)      CP_WAIT2();
        else if (r == NR - 2) CP_WAIT1();
        else                  CP_WAIT0();
        __syncthreads();
        if (r + 3 < NR) issue(r + 3, (r + 3) & 3);

        int st = r & 3;
        #pragma unroll
        for (int s2 = 0; s2 < 2; s2++) {
            uint4 af[4];
            #pragma unroll
            for (int i = 0; i < 4; i++)
                af[i] = *(const uint4*)&Asm[st*512 + s2*256 + (mw*4 + i)*32 + lane];
            const float* bp = Bs + st*CV_BSTG + s2*CV_BSUB + (lane & 3)*2*CV_BSTRIDE;
            uint32_t bf[4][2];
            #pragma unroll
            for (int j = 0; j < 4; j++) {
                int n = nw*32 + j*8 + (lane >> 2);
                bf[j][0] = __float_as_uint(bp[n]);
                bf[j][1] = __float_as_uint(bp[CV_BSTRIDE + n]);
            }
            #pragma unroll
            for (int i = 0; i < 4; i++)
                #pragma unroll
                for (int j = 0; j < 4; j++)
                    mma_tf32(acc[i][j], (const uint32_t*)&af[i], bf[j]);
        }
    }

    // epilogue
    #pragma unroll
    for (int i = 0; i < 4; i++) {
        int m0 = mw*64 + i*16 + (lane >> 2);
        float bb0 = bias[m0], bb1 = bias[m0 + 8];
        size_t ob = ((size_t)(b*C + m0) << 14) + (size_t)(h0 + nw)*W + w0;
        #pragma unroll
        for (int j = 0; j < 4; j++) {
            int co = j*8 + (lane & 3)*2;
            float v0 = acc[i][j][0] + bb0, v1 = acc[i][j][1] + bb0;
            float v2 = acc[i][j][2] + bb1, v3 = acc[i][j][3] + bb1;
            if (SIGM) {
                v0 = 1.f/(1.f + __expf(-v0)); v1 = 1.f/(1.f + __expf(-v1));
                v2 = 1.f/(1.f + __expf(-v2)); v3 = 1.f/(1.f + __expf(-v3));
            }
            *(float2*)(outp + ob + co)             = make_float2(v0, v1);
            *(float2*)(outp + ob + (8 << 14) + co) = make_float2(v2, v3);
            if (WXM) {
                float2 t0 = *(const float2*)(g_t + ob + co);
                float2 t1 = *(const float2*)(g_t + ob + (8 << 14) + co);
                *(float2*)(g_xm + ob + co)             = make_float2(v0*t0.x, v1*t0.y);
                *(float2*)(g_xm + ob + (8 << 14) + co) = make_float2(v2*t1.x, v3*t1.y);
            }
        }
    }
}

// ---------------- merged q/k/v 1x1 GEMM (shared B staging) ------------------
__global__ void __launch_bounds__(256, 2)
conv_qkv(const float* __restrict__ bq, const float* __restrict__ bk,
         const float* __restrict__ bv_)
{
    extern __shared__ float sm[];
    float*  Bsq = sm;                       // 16 subs * 1024 floats = 64KB
    float4* Asq = (float4*)(sm + 16384);    // 2 * 512 float4 = 16KB

    const int tid  = threadIdx.x;
    const int lane = tid & 31, wid = tid >> 5;
    const int mw = wid >> 2, nw = wid & 3;
    const int b  = blockIdx.y;
    const int h0 = (blockIdx.x >> 2) << 2;
    const int w0 = (blockIdx.x & 3) << 5;

    const int sub  = tid >> 7;
    const int nn   = tid & 127;
    const int prow = nn >> 5, pcol = nn & 31;

    const uint32_t aBase = smem_u32(Asq);
    auto cpA = [&](const float4* wA, int r, int buf) {
        const float4* src = wA + (size_t)r*512;
        uint32_t d0 = aBase + ((buf*512 + tid) << 4);
        CP_ASYNC16(d0,               src + tid);
        CP_ASYNC16(d0 + (256 << 4),  src + tid + 256);
        CP_COMMIT();
    };

    // stage whole B (K=128), raw fp32 bits (HW tf32-truncates)
    {
        const float* src0 = (const float*)g_xm + ((size_t)(b*C) << 14)
                          + (size_t)(h0 + prow)*W + (w0 + pcol);
        #pragma unroll
        for (int it = 0; it < 8; it++) {
            int ks = it*2 + sub;
            const float* src = src0 + ((size_t)(ks*8) << 14);
            float bvr[8];
            #pragma unroll
            for (int j = 0; j < 8; j++)
                bvr[j] = src[(size_t)j << 14];
            float* bd = &Bsq[ks*1024 + nn*8];
            *(float4*)(bd)     = make_float4(bvr[0], bvr[4], bvr[1], bvr[5]);
            *(float4*)(bd + 4) = make_float4(bvr[2], bvr[6], bvr[3], bvr[7]);
        }
    }

    for (int set = 0; set < 3; set++) {
        const float4* wA = g_wA1[set];
        const float* bias = (set == 0) ? bq : (set == 1) ? bk : bv_;
        float* out = (set == 0) ? g_q : (set == 1) ? g_k : g_v;

        float acc[4][4][4];
        #pragma unroll
        for (int i = 0; i < 4; i++)
            #pragma unroll
            for (int j = 0; j < 4; j++)
                #pragma unroll
                for (int r = 0; r < 4; r++) acc[i][j][r] = 0.f;

        cpA(wA, 0, 0);
        CP_WAIT0();
        __syncthreads();

        for (int r = 0; r < 8; r++) {
            int buf = r & 1;
            if (r + 1 < 8) cpA(wA, r + 1, buf ^ 1);
            #pragma unroll
            for (int s2 = 0; s2 < 2; s2++) {
                int ks = r*2 + s2;
                uint4 af[4];
                #pragma unroll
                for (int i = 0; i < 4; i++)
                    af[i] = *(const uint4*)&Asq[buf*512 + s2*256 + (mw*4 + i)*32 + lane];
                uint32_t bf[4][2];
                #pragma unroll
                for (int j = 0; j < 4; j++) {
                    float2 t = *(const float2*)&Bsq[ks*1024 +
                                (nw*32 + j*8 + (lane >> 2))*8 + (lane & 3)*2];
                    bf[j][0] = __float_as_uint(t.x);
                    bf[j][1] = __float_as_uint(t.y);
                }
                #pragma unroll
                for (int i = 0; i < 4; i++)
                    #pragma unroll
                    for (int j = 0; j < 4; j++)
                        mma_tf32(acc[i][j], (const uint32_t*)&af[i], bf[j]);
            }
            if (r + 1 < 8) {
                CP_WAIT0();
                __syncthreads();
            }
        }

        #pragma unroll
        for (int i = 0; i < 4; i++) {
            int m0 = mw*64 + i*16 + (lane >> 2);
            float bb0 = bias[m0], bb1 = bias[m0 + 8];
            size_t ob = ((size_t)(b*C + m0) << 14) + (size_t)(h0 + nw)*W + w0;
            #pragma unroll
            for (int j = 0; j < 4; j++) {
                int co = j*8 + (lane & 3)*2;
                *(float2*)(out + ob + co) =
                    make_float2(acc[i][j][0] + bb0, acc[i][j][1] + bb0);
                *(float2*)(out + ob + (8 << 14) + co) =
                    make_float2(acc[i][j][2] + bb1, acc[i][j][3] + bb1);
            }
        }
        __syncthreads();
    }
}

// ---------------- local 3x3 attention + blend + residual --------------------
// 2-way channel split: cg0/cg1 each accumulate 64 channels of logits;
// smem-combined, cg0 softmaxes, both halves apply V. 4 px/thread.
__global__ void __launch_bounds__(256)
attn_kernel(const float* __restrict__ x, const float* __restrict__ k_b,
            const float* __restrict__ v_b, float* __restrict__ out)
{
    __shared__ float att[4][32][37];

    const int b    = blockIdx.y;
    const int tid  = threadIdx.x;
    const int cg   = tid >> 7;
    const int t    = tid & 127;
    const int row  = t >> 5;
    const int lane = t & 31;
    const int h    = blockIdx.x*4 + row;
    const int wq   = lane*4;
    const size_t bbase = (size_t)b*C*HW;
    const int poff = h*W + wq;
    const int c0 = cg*64;

    float sims[9][4];
    #pragma unroll
    for (int o = 0; o < 9; o++)
        #pragma unroll
        for (int p = 0; p < 4; p++) sims[o][p] = 0.f;

    for (int ci = 0; ci < 64; ci++) {
        int c = c0 + ci;
        const float* kp = g_k + bbase + ((size_t)c << 14);
        float kbv = __ldg(k_b + c);
        float4 qv = *(const float4*)(g_q + bbase + ((size_t)c << 14) + poff);
        float q[4] = {qv.x, qv.y, qv.z, qv.w};
        #pragma unroll
        for (int dr = 0; dr < 3; dr++) {
            int hh = h + dr - 1;
            bool rok = ((unsigned)hh < (unsigned)H);
            const float* rp = kp + hh*W;
            float4 mid = rok ? *(const float4*)(rp + wq)
                             : make_float4(kbv, kbv, kbv, kbv);
            float lf = (rok && wq > 0)   ? rp[wq - 1] : kbv;
            float rt = (rok && wq < 124) ? rp[wq + 4] : kbv;
            float val[6] = {lf, mid.x, mid.y, mid.z, mid.w, rt};
            #pragma unroll
            for (int dj = 0; dj < 3; dj++)
                #pragma unroll
                for (int p = 0; p < 4; p++)
                    sims[dr*3 + dj][p] = fmaf(q[p], val[p + dj], sims[dr*3 + dj][p]);
        }
    }

    if (cg == 1) {
        #pragma unroll
        for (int o = 0; o < 9; o++)
            #pragma unroll
            for (int p = 0; p < 4; p++)
                att[row][lane][o*4 + p] = sims[o][p];
    }
    __syncthreads();
    if (cg == 0) {
        #pragma unroll
        for (int o = 0; o < 9; o++)
            #pragma unroll
            for (int p = 0; p < 4; p++)
                sims[o][p] += att[row][lane][o*4 + p];
        #pragma unroll
        for (int p = 0; p < 4; p++) {
            float mx = sims[0][p];
            #pragma unroll
            for (int o = 1; o < 9; o++) mx = fmaxf(mx, sims[o][p]);
            float se = 0.f;
            #pragma unroll
            for (int o = 0; o < 9; o++) { sims[o][p] = __expf(sims[o][p] - mx); se += sims[o][p]; }
            float inv = 1.f / se;
            #pragma unroll
            for (int o = 0; o < 9; o++) sims[o][p] *= inv;
        }
        #pragma unroll
        for (int o = 0; o < 9; o++)
            #pragma unroll
            for (int p = 0; p < 4; p++)
                att[row][lane][o*4 + p] = sims[o][p];
    }
    __syncthreads();
    #pragma unroll
    for (int o = 0; o < 9; o++)
        #pragma unroll
        for (int p = 0; p < 4; p++)
            sims[o][p] = att[row][lane][o*4 + p];

    for (int ci = 0; ci < 64; ci++) {
        int c = c0 + ci;
        const float* vp = g_v + bbase + ((size_t)c << 14);
        float vbv = __ldg(v_b + c);
        float o2[4] = {0.f, 0.f, 0.f, 0.f};
        #pragma unroll
        for (int dr = 0; dr < 3; dr++) {
            int hh = h + dr - 1;
            bool rok = ((unsigned)hh < (unsigned)H);
            const float* rp = vp + hh*W;
            float4 mid = rok ? *(const float4*)(rp + wq)
                             : make_float4(vbv, vbv, vbv, vbv);
            float lf = (rok && wq > 0)   ? rp[wq - 1] : vbv;
            float rt = (rok && wq < 124) ? rp[wq + 4] : vbv;
            float val[6] = {lf, mid.x, mid.y, mid.z, mid.w, rt};
            #pragma unroll
            for (int dj = 0; dj < 3; dj++)
                #pragma unroll
                for (int p = 0; p < 4; p++)
                    o2[p] = fmaf(sims[dr*3 + dj][p], val[p + dj], o2[p]);
        }
        size_t idx = bbase + ((size_t)c << 14) + poff;
        float4 mv = *(const float4*)(g_m    + idx);
        float4 o1 = *(const float4*)(g_out1 + idx);
        float4 xv = *(const float4*)(x      + idx);
        float4 ov;
        ov.x = xv.x + o1.x*mv.x + (1.f - mv.x)*o2[0];
        ov.y = xv.y + o1.y*mv.y + (1.f - mv.y)*o2[1];
        ov.z = xv.z + o1.z*mv.z + (1.f - mv.z)*o2[2];
        ov.w = xv.w + o1.w*mv.w + (1.f - mv.w)*o2[3];
        *(float4*)(out + idx) = ov;
    }
}

// ---------------- launch ----------------------------------------------------
#define QKV_SMEM (65536 + 16384)

extern "C" void kernel_launch(void* const* d_in, const int* in_sizes, int n_in,
                              void* d_out, int out_size)
{
    const float* x  = (const float*)d_in[0];
    const float* w1 = (const float*)d_in[1];
    const float* b1 = (const float*)d_in[2];
    const float* w2 = (const float*)d_in[3];
    const float* b2 = (const float*)d_in[4];
    const float* wm = (const float*)d_in[5];
    const float* bm = (const float*)d_in[6];
    const float* wq = (const float*)d_in[7];
    const float* bq = (const float*)d_in[8];
    const float* wk = (const float*)d_in[9];
    const float* bk = (const float*)d_in[10];
    const float* wv = (const float*)d_in[11];
    const float* bv = (const float*)d_in[12];
    float* out = (float*)d_out;

    float* y1p;   cudaGetSymbolAddress((void**)&y1p,   g_y1);
    float* tp;    cudaGetSymbolAddress((void**)&tp,    g_t);
    float* out1p; cudaGetSymbolAddress((void**)&out1p, g_out1);
    float* mp;    cudaGetSymbolAddress((void**)&mp,    g_m);

    cudaFuncSetAttribute(conv_mma<false,false>, cudaFuncAttributeMaxDynamicSharedMemorySize, CONV_SMEM);
    cudaFuncSetAttribute(conv_mma<true, true >, cudaFuncAttributeMaxDynamicSharedMemorySize, CONV_SMEM);
    cudaFuncSetAttribute(conv_qkv, cudaFuncAttributeMaxDynamicSharedMemorySize, QKV_SMEM);

    pack_weights<<<432, 256>>>(w1, w2, wm, wq, wk, wv);

    dim3 gc(128, BATCH);
    conv_mma<false,false><<<gc, 256, CONV_SMEM>>>(x,  0, y1p,   b1);
    stats_norm_kernel<<<BATCH*C, 512>>>();
    conv_mma<false,false><<<gc, 256, CONV_SMEM>>>(tp, 1, out1p, b2);
    conv_mma<true, true ><<<gc, 256, CONV_SMEM>>>(tp, 2, mp,    bm);
    conv_qkv<<<gc, 256, QKV_SMEM>>>(bq, bk, bv);

    dim3 ga(H/4, BATCH);
    attn_kernel<<<ga, 256>>>(x, bk, bv, out);
}

// round 8
// speedup vs baseline: 3.7555x; 1.0217x over previous
#include <cuda_runtime.h>
#include <cstdint>

#define BATCH 8
#define C 128
#define H 128
#define W 128
#define HW (H*W)

// ---------------- scratch (device globals; no allocation allowed) ----------
__device__ float g_y1  [BATCH*C*HW];   // conv1 raw output
__device__ float g_t   [BATCH*C*HW];   // leaky(norm(y1))
__device__ float g_out1[BATCH*C*HW];
__device__ float g_m   [BATCH*C*HW];
__device__ float g_xm  [BATCH*C*HW];   // t * m
__device__ float g_q   [BATCH*C*HW];
__device__ float g_k   [BATCH*C*HW];
__device__ float g_v   [BATCH*C*HW];
__device__ float g_mu  [BATCH*C];
__device__ float g_rsig[BATCH*C];
// weights packed in per-thread mma-fragment order, tf32-converted (rna)
__device__ float4 g_wA3[3][144*8*32];
__device__ float4 g_wA1[3][16*8*32];

__constant__ int c_di[9] = {-1,-1,-1, 0,0,0, 1,1,1};
__constant__ int c_dj[9] = {-1, 0, 1,-1,0,1,-1,0,1};

__device__ __forceinline__ uint32_t f2tf32(float f) {
    uint32_t r;
    asm("cvt.rna.tf32.f32 %0, %1;" : "=r"(r) : "f"(f));
    return r;
}
__device__ __forceinline__ void mma_tf32(float* d, const uint32_t* a, const uint32_t* b) {
    asm volatile(
        "mma.sync.aligned.m16n8k8.row.col.f32.tf32.tf32.f32 "
        "{%0,%1,%2,%3}, {%4,%5,%6,%7}, {%8,%9}, {%0,%1,%2,%3};"
        : "+f"(d[0]), "+f"(d[1]), "+f"(d[2]), "+f"(d[3])
        : "r"(a[0]), "r"(a[1]), "r"(a[2]), "r"(a[3]), "r"(b[0]), "r"(b[1]));
}
__device__ __forceinline__ uint32_t smem_u32(const void* p) {
    uint32_t a;
    asm("{ .reg .u64 t; cvta.to.shared.u64 t, %1; cvt.u32.u64 %0, t; }"
        : "=r"(a) : "l"(p));
    return a;
}
#define CP_ASYNC16(dst, src) \
    asm volatile("cp.async.ca.shared.global [%0], [%1], 16;" :: "r"(dst), "l"(src))
#define CP_ASYNC4Z(dst, src, ss) \
    asm volatile("cp.async.ca.shared.global [%0], [%1], 4, %2;" :: "r"(dst), "l"(src), "r"(ss))
#define CP_COMMIT() asm volatile("cp.async.commit_group;")
#define CP_WAIT0()  asm volatile("cp.async.wait_group 0;" ::: "memory")
#define CP_WAIT1()  asm volatile("cp.async.wait_group 1;" ::: "memory")
#define CP_WAIT2()  asm volatile("cp.async.wait_group 2;" ::: "memory")

// ---------------- weight packing --------------------------------------------
__global__ void pack_weights(const float* __restrict__ w1, const float* __restrict__ w2,
                             const float* __restrict__ wm, const float* __restrict__ wq,
                             const float* __restrict__ wk, const float* __restrict__ wv)
{
    int idx = blockIdx.x * blockDim.x + threadIdx.x;
    {
        int lane = idx & 31;
        int fr   = (idx >> 5) & 7;
        int t3   = idx >> 8;
        int ks   = t3 % 144;
        int conv = t3 / 144;
        if (conv < 3) {
            const float* w = (conv == 0) ? w1 : (conv == 1) ? w2 : wm;
            int m0  = fr*16 + (lane >> 2);
            int tap = ks >> 4;
            int c   = ((ks & 15) << 3) + (lane & 3);
            float4 o;
            o.x = __uint_as_float(f2tf32(w[ m0   *1152 +  c   *9 + tap]));
            o.y = __uint_as_float(f2tf32(w[(m0+8)*1152 +  c   *9 + tap]));
            o.z = __uint_as_float(f2tf32(w[ m0   *1152 + (c+4)*9 + tap]));
            o.w = __uint_as_float(f2tf32(w[(m0+8)*1152 + (c+4)*9 + tap]));
            g_wA3[conv][(ks*8 + fr)*32 + lane] = o;
        }
    }
    if (idx < 3*16*8*32) {
        int lane = idx & 31;
        int fr   = (idx >> 5) & 7;
        int t3   = idx >> 8;
        int ks   = t3 % 16;
        int set  = t3 / 16;
        const float* w = (set == 0) ? wq : (set == 1) ? wk : wv;
        int m0 = fr*16 + (lane >> 2);
        int c  = ks*8 + (lane & 3);
        float4 o;
        o.x = __uint_as_float(f2tf32(w[ m0   *128 + c  ]));
        o.y = __uint_as_float(f2tf32(w[(m0+8)*128 + c  ]));
        o.z = __uint_as_float(f2tf32(w[ m0   *128 + c+4]));
        o.w = __uint_as_float(f2tf32(w[(m0+8)*128 + c+4]));
        g_wA1[set][(ks*8 + fr)*32 + lane] = o;
    }
}

// ---------------- fused stats + normalize (y1 -> t) -------------------------
__global__ void __launch_bounds__(512)
stats_norm_kernel()
{
    int bc = blockIdx.x;
    const float4* p = (const float4*)(g_y1 + (size_t)bc * HW);
    float4* d = (float4*)(g_t + (size_t)bc * HW);
    float4 vals[8];
    float s = 0.f, sq = 0.f;
    #pragma unroll
    for (int i = 0; i < 8; i++) {
        float4 v = p[threadIdx.x + 512*i];
        vals[i] = v;
        s  += (v.x + v.y) + (v.z + v.w);
        sq += v.x*v.x + v.y*v.y + v.z*v.z + v.w*v.w;
    }
    #pragma unroll
    for (int o = 16; o; o >>= 1) {
        s  += __shfl_xor_sync(0xffffffffu, s,  o);
        sq += __shfl_xor_sync(0xffffffffu, sq, o);
    }
    __shared__ float ss[16], sqq[16];
    __shared__ float s_mu, s_rs;
    int wrp = threadIdx.x >> 5;
    if ((threadIdx.x & 31) == 0) { ss[wrp] = s; sqq[wrp] = sq; }
    __syncthreads();
    if (threadIdx.x == 0) {
        float S = 0.f, Q = 0.f;
        #pragma unroll
        for (int i = 0; i < 16; i++) { S += ss[i]; Q += sqq[i]; }
        float mu  = S / (float)HW;
        float var = Q / (float)HW - mu*mu;
        float rs  = rsqrtf(var + 1e-5f);
        g_mu[bc] = mu; g_rsig[bc] = rs;
        s_mu = mu; s_rs = rs;
    }
    __syncthreads();
    float mu = s_mu, rs = s_rs;
    #pragma unroll
    for (int i = 0; i < 8; i++) {
        float4 v = vals[i];
        float t0 = (v.x - mu)*rs; t0 = (t0 < 0.f) ? 0.2f*t0 : t0;
        float t1 = (v.y - mu)*rs; t1 = (t1 < 0.f) ? 0.2f*t1 : t1;
        float t2 = (v.z - mu)*rs; t2 = (t2 < 0.f) ? 0.2f*t2 : t2;
        float t3 = (v.w - mu)*rs; t3 = (t3 < 0.f) ? 0.2f*t3 : t3;
        d[threadIdx.x + 512*i] = make_float4(t0, t1, t2, t3);
    }
}

// ---------------- shared constants for conv kernels --------------------------
#define CV_STAGES 4
#define CV_BSTRIDE 132
#define CV_BSUB   (8*CV_BSTRIDE)        // 1056
#define CV_BSTG   (2*CV_BSUB)           // 2112

// ---------------- conv1: single-output 3x3 tf32 conv ------------------------
#define CV_AFLOATS (CV_STAGES*512*4)
#define CONV_SMEM ((CV_AFLOATS + CV_STAGES*CV_BSTG) * 4)

__global__ void __launch_bounds__(256, 2)
conv_mma(const float* __restrict__ in, int wsel, float* __restrict__ outp,
         const float* __restrict__ bias)
{
    extern __shared__ float sm[];
    float4* Asm = (float4*)sm;
    float*  Bs  = sm + CV_AFLOATS;

    const int tid  = threadIdx.x;
    const int lane = tid & 31, wid = tid >> 5;
    const int mw = wid >> 2, nw = wid & 3;
    const int b  = blockIdx.y;
    const int h0 = (blockIdx.x >> 2) << 2;
    const int w0 = (blockIdx.x & 3) << 5;

    const float4* wA = g_wA3[wsel];

    const int sub  = tid >> 7;
    const int nn   = tid & 127;
    const int prow = nn >> 5, pcol = nn & 31;

    float acc[4][4][4];
    #pragma unroll
    for (int i = 0; i < 4; i++)
        #pragma unroll
        for (int j = 0; j < 4; j++)
            #pragma unroll
            for (int r = 0; r < 4; r++) acc[i][j][r] = 0.f;

    const uint32_t aBase = smem_u32(Asm);
    const uint32_t bBase = smem_u32(Bs);

    auto issue = [&](int r, int st) {
        const float4* srcA = wA + (size_t)r*512;
        uint32_t dA = aBase + ((st*512 + tid) << 4);
        CP_ASYNC16(dA,              srcA + tid);
        CP_ASYNC16(dA + (256 << 4), srcA + tid + 256);
        int ks  = r*2 + sub;
        int tap = ks >> 4;
        int c0  = (ks & 15) << 3;
        int ih  = h0 + prow + c_di[tap];
        int iw  = w0 + pcol + c_dj[tap];
        bool ok = ((unsigned)ih < (unsigned)H) && ((unsigned)iw < (unsigned)W);
        uint32_t ss = ok ? 4u : 0u;
        const float* src = in + ((size_t)(b*C + c0) << 14)
                         + (ok ? (size_t)(ih*W + iw) : 0);
        uint32_t dB = bBase + ((st*CV_BSTG + sub*CV_BSUB + nn) << 2);
        #pragma unroll
        for (int j = 0; j < 8; j++) {
            int pos = (j < 4) ? (2*j) : (2*(j - 4) + 1);
            CP_ASYNC4Z(dB + (uint32_t)(pos*CV_BSTRIDE*4), src + ((size_t)j << 14), ss);
        }
        CP_COMMIT();
    };

    const int NR = 72;
    issue(0, 0); issue(1, 1); issue(2, 2);

    for (int r = 0; r < NR; r++) {
        if (r <= NR - 3)      CP_WAIT2();
        else if (r == NR - 2) CP_WAIT1();
        else                  CP_WAIT0();
        __syncthreads();
        if (r + 3 < NR) issue(r + 3, (r + 3) & 3);

        int st = r & 3;
        #pragma unroll
        for (int s2 = 0; s2 < 2; s2++) {
            uint4 af[4];
            #pragma unroll
            for (int i = 0; i < 4; i++)
                af[i] = *(const uint4*)&Asm[st*512 + s2*256 + (mw*4 + i)*32 + lane];
            const float* bp = Bs + st*CV_BSTG + s2*CV_BSUB + (lane & 3)*2*CV_BSTRIDE;
            uint32_t bf[4][2];
            #pragma unroll
            for (int j = 0; j < 4; j++) {
                int n = nw*32 + j*8 + (lane >> 2);
                bf[j][0] = __float_as_uint(bp[n]);
                bf[j][1] = __float_as_uint(bp[CV_BSTRIDE + n]);
            }
            #pragma unroll
            for (int i = 0; i < 4; i++)
                #pragma unroll
                for (int j = 0; j < 4; j++)
                    mma_tf32(acc[i][j], (const uint32_t*)&af[i], bf[j]);
        }
    }

    #pragma unroll
    for (int i = 0; i < 4; i++) {
        int m0 = mw*64 + i*16 + (lane >> 2);
        float bb0 = bias[m0], bb1 = bias[m0 + 8];
        size_t ob = ((size_t)(b*C + m0) << 14) + (size_t)(h0 + nw)*W + w0;
        #pragma unroll
        for (int j = 0; j < 4; j++) {
            int co = j*8 + (lane & 3)*2;
            *(float2*)(outp + ob + co) =
                make_float2(acc[i][j][0] + bb0, acc[i][j][1] + bb0);
            *(float2*)(outp + ob + (8 << 14) + co) =
                make_float2(acc[i][j][2] + bb1, acc[i][j][3] + bb1);
        }
    }
}

// ---------------- merged conv2 + mask (shared B, dual accumulators) ---------
#define CV2_AFLOATS (CV_STAGES*1024*4)
#define CONV2_SMEM ((CV2_AFLOATS + CV_STAGES*CV_BSTG) * 4)

__global__ void __launch_bounds__(256, 1)
conv_mma2(const float* __restrict__ in,
          const float* __restrict__ b2, const float* __restrict__ bm)
{
    extern __shared__ float sm[];
    float4* Asm = (float4*)sm;                 // [stage][set][512]
    float*  Bs  = sm + CV2_AFLOATS;

    const int tid  = threadIdx.x;
    const int lane = tid & 31, wid = tid >> 5;
    const int mw = wid >> 2, nw = wid & 3;
    const int b  = blockIdx.y;
    const int h0 = (blockIdx.x >> 2) << 2;
    const int w0 = (blockIdx.x & 3) << 5;

    const float4* wA2 = g_wA3[1];
    const float4* wAm = g_wA3[2];

    const int sub  = tid >> 7;
    const int nn   = tid & 127;
    const int prow = nn >> 5, pcol = nn & 31;

    float acc[2][4][4][4];
    #pragma unroll
    for (int q = 0; q < 2; q++)
        #pragma unroll
        for (int i = 0; i < 4; i++)
            #pragma unroll
            for (int j = 0; j < 4; j++)
                #pragma unroll
                for (int r = 0; r < 4; r++) acc[q][i][j][r] = 0.f;

    const uint32_t aBase = smem_u32(Asm);
    const uint32_t bBase = smem_u32(Bs);

    auto issue = [&](int r, int st) {
        const float4* sA2 = wA2 + (size_t)r*512;
        const float4* sAm = wAm + (size_t)r*512;
        uint32_t dA = aBase + ((st*1024 + tid) << 4);
        CP_ASYNC16(dA,              sA2 + tid);
        CP_ASYNC16(dA + (256 << 4), sA2 + tid + 256);
        CP_ASYNC16(dA + (512 << 4), sAm + tid);
        CP_ASYNC16(dA + (768 << 4), sAm + tid + 256);
        int ks  = r*2 + sub;
        int tap = ks >> 4;
        int c0  = (ks & 15) << 3;
        int ih  = h0 + prow + c_di[tap];
        int iw  = w0 + pcol + c_dj[tap];
        bool ok = ((unsigned)ih < (unsigned)H) && ((unsigned)iw < (unsigned)W);
        uint32_t ss = ok ? 4u : 0u;
        const float* src = in + ((size_t)(b*C + c0) << 14)
                         + (ok ? (size_t)(ih*W + iw) : 0);
        uint32_t dB = bBase + ((st*CV_BSTG + sub*CV_BSUB + nn) << 2);
        #pragma unroll
        for (int j = 0; j < 8; j++) {
            int pos = (j < 4) ? (2*j) : (2*(j - 4) + 1);
            CP_ASYNC4Z(dB + (uint32_t)(pos*CV_BSTRIDE*4), src + ((size_t)j << 14), ss);
        }
        CP_COMMIT();
    };

    const int NR = 72;
    issue(0, 0); issue(1, 1); issue(2, 2);

    for (int r = 0; r < NR; r++) {
        if (r <= NR - 3)      CP_WAIT2();
        else if (r == NR - 2) CP_WAIT1();
        else                  CP_WAIT0();
        __syncthreads();
        if (r + 3 < NR) issue(r + 3, (r + 3) & 3);

        int st = r & 3;
        #pragma unroll
        for (int s2 = 0; s2 < 2; s2++) {
            const float* bp = Bs + st*CV_BSTG + s2*CV_BSUB + (lane & 3)*2*CV_BSTRIDE;
            uint32_t bf[4][2];
            #pragma unroll
            for (int j = 0; j < 4; j++) {
                int n = nw*32 + j*8 + (lane >> 2);
                bf[j][0] = __float_as_uint(bp[n]);
                bf[j][1] = __float_as_uint(bp[CV_BSTRIDE + n]);
            }
            #pragma unroll
            for (int q = 0; q < 2; q++) {
                #pragma unroll
                for (int i = 0; i < 4; i++) {
                    uint4 af = *(const uint4*)&Asm[st*1024 + q*512 + s2*256
                                                   + (mw*4 + i)*32 + lane];
                    #pragma unroll
                    for (int j = 0; j < 4; j++)
                        mma_tf32(acc[q][i][j], (const uint32_t*)&af, bf[j]);
                }
            }
        }
    }

    // epilogue: out1 = acc0+b2; m = sigmoid(acc1+bm); xm = t*m
    #pragma unroll
    for (int i = 0; i < 4; i++) {
        int m0 = mw*64 + i*16 + (lane >> 2);
        float c20 = b2[m0], c21 = b2[m0 + 8];
        float m20 = bm[m0], m21 = bm[m0 + 8];
        size_t ob = ((size_t)(b*C + m0) << 14) + (size_t)(h0 + nw)*W + w0;
        #pragma unroll
        for (int j = 0; j < 4; j++) {
            int co = j*8 + (lane & 3)*2;
            float o0 = acc[0][i][j][0] + c20, o1 = acc[0][i][j][1] + c20;
            float o2 = acc[0][i][j][2] + c21, o3 = acc[0][i][j][3] + c21;
            float s0 = 1.f/(1.f + __expf(-(acc[1][i][j][0] + m20)));
            float s1 = 1.f/(1.f + __expf(-(acc[1][i][j][1] + m20)));
            float s2 = 1.f/(1.f + __expf(-(acc[1][i][j][2] + m21)));
            float s3 = 1.f/(1.f + __expf(-(acc[1][i][j][3] + m21)));
            *(float2*)(g_out1 + ob + co)             = make_float2(o0, o1);
            *(float2*)(g_out1 + ob + (8 << 14) + co) = make_float2(o2, o3);
            *(float2*)(g_m + ob + co)                = make_float2(s0, s1);
            *(float2*)(g_m + ob + (8 << 14) + co)    = make_float2(s2, s3);
            float2 t0 = *(const float2*)(g_t + ob + co);
            float2 t1 = *(const float2*)(g_t + ob + (8 << 14) + co);
            *(float2*)(g_xm + ob + co)               = make_float2(s0*t0.x, s1*t0.y);
            *(float2*)(g_xm + ob + (8 << 14) + co)   = make_float2(s2*t1.x, s3*t1.y);
        }
    }
}

// ---------------- merged q/k/v 1x1 GEMM (shared B staging) ------------------
__global__ void __launch_bounds__(256, 2)
conv_qkv(const float* __restrict__ bq, const float* __restrict__ bk,
         const float* __restrict__ bv_)
{
    extern __shared__ float sm[];
    float*  Bsq = sm;
    float4* Asq = (float4*)(sm + 16384);

    const int tid  = threadIdx.x;
    const int lane = tid & 31, wid = tid >> 5;
    const int mw = wid >> 2, nw = wid & 3;
    const int b  = blockIdx.y;
    const int h0 = (blockIdx.x >> 2) << 2;
    const int w0 = (blockIdx.x & 3) << 5;

    const int sub  = tid >> 7;
    const int nn   = tid & 127;
    const int prow = nn >> 5, pcol = nn & 31;

    const uint32_t aBase = smem_u32(Asq);
    auto cpA = [&](const float4* wA, int r, int buf) {
        const float4* src = wA + (size_t)r*512;
        uint32_t d0 = aBase + ((buf*512 + tid) << 4);
        CP_ASYNC16(d0,               src + tid);
        CP_ASYNC16(d0 + (256 << 4),  src + tid + 256);
        CP_COMMIT();
    };

    {
        const float* src0 = (const float*)g_xm + ((size_t)(b*C) << 14)
                          + (size_t)(h0 + prow)*W + (w0 + pcol);
        #pragma unroll
        for (int it = 0; it < 8; it++) {
            int ks = it*2 + sub;
            const float* src = src0 + ((size_t)(ks*8) << 14);
            float bvr[8];
            #pragma unroll
            for (int j = 0; j < 8; j++)
                bvr[j] = src[(size_t)j << 14];
            float* bd = &Bsq[ks*1024 + nn*8];
            *(float4*)(bd)     = make_float4(bvr[0], bvr[4], bvr[1], bvr[5]);
            *(float4*)(bd + 4) = make_float4(bvr[2], bvr[6], bvr[3], bvr[7]);
        }
    }

    for (int set = 0; set < 3; set++) {
        const float4* wA = g_wA1[set];
        const float* bias = (set == 0) ? bq : (set == 1) ? bk : bv_;
        float* out = (set == 0) ? g_q : (set == 1) ? g_k : g_v;

        float acc[4][4][4];
        #pragma unroll
        for (int i = 0; i < 4; i++)
            #pragma unroll
            for (int j = 0; j < 4; j++)
                #pragma unroll
                for (int r = 0; r < 4; r++) acc[i][j][r] = 0.f;

        cpA(wA, 0, 0);
        CP_WAIT0();
        __syncthreads();

        for (int r = 0; r < 8; r++) {
            int buf = r & 1;
            if (r + 1 < 8) cpA(wA, r + 1, buf ^ 1);
            #pragma unroll
            for (int s2 = 0; s2 < 2; s2++) {
                int ks = r*2 + s2;
                uint4 af[4];
                #pragma unroll
                for (int i = 0; i < 4; i++)
                    af[i] = *(const uint4*)&Asq[buf*512 + s2*256 + (mw*4 + i)*32 + lane];
                uint32_t bf[4][2];
                #pragma unroll
                for (int j = 0; j < 4; j++) {
                    float2 t = *(const float2*)&Bsq[ks*1024 +
                                (nw*32 + j*8 + (lane >> 2))*8 + (lane & 3)*2];
                    bf[j][0] = __float_as_uint(t.x);
                    bf[j][1] = __float_as_uint(t.y);
                }
                #pragma unroll
                for (int i = 0; i < 4; i++)
                    #pragma unroll
                    for (int j = 0; j < 4; j++)
                        mma_tf32(acc[i][j], (const uint32_t*)&af[i], bf[j]);
            }
            if (r + 1 < 8) {
                CP_WAIT0();
                __syncthreads();
            }
        }

        #pragma unroll
        for (int i = 0; i < 4; i++) {
            int m0 = mw*64 + i*16 + (lane >> 2);
            float bb0 = bias[m0], bb1 = bias[m0 + 8];
            size_t ob = ((size_t)(b*C + m0) << 14) + (size_t)(h0 + nw)*W + w0;
            #pragma unroll
            for (int j = 0; j < 4; j++) {
                int co = j*8 + (lane & 3)*2;
                *(float2*)(out + ob + co) =
                    make_float2(acc[i][j][0] + bb0, acc[i][j][1] + bb0);
                *(float2*)(out + ob + (8 << 14) + co) =
                    make_float2(acc[i][j][2] + bb1, acc[i][j][3] + bb1);
            }
        }
        __syncthreads();
    }
}

// ---------------- local 3x3 attention + blend + residual --------------------
// 4-way channel split (32 ch each); logits combined in smem; each group
// redundantly softmaxes; one __syncthreads total. 4 px/thread, 2 rows/CTA.
__global__ void __launch_bounds__(256)
attn_kernel(const float* __restrict__ x, const float* __restrict__ k_b,
            const float* __restrict__ v_b, float* __restrict__ out)
{
    __shared__ float att[4][2][32][37];

    const int b    = blockIdx.y;
    const int tid  = threadIdx.x;
    const int cg   = tid >> 6;
    const int t    = tid & 63;
    const int row  = t >> 5;
    const int lane = t & 31;
    const int h    = blockIdx.x*2 + row;
    const int wq   = lane*4;
    const size_t bbase = (size_t)b*C*HW;
    const int poff = h*W + wq;
    const int c0 = cg*32;

    float sims[9][4];
    #pragma unroll
    for (int o = 0; o < 9; o++)
        #pragma unroll
        for (int p = 0; p < 4; p++) sims[o][p] = 0.f;

    for (int ci = 0; ci < 32; ci++) {
        int c = c0 + ci;
        const float* kp = g_k + bbase + ((size_t)c << 14);
        float kbv = __ldg(k_b + c);
        float4 qv = *(const float4*)(g_q + bbase + ((size_t)c << 14) + poff);
        float q[4] = {qv.x, qv.y, qv.z, qv.w};
        #pragma unroll
        for (int dr = 0; dr < 3; dr++) {
            int hh = h + dr - 1;
            bool rok = ((unsigned)hh < (unsigned)H);
            const float* rp = kp + hh*W;
            float4 mid = rok ? *(const float4*)(rp + wq)
                             : make_float4(kbv, kbv, kbv, kbv);
            float lf = (rok && wq > 0)   ? rp[wq - 1] : kbv;
            float rt = (rok && wq < 124) ? rp[wq + 4] : kbv;
            float val[6] = {lf, mid.x, mid.y, mid.z, mid.w, rt};
            #pragma unroll
            for (int dj = 0; dj < 3; dj++)
                #pragma unroll
                for (int p = 0; p < 4; p++)
                    sims[dr*3 + dj][p] = fmaf(q[p], val[p + dj], sims[dr*3 + dj][p]);
        }
    }

    #pragma unroll
    for (int o = 0; o < 9; o++)
        #pragma unroll
        for (int p = 0; p < 4; p++)
            att[cg][row][lane][o*4 + p] = sims[o][p];
    __syncthreads();

    // every thread sums all 4 groups and softmaxes (redundant but sync-free)
    #pragma unroll
    for (int o = 0; o < 9; o++)
        #pragma unroll
        for (int p = 0; p < 4; p++)
            sims[o][p] = att[0][row][lane][o*4 + p] + att[1][row][lane][o*4 + p]
                       + att[2][row][lane][o*4 + p] + att[3][row][lane][o*4 + p];
    #pragma unroll
    for (int p = 0; p < 4; p++) {
        float mx = sims[0][p];
        #pragma unroll
        for (int o = 1; o < 9; o++) mx = fmaxf(mx, sims[o][p]);
        float se = 0.f;
        #pragma unroll
        for (int o = 0; o < 9; o++) { sims[o][p] = __expf(sims[o][p] - mx); se += sims[o][p]; }
        float inv = 1.f / se;
        #pragma unroll
        for (int o = 0; o < 9; o++) sims[o][p] *= inv;
    }

    for (int ci = 0; ci < 32; ci++) {
        int c = c0 + ci;
        const float* vp = g_v + bbase + ((size_t)c << 14);
        float vbv = __ldg(v_b + c);
        float o2[4] = {0.f, 0.f, 0.f, 0.f};
        #pragma unroll
        for (int dr = 0; dr < 3; dr++) {
            int hh = h + dr - 1;
            bool rok = ((unsigned)hh < (unsigned)H);
            const float* rp = vp + hh*W;
            float4 mid = rok ? *(const float4*)(rp + wq)
                             : make_float4(vbv, vbv, vbv, vbv);
            float lf = (rok && wq > 0)   ? rp[wq - 1] : vbv;
            float rt = (rok && wq < 124) ? rp[wq + 4] : vbv;
            float val[6] = {lf, mid.x, mid.y, mid.z, mid.w, rt};
            #pragma unroll
            for (int dj = 0; dj < 3; dj++)
                #pragma unroll
                for (int p = 0; p < 4; p++)
                    o2[p] = fmaf(sims[dr*3 + dj][p], val[p + dj], o2[p]);
        }
        size_t idx = bbase + ((size_t)c << 14) + poff;
        float4 mv = *(const float4*)(g_m    + idx);
        float4 o1 = *(const float4*)(g_out1 + idx);
        float4 xv = *(const float4*)(x      + idx);
        float4 ov;
        ov.x = xv.x + o1.x*mv.x + (1.f - mv.x)*o2[0];
        ov.y = xv.y + o1.y*mv.y + (1.f - mv.y)*o2[1];
        ov.z = xv.z + o1.z*mv.z + (1.f - mv.z)*o2[2];
        ov.w = xv.w + o1.w*mv.w + (1.f - mv.w)*o2[3];
        *(float4*)(out + idx) = ov;
    }
}

// ---------------- launch ----------------------------------------------------
#define QKV_SMEM (65536 + 16384)

extern "C" void kernel_launch(void* const* d_in, const int* in_sizes, int n_in,
                              void* d_out, int out_size)
{
    const float* x  = (const float*)d_in[0];
    const float* w1 = (const float*)d_in[1];
    const float* b1 = (const float*)d_in[2];
    const float* w2 = (const float*)d_in[3];
    const float* b2 = (const float*)d_in[4];
    const float* wm = (const float*)d_in[5];
    const float* bm = (const float*)d_in[6];
    const float* wq = (const float*)d_in[7];
    const float* bq = (const float*)d_in[8];
    const float* wk = (const float*)d_in[9];
    const float* bk = (const float*)d_in[10];
    const float* wv = (const float*)d_in[11];
    const float* bv = (const float*)d_in[12];
    float* out = (float*)d_out;

    float* y1p; cudaGetSymbolAddress((void**)&y1p, g_y1);
    float* tp;  cudaGetSymbolAddress((void**)&tp,  g_t);

    cudaFuncSetAttribute(conv_mma,  cudaFuncAttributeMaxDynamicSharedMemorySize, CONV_SMEM);
    cudaFuncSetAttribute(conv_mma2, cudaFuncAttributeMaxDynamicSharedMemorySize, CONV2_SMEM);
    cudaFuncSetAttribute(conv_qkv,  cudaFuncAttributeMaxDynamicSharedMemorySize, QKV_SMEM);

    pack_weights<<<432, 256>>>(w1, w2, wm, wq, wk, wv);

    dim3 gc(128, BATCH);
    conv_mma<<<gc, 256, CONV_SMEM>>>(x, 0, y1p, b1);
    stats_norm_kernel<<<BATCH*C, 512>>>();
    conv_mma2<<<gc, 256, CONV2_SMEM>>>(tp, b2, bm);
    conv_qkv<<<gc, 256, QKV_SMEM>>>(bq, bk, bv);

    dim3 ga(H/2, BATCH);
    attn_kernel<<<ga, 256>>>(x, bk, bv, out);
}

// round 9
// speedup vs baseline: 4.9341x; 1.3138x over previous
#include <cuda_runtime.h>
#include <cuda_fp16.h>
#include <cstdint>

#define BATCH 8
#define C 128
#define H 128
#define W 128
#define HW (H*W)

// ---------------- scratch (device globals; no allocation allowed) ----------
__device__ float g_y1  [BATCH*C*HW];   // conv1 raw output
__device__ float g_t   [BATCH*C*HW];   // leaky(norm(y1))
__device__ float g_out1[BATCH*C*HW];
__device__ float g_m   [BATCH*C*HW];
__device__ float g_xm  [BATCH*C*HW];   // t * m
__device__ float g_q   [BATCH*C*HW];
__device__ float g_k   [BATCH*C*HW];
__device__ float g_v   [BATCH*C*HW];
__device__ float g_mu  [BATCH*C];
__device__ float g_rsig[BATCH*C];
// fp16 weights packed in per-thread m16n8k16 fragment order
__device__ uint4 g_wH3[3][72*8*32];    // 3x3 convs: [(ks*8+fr)*32+lane]
__device__ uint4 g_wH1[3][8*8*32];     // 1x1 convs

__constant__ int c_di[9] = {-1,-1,-1, 0,0,0, 1,1,1};
__constant__ int c_dj[9] = {-1, 0, 1,-1,0,1,-1,0,1};

__device__ __forceinline__ void mma_f16(float* d, const uint32_t* a, const uint32_t* b) {
    asm volatile(
        "mma.sync.aligned.m16n8k16.row.col.f32.f16.f16.f32 "
        "{%0,%1,%2,%3}, {%4,%5,%6,%7}, {%8,%9}, {%0,%1,%2,%3};"
        : "+f"(d[0]), "+f"(d[1]), "+f"(d[2]), "+f"(d[3])
        : "r"(a[0]), "r"(a[1]), "r"(a[2]), "r"(a[3]), "r"(b[0]), "r"(b[1]));
}
__device__ __forceinline__ uint32_t smem_u32(const void* p) {
    uint32_t a;
    asm("{ .reg .u64 t; cvta.to.shared.u64 t, %1; cvt.u32.u64 %0, t; }"
        : "=r"(a) : "l"(p));
    return a;
}
__device__ __forceinline__ uint32_t pk2(float lo, float hi) {
    __half2 h = __floats2half2_rn(lo, hi);
    return *(uint32_t*)&h;
}
#define CP_ASYNC16(dst, src) \
    asm volatile("cp.async.ca.shared.global [%0], [%1], 16;" :: "r"(dst), "l"(src))
#define CP_COMMIT() asm volatile("cp.async.commit_group;")
#define CP_WAIT0()  asm volatile("cp.async.wait_group 0;" ::: "memory")

// ---------------- weight packing (fp16 fragment order) ----------------------
// 3x3: K=1152 = 9 taps x 128ch; step ks (0..71) covers k = ks*16..+15
// (tap = ks>>3, c_base = (ks&7)*16). Fragment regs per PTX m16n8k16:
//   a0=(g, 2q..2q+1) a1=(g+8, same) a2=(g, 8+2q..) a3=(g+8, 8+2q..)
__global__ void pack_weights(const float* __restrict__ w1, const float* __restrict__ w2,
                             const float* __restrict__ wm, const float* __restrict__ wq,
                             const float* __restrict__ wk, const float* __restrict__ wv)
{
    int idx = blockIdx.x * blockDim.x + threadIdx.x;
    int lane = idx & 31;
    int fr   = (idx >> 5) & 7;
    int rest = idx >> 8;
    {
        int ks   = rest % 72;
        int conv = rest / 72;
        if (conv < 3) {
            const float* w = (conv == 0) ? w1 : (conv == 1) ? w2 : wm;
            int m0  = fr*16 + (lane >> 2);
            int kq  = lane & 3;
            int tap = ks >> 3;
            int cb  = (ks & 7) << 4;
            int ca  = cb + 2*kq;
            int cc  = cb + 8 + 2*kq;
            uint4 o;
            o.x = pk2(w[ m0   *1152 + ca*9 + tap], w[ m0   *1152 + (ca+1)*9 + tap]);
            o.y = pk2(w[(m0+8)*1152 + ca*9 + tap], w[(m0+8)*1152 + (ca+1)*9 + tap]);
            o.z = pk2(w[ m0   *1152 + cc*9 + tap], w[ m0   *1152 + (cc+1)*9 + tap]);
            o.w = pk2(w[(m0+8)*1152 + cc*9 + tap], w[(m0+8)*1152 + (cc+1)*9 + tap]);
            g_wH3[conv][(ks*8 + fr)*32 + lane] = o;
        }
    }
    if (idx < 3*8*8*32) {
        int ks  = rest % 8;
        int set = rest / 8;
        const float* w = (set == 0) ? wq : (set == 1) ? wk : wv;
        int m0 = fr*16 + (lane >> 2);
        int kq = lane & 3;
        int cb = ks << 4;
        int ca = cb + 2*kq;
        int cc = cb + 8 + 2*kq;
        uint4 o;
        o.x = pk2(w[ m0   *128 + ca], w[ m0   *128 + ca+1]);
        o.y = pk2(w[(m0+8)*128 + ca], w[(m0+8)*128 + ca+1]);
        o.z = pk2(w[ m0   *128 + cc], w[ m0   *128 + cc+1]);
        o.w = pk2(w[(m0+8)*128 + cc], w[(m0+8)*128 + cc+1]);
        g_wH1[set][(ks*8 + fr)*32 + lane] = o;
    }
}

// ---------------- fused stats + normalize (y1 -> t) -------------------------
__global__ void __launch_bounds__(512)
stats_norm_kernel()
{
    int bc = blockIdx.x;
    const float4* p = (const float4*)(g_y1 + (size_t)bc * HW);
    float4* d = (float4*)(g_t + (size_t)bc * HW);
    float4 vals[8];
    float s = 0.f, sq = 0.f;
    #pragma unroll
    for (int i = 0; i < 8; i++) {
        float4 v = p[threadIdx.x + 512*i];
        vals[i] = v;
        s  += (v.x + v.y) + (v.z + v.w);
        sq += v.x*v.x + v.y*v.y + v.z*v.z + v.w*v.w;
    }
    #pragma unroll
    for (int o = 16; o; o >>= 1) {
        s  += __shfl_xor_sync(0xffffffffu, s,  o);
        sq += __shfl_xor_sync(0xffffffffu, sq, o);
    }
    __shared__ float ss[16], sqq[16];
    __shared__ float s_mu, s_rs;
    int wrp = threadIdx.x >> 5;
    if ((threadIdx.x & 31) == 0) { ss[wrp] = s; sqq[wrp] = sq; }
    __syncthreads();
    if (threadIdx.x == 0) {
        float S = 0.f, Q = 0.f;
        #pragma unroll
        for (int i = 0; i < 16; i++) { S += ss[i]; Q += sqq[i]; }
        float mu  = S / (float)HW;
        float var = Q / (float)HW - mu*mu;
        float rs  = rsqrtf(var + 1e-5f);
        g_mu[bc] = mu; g_rsig[bc] = rs;
        s_mu = mu; s_rs = rs;
    }
    __syncthreads();
    float mu = s_mu, rs = s_rs;
    #pragma unroll
    for (int i = 0; i < 8; i++) {
        float4 v = vals[i];
        float t0 = (v.x - mu)*rs; t0 = (t0 < 0.f) ? 0.2f*t0 : t0;
        float t1 = (v.y - mu)*rs; t1 = (t1 < 0.f) ? 0.2f*t1 : t1;
        float t2 = (v.z - mu)*rs; t2 = (t2 < 0.f) ? 0.2f*t2 : t2;
        float t3 = (v.w - mu)*rs; t3 = (t3 < 0.f) ? 0.2f*t3 : t3;
        d[threadIdx.x + 512*i] = make_float4(t0, t1, t2, t3);
    }
}

// ---------------- fp16 mma.sync 3x3 conv ------------------------------------
// CTA: 128 cout (M) x 128 px (N). Warps 2(M)x4(N): warp tile 64x32.
// Per round: K=16 (one m16n8k16 step). B smem: [pos(8), stride 136][n(128)]
// of half2 (pos q holds k-pair 2q,2q+1). Conflict-free producer & consumer.
#define BP 136

template<bool SIGM, bool WXM>
__global__ void __launch_bounds__(256, 2)
conv_mma(const float* __restrict__ in, int wsel, float* __restrict__ outp,
         const float* __restrict__ bias)
{
    __shared__ uint4    Asm[2][256];
    __shared__ uint32_t Bs[2][8*BP];

    const int tid  = threadIdx.x;
    const int lane = tid & 31, wid = tid >> 5;
    const int mw = wid >> 2, nw = wid & 3;
    const int b  = blockIdx.y;
    const int h0 = (blockIdx.x >> 2) << 2;
    const int w0 = (blockIdx.x & 3) << 5;

    const uint4* wA = g_wH3[wsel];

    const int sub  = tid >> 7;          // half of K16 (k 0-7 vs 8-15)
    const int nn   = tid & 127;         // pixel
    const int prow = nn >> 5, pcol = nn & 31;

    float acc[4][4][4];
    #pragma unroll
    for (int i = 0; i < 4; i++)
        #pragma unroll
        for (int j = 0; j < 4; j++)
            #pragma unroll
            for (int r = 0; r < 4; r++) acc[i][j][r] = 0.f;

    const uint32_t aBase = smem_u32(&Asm[0][0]);
    float vb[8];

    auto cpA = [&](int r, int buf) {
        CP_ASYNC16(aBase + ((buf*256 + tid) << 4), wA + (size_t)r*256 + tid);
        CP_COMMIT();
    };
    auto ldgB = [&](int r) {
        int tap = r >> 3;
        int c0  = ((r & 7) << 4) + sub*8;
        int ih  = h0 + prow + c_di[tap];
        int iw  = w0 + pcol + c_dj[tap];
        bool ok = ((unsigned)ih < (unsigned)H) && ((unsigned)iw < (unsigned)W);
        const float* src = in + ((size_t)(b*C + c0) << 14) + (size_t)ih*W + iw;
        #pragma unroll
        for (int j = 0; j < 8; j++)
            vb[j] = ok ? src[(size_t)j << 14] : 0.f;
    };
    auto stsB = [&](int buf) {
        #pragma unroll
        for (int p = 0; p < 4; p++)
            Bs[buf][(sub*4 + p)*BP + nn] = pk2(vb[2*p], vb[2*p + 1]);
    };

    const int NR = 72;
    cpA(0, 0);
    ldgB(0);
    stsB(0);
    CP_WAIT0();
    __syncthreads();

    for (int r = 0; r < NR; r++) {
        int buf = r & 1;
        if (r + 1 < NR) { cpA(r + 1, buf ^ 1); ldgB(r + 1); }
        {
            uint4 af[4];
            #pragma unroll
            for (int i = 0; i < 4; i++)
                af[i] = Asm[buf][(mw*4 + i)*32 + lane];
            uint32_t bf[4][2];
            const int q = lane & 3;
            #pragma unroll
            for (int j = 0; j < 4; j++) {
                int n = nw*32 + j*8 + (lane >> 2);
                bf[j][0] = Bs[buf][ q     *BP + n];
                bf[j][1] = Bs[buf][(4 + q)*BP + n];
            }
            #pragma unroll
            for (int i = 0; i < 4; i++)
                #pragma unroll
                for (int j = 0; j < 4; j++)
                    mma_f16(acc[i][j], (const uint32_t*)&af[i], bf[j]);
        }
        if (r + 1 < NR) {
            stsB(buf ^ 1);
            CP_WAIT0();
            __syncthreads();
        }
    }

    // epilogue
    #pragma unroll
    for (int i = 0; i < 4; i++) {
        int m0 = mw*64 + i*16 + (lane >> 2);
        float bb0 = bias[m0], bb1 = bias[m0 + 8];
        size_t ob = ((size_t)(b*C + m0) << 14) + (size_t)(h0 + nw)*W + w0;
        #pragma unroll
        for (int j = 0; j < 4; j++) {
            int co = j*8 + (lane & 3)*2;
            float v0 = acc[i][j][0] + bb0, v1 = acc[i][j][1] + bb0;
            float v2 = acc[i][j][2] + bb1, v3 = acc[i][j][3] + bb1;
            if (SIGM) {
                v0 = 1.f/(1.f + __expf(-v0)); v1 = 1.f/(1.f + __expf(-v1));
                v2 = 1.f/(1.f + __expf(-v2)); v3 = 1.f/(1.f + __expf(-v3));
            }
            *(float2*)(outp + ob + co)             = make_float2(v0, v1);
            *(float2*)(outp + ob + (8 << 14) + co) = make_float2(v2, v3);
            if (WXM) {
                float2 t0 = *(const float2*)(g_t + ob + co);
                float2 t1 = *(const float2*)(g_t + ob + (8 << 14) + co);
                *(float2*)(g_xm + ob + co)             = make_float2(v0*t0.x, v1*t0.y);
                *(float2*)(g_xm + ob + (8 << 14) + co) = make_float2(v2*t1.x, v3*t1.y);
            }
        }
    }
}

// ---------------- merged q/k/v 1x1 GEMM (shared fp16 B staging) --------------
__global__ void __launch_bounds__(256, 2)
conv_qkv(const float* __restrict__ bq, const float* __restrict__ bk,
         const float* __restrict__ bv_)
{
    __shared__ uint32_t Bsq[8][8*BP];   // [step][pos][n] 34.8KB
    __shared__ uint4    Asq[2][256];

    const int tid  = threadIdx.x;
    const int lane = tid & 31, wid = tid >> 5;
    const int mw = wid >> 2, nw = wid & 3;
    const int b  = blockIdx.y;
    const int h0 = (blockIdx.x >> 2) << 2;
    const int w0 = (blockIdx.x & 3) << 5;

    const int sub  = tid >> 7;
    const int nn   = tid & 127;
    const int prow = nn >> 5, pcol = nn & 31;

    const uint32_t aBase = smem_u32(&Asq[0][0]);
    auto cpA = [&](const uint4* wA, int r, int buf) {
        CP_ASYNC16(aBase + ((buf*256 + tid) << 4), wA + (size_t)r*256 + tid);
        CP_COMMIT();
    };

    // stage whole B (K=128 = 8 k16-steps) as fp16
    {
        const float* src0 = (const float*)g_xm + ((size_t)(b*C) << 14)
                          + (size_t)(h0 + prow)*W + (w0 + pcol);
        #pragma unroll
        for (int ks = 0; ks < 8; ks++) {
            const float* src = src0 + ((size_t)(ks*16 + sub*8) << 14);
            float vb[8];
            #pragma unroll
            for (int j = 0; j < 8; j++)
                vb[j] = src[(size_t)j << 14];
            #pragma unroll
            for (int p = 0; p < 4; p++)
                Bsq[ks][(sub*4 + p)*BP + nn] = pk2(vb[2*p], vb[2*p + 1]);
        }
    }

    for (int set = 0; set < 3; set++) {
        const uint4* wA = g_wH1[set];
        const float* bias = (set == 0) ? bq : (set == 1) ? bk : bv_;
        float* out = (set == 0) ? g_q : (set == 1) ? g_k : g_v;

        float acc[4][4][4];
        #pragma unroll
        for (int i = 0; i < 4; i++)
            #pragma unroll
            for (int j = 0; j < 4; j++)
                #pragma unroll
                for (int r = 0; r < 4; r++) acc[i][j][r] = 0.f;

        cpA(wA, 0, 0);
        CP_WAIT0();
        __syncthreads();   // covers B staging on set 0, Asq on all

        for (int r = 0; r < 8; r++) {
            int buf = r & 1;
            if (r + 1 < 8) cpA(wA, r + 1, buf ^ 1);
            uint4 af[4];
            #pragma unroll
            for (int i = 0; i < 4; i++)
                af[i] = Asq[buf][(mw*4 + i)*32 + lane];
            uint32_t bf[4][2];
            const int q = lane & 3;
            #pragma unroll
            for (int j = 0; j < 4; j++) {
                int n = nw*32 + j*8 + (lane >> 2);
                bf[j][0] = Bsq[r][ q     *BP + n];
                bf[j][1] = Bsq[r][(4 + q)*BP + n];
            }
            #pragma unroll
            for (int i = 0; i < 4; i++)
                #pragma unroll
                for (int j = 0; j < 4; j++)
                    mma_f16(acc[i][j], (const uint32_t*)&af[i], bf[j]);
            if (r + 1 < 8) {
                CP_WAIT0();
                __syncthreads();
            }
        }

        #pragma unroll
        for (int i = 0; i < 4; i++) {
            int m0 = mw*64 + i*16 + (lane >> 2);
            float bb0 = bias[m0], bb1 = bias[m0 + 8];
            size_t ob = ((size_t)(b*C + m0) << 14) + (size_t)(h0 + nw)*W + w0;
            #pragma unroll
            for (int j = 0; j < 4; j++) {
                int co = j*8 + (lane & 3)*2;
                *(float2*)(out + ob + co) =
                    make_float2(acc[i][j][0] + bb0, acc[i][j][1] + bb0);
                *(float2*)(out + ob + (8 << 14) + co) =
                    make_float2(acc[i][j][2] + bb1, acc[i][j][3] + bb1);
            }
        }
        __syncthreads();   // protect Asq before next set's prologue cpA
    }
}

// ---------------- local 3x3 attention + blend + residual --------------------
// 4-way channel split (32 ch each); logits combined in smem; redundant
// per-thread softmax; one __syncthreads. 4 px/thread, 2 rows/CTA.
__global__ void __launch_bounds__(256)
attn_kernel(const float* __restrict__ x, const float* __restrict__ k_b,
            const float* __restrict__ v_b, float* __restrict__ out)
{
    __shared__ float att[4][2][32][37];

    const int b    = blockIdx.y;
    const int tid  = threadIdx.x;
    const int cg   = tid >> 6;
    const int t    = tid & 63;
    const int row  = t >> 5;
    const int lane = t & 31;
    const int h    = blockIdx.x*2 + row;
    const int wq   = lane*4;
    const size_t bbase = (size_t)b*C*HW;
    const int poff = h*W + wq;
    const int c0 = cg*32;

    float sims[9][4];
    #pragma unroll
    for (int o = 0; o < 9; o++)
        #pragma unroll
        for (int p = 0; p < 4; p++) sims[o][p] = 0.f;

    for (int ci = 0; ci < 32; ci++) {
        int c = c0 + ci;
        const float* kp = g_k + bbase + ((size_t)c << 14);
        float kbv = __ldg(k_b + c);
        float4 qv = *(const float4*)(g_q + bbase + ((size_t)c << 14) + poff);
        float q[4] = {qv.x, qv.y, qv.z, qv.w};
        #pragma unroll
        for (int dr = 0; dr < 3; dr++) {
            int hh = h + dr - 1;
            bool rok = ((unsigned)hh < (unsigned)H);
            const float* rp = kp + hh*W;
            float4 mid = rok ? *(const float4*)(rp + wq)
                             : make_float4(kbv, kbv, kbv, kbv);
            float lf = (rok && wq > 0)   ? rp[wq - 1] : kbv;
            float rt = (rok && wq < 124) ? rp[wq + 4] : kbv;
            float val[6] = {lf, mid.x, mid.y, mid.z, mid.w, rt};
            #pragma unroll
            for (int dj = 0; dj < 3; dj++)
                #pragma unroll
                for (int p = 0; p < 4; p++)
                    sims[dr*3 + dj][p] = fmaf(q[p], val[p + dj], sims[dr*3 + dj][p]);
        }
    }

    #pragma unroll
    for (int o = 0; o < 9; o++)
        #pragma unroll
        for (int p = 0; p < 4; p++)
            att[cg][row][lane][o*4 + p] = sims[o][p];
    __syncthreads();

    #pragma unroll
    for (int o = 0; o < 9; o++)
        #pragma unroll
        for (int p = 0; p < 4; p++)
            sims[o][p] = att[0][row][lane][o*4 + p] + att[1][row][lane][o*4 + p]
                       + att[2][row][lane][o*4 + p] + att[3][row][lane][o*4 + p];
    #pragma unroll
    for (int p = 0; p < 4; p++) {
        float mx = sims[0][p];
        #pragma unroll
        for (int o = 1; o < 9; o++) mx = fmaxf(mx, sims[o][p]);
        float se = 0.f;
        #pragma unroll
        for (int o = 0; o < 9; o++) { sims[o][p] = __expf(sims[o][p] - mx); se += sims[o][p]; }
        float inv = 1.f / se;
        #pragma unroll
        for (int o = 0; o < 9; o++) sims[o][p] *= inv;
    }

    for (int ci = 0; ci < 32; ci++) {
        int c = c0 + ci;
        const float* vp = g_v + bbase + ((size_t)c << 14);
        float vbv = __ldg(v_b + c);
        float o2[4] = {0.f, 0.f, 0.f, 0.f};
        #pragma unroll
        for (int dr = 0; dr < 3; dr++) {
            int hh = h + dr - 1;
            bool rok = ((unsigned)hh < (unsigned)H);
            const float* rp = vp + hh*W;
            float4 mid = rok ? *(const float4*)(rp + wq)
                             : make_float4(vbv, vbv, vbv, vbv);
            float lf = (rok && wq > 0)   ? rp[wq - 1] : vbv;
            float rt = (rok && wq < 124) ? rp[wq + 4] : vbv;
            float val[6] = {lf, mid.x, mid.y, mid.z, mid.w, rt};
            #pragma unroll
            for (int dj = 0; dj < 3; dj++)
                #pragma unroll
                for (int p = 0; p < 4; p++)
                    o2[p] = fmaf(sims[dr*3 + dj][p], val[p + dj], o2[p]);
        }
        size_t idx = bbase + ((size_t)c << 14) + poff;
        float4 mv = *(const float4*)(g_m    + idx);
        float4 o1 = *(const float4*)(g_out1 + idx);
        float4 xv = *(const float4*)(x      + idx);
        float4 ov;
        ov.x = xv.x + o1.x*mv.x + (1.f - mv.x)*o2[0];
        ov.y = xv.y + o1.y*mv.y + (1.f - mv.y)*o2[1];
        ov.z = xv.z + o1.z*mv.z + (1.f - mv.z)*o2[2];
        ov.w = xv.w + o1.w*mv.w + (1.f - mv.w)*o2[3];
        *(float4*)(out + idx) = ov;
    }
}

// ---------------- launch ----------------------------------------------------
extern "C" void kernel_launch(void* const* d_in, const int* in_sizes, int n_in,
                              void* d_out, int out_size)
{
    const float* x  = (const float*)d_in[0];
    const float* w1 = (const float*)d_in[1];
    const float* b1 = (const float*)d_in[2];
    const float* w2 = (const float*)d_in[3];
    const float* b2 = (const float*)d_in[4];
    const float* wm = (const float*)d_in[5];
    const float* bm = (const float*)d_in[6];
    const float* wq = (const float*)d_in[7];
    const float* bq = (const float*)d_in[8];
    const float* wk = (const float*)d_in[9];
    const float* bk = (const float*)d_in[10];
    const float* wv = (const float*)d_in[11];
    const float* bv = (const float*)d_in[12];
    float* out = (float*)d_out;

    float* y1p;   cudaGetSymbolAddress((void**)&y1p,   g_y1);
    float* tp;    cudaGetSymbolAddress((void**)&tp,    g_t);
    float* out1p; cudaGetSymbolAddress((void**)&out1p, g_out1);
    float* mp;    cudaGetSymbolAddress((void**)&mp,    g_m);

    pack_weights<<<216, 256>>>(w1, w2, wm, wq, wk, wv);

    dim3 gc(128, BATCH);
    conv_mma<false,false><<<gc, 256>>>(x,  0, y1p,   b1);
    stats_norm_kernel<<<BATCH*C, 512>>>();
    conv_mma<false,false><<<gc, 256>>>(tp, 1, out1p, b2);
    conv_mma<true, true ><<<gc, 256>>>(tp, 2, mp,    bm);
    conv_qkv<<<gc, 256>>>(bq, bk, bv);

    dim3 ga(H/2, BATCH);
    attn_kernel<<<ga, 256>>>(x, bk, bv, out);
}

// round 10
// speedup vs baseline: 5.6591x; 1.1469x over previous
#include <cuda_runtime.h>
#include <cuda_fp16.h>
#include <cstdint>

#define BATCH 8
#define C 128
#define H 128
#define W 128
#define HW (H*W)

// ---------------- scratch (device globals; no allocation allowed) ----------
__device__ float g_y1  [BATCH*C*HW];   // conv1 raw output
__device__ float g_t   [BATCH*C*HW];   // leaky(norm(y1))
__device__ float g_out1[BATCH*C*HW];
__device__ float g_m   [BATCH*C*HW];
__device__ float g_xm  [BATCH*C*HW];   // t * m
__device__ float g_q   [BATCH*C*HW];
__device__ float g_k   [BATCH*C*HW];
__device__ float g_v   [BATCH*C*HW];
__device__ float g_mu  [BATCH*C];
__device__ float g_rsig[BATCH*C];
// fp16 weights packed in per-thread m16n8k16 fragment order
__device__ uint4 g_wH3[3][72*8*32];    // 3x3 convs: [(ks*8+fr)*32+lane]
__device__ uint4 g_wH1[3][8*8*32];     // 1x1 convs

__constant__ int c_di[9] = {-1,-1,-1, 0,0,0, 1,1,1};
__constant__ int c_dj[9] = {-1, 0, 1,-1,0,1,-1,0,1};

__device__ __forceinline__ void mma_f16(float* d, const uint32_t* a, const uint32_t* b) {
    asm volatile(
        "mma.sync.aligned.m16n8k16.row.col.f32.f16.f16.f32 "
        "{%0,%1,%2,%3}, {%4,%5,%6,%7}, {%8,%9}, {%0,%1,%2,%3};"
        : "+f"(d[0]), "+f"(d[1]), "+f"(d[2]), "+f"(d[3])
        : "r"(a[0]), "r"(a[1]), "r"(a[2]), "r"(a[3]), "r"(b[0]), "r"(b[1]));
}
__device__ __forceinline__ uint32_t smem_u32(const void* p) {
    uint32_t a;
    asm("{ .reg .u64 t; cvta.to.shared.u64 t, %1; cvt.u32.u64 %0, t; }"
        : "=r"(a) : "l"(p));
    return a;
}
__device__ __forceinline__ uint32_t pk2(float lo, float hi) {
    __half2 h = __floats2half2_rn(lo, hi);
    return *(uint32_t*)&h;
}
#define CP_ASYNC16(dst, src) \
    asm volatile("cp.async.ca.shared.global [%0], [%1], 16;" :: "r"(dst), "l"(src))
#define CP_COMMIT() asm volatile("cp.async.commit_group;")
#define CP_WAIT0()  asm volatile("cp.async.wait_group 0;" ::: "memory")

// ---------------- weight packing (fp16 fragment order) ----------------------
__global__ void pack_weights(const float* __restrict__ w1, const float* __restrict__ w2,
                             const float* __restrict__ wm, const float* __restrict__ wq,
                             const float* __restrict__ wk, const float* __restrict__ wv)
{
    int idx = blockIdx.x * blockDim.x + threadIdx.x;
    int lane = idx & 31;
    int fr   = (idx >> 5) & 7;
    int rest = idx >> 8;
    {
        int ks   = rest % 72;
        int conv = rest / 72;
        if (conv < 3) {
            const float* w = (conv == 0) ? w1 : (conv == 1) ? w2 : wm;
            int m0  = fr*16 + (lane >> 2);
            int kq  = lane & 3;
            int tap = ks >> 3;
            int cb  = (ks & 7) << 4;
            int ca  = cb + 2*kq;
            int cc  = cb + 8 + 2*kq;
            uint4 o;
            o.x = pk2(w[ m0   *1152 + ca*9 + tap], w[ m0   *1152 + (ca+1)*9 + tap]);
            o.y = pk2(w[(m0+8)*1152 + ca*9 + tap], w[(m0+8)*1152 + (ca+1)*9 + tap]);
            o.z = pk2(w[ m0   *1152 + cc*9 + tap], w[ m0   *1152 + (cc+1)*9 + tap]);
            o.w = pk2(w[(m0+8)*1152 + cc*9 + tap], w[(m0+8)*1152 + (cc+1)*9 + tap]);
            g_wH3[conv][(ks*8 + fr)*32 + lane] = o;
        }
    }
    if (idx < 3*8*8*32) {
        int ks  = rest % 8;
        int set = rest / 8;
        const float* w = (set == 0) ? wq : (set == 1) ? wk : wv;
        int m0 = fr*16 + (lane >> 2);
        int kq = lane & 3;
        int cb = ks << 4;
        int ca = cb + 2*kq;
        int cc = cb + 8 + 2*kq;
        uint4 o;
        o.x = pk2(w[ m0   *128 + ca], w[ m0   *128 + ca+1]);
        o.y = pk2(w[(m0+8)*128 + ca], w[(m0+8)*128 + ca+1]);
        o.z = pk2(w[ m0   *128 + cc], w[ m0   *128 + cc+1]);
        o.w = pk2(w[(m0+8)*128 + cc], w[(m0+8)*128 + cc+1]);
        g_wH1[set][(ks*8 + fr)*32 + lane] = o;
    }
}

// ---------------- fused stats + normalize (y1 -> t) -------------------------
__global__ void __launch_bounds__(512)
stats_norm_kernel()
{
    int bc = blockIdx.x;
    const float4* p = (const float4*)(g_y1 + (size_t)bc * HW);
    float4* d = (float4*)(g_t + (size_t)bc * HW);
    float4 vals[8];
    float s = 0.f, sq = 0.f;
    #pragma unroll
    for (int i = 0; i < 8; i++) {
        float4 v = p[threadIdx.x + 512*i];
        vals[i] = v;
        s  += (v.x + v.y) + (v.z + v.w);
        sq += v.x*v.x + v.y*v.y + v.z*v.z + v.w*v.w;
    }
    #pragma unroll
    for (int o = 16; o; o >>= 1) {
        s  += __shfl_xor_sync(0xffffffffu, s,  o);
        sq += __shfl_xor_sync(0xffffffffu, sq, o);
    }
    __shared__ float ss[16], sqq[16];
    __shared__ float s_mu, s_rs;
    int wrp = threadIdx.x >> 5;
    if ((threadIdx.x & 31) == 0) { ss[wrp] = s; sqq[wrp] = sq; }
    __syncthreads();
    if (threadIdx.x == 0) {
        float S = 0.f, Q = 0.f;
        #pragma unroll
        for (int i = 0; i < 16; i++) { S += ss[i]; Q += sqq[i]; }
        float mu  = S / (float)HW;
        float var = Q / (float)HW - mu*mu;
        float rs  = rsqrtf(var + 1e-5f);
        g_mu[bc] = mu; g_rsig[bc] = rs;
        s_mu = mu; s_rs = rs;
    }
    __syncthreads();
    float mu = s_mu, rs = s_rs;
    #pragma unroll
    for (int i = 0; i < 8; i++) {
        float4 v = vals[i];
        float t0 = (v.x - mu)*rs; t0 = (t0 < 0.f) ? 0.2f*t0 : t0;
        float t1 = (v.y - mu)*rs; t1 = (t1 < 0.f) ? 0.2f*t1 : t1;
        float t2 = (v.z - mu)*rs; t2 = (t2 < 0.f) ? 0.2f*t2 : t2;
        float t3 = (v.w - mu)*rs; t3 = (t3 < 0.f) ? 0.2f*t3 : t3;
        d[threadIdx.x + 512*i] = make_float4(t0, t1, t2, t3);
    }
}

// ---------------- fp16 3x3 conv: B-stationary smem tile, barrier-free -------
// Input tile (128 ch x 6x34 halo px) staged once as fp16, channel-contiguous:
// word[pix*68 + c/2]. Consumer LDS banks: 68 = 4 (mod 32) -> 4*g+q, all
// distinct. Mainloop per round: 4 LDG.128 (A prefetch) + 8 LDS.32 + 16 MMA,
// no barriers. A streams from L2-hot packed weights.
#define TPIX 204
#define TSTRIDE 68
#define CONV_SMEM (TPIX*TSTRIDE*4)     // 55488 B

template<bool SIGM, bool WXM>
__global__ void __launch_bounds__(256, 2)
conv_tile(const float* __restrict__ in, int wsel, float* __restrict__ outp,
          const float* __restrict__ bias)
{
    extern __shared__ uint32_t tile[];

    const int tid  = threadIdx.x;
    const int lane = tid & 31, wid = tid >> 5;
    const int mw = wid >> 2, nw = wid & 3;
    const int b  = blockIdx.y;
    const int h0 = (blockIdx.x >> 2) << 2;
    const int w0 = (blockIdx.x & 3) << 5;

    // ---- prologue: stage input tile as fp16 ----
    #pragma unroll 4
    for (int pp = 0; pp < 51; pp++) {
        int idx  = pp*256 + tid;           // 0..13055 = 64 pairs * 204 px
        int pair = idx / 204;
        int pix  = idx - pair*204;
        int pr = pix / 34, pc = pix - pr*34;
        int ih = h0 + pr - 1, iw = w0 + pc - 1;
        float v0 = 0.f, v1 = 0.f;
        if (((unsigned)ih < (unsigned)H) && ((unsigned)iw < (unsigned)W)) {
            const float* s = in + ((size_t)(b*C + 2*pair) << 14) + (size_t)ih*W + iw;
            v0 = s[0];
            v1 = s[(size_t)1 << 14];
        }
        tile[pix*TSTRIDE + pair] = pk2(v0, v1);
    }
    __syncthreads();

    float acc[4][4][4];
    #pragma unroll
    for (int i = 0; i < 4; i++)
        #pragma unroll
        for (int j = 0; j < 4; j++)
            #pragma unroll
            for (int r = 0; r < 4; r++) acc[i][j][r] = 0.f;

    const uint4* wA = g_wH3[wsel];
    const int q = lane & 3, g = lane >> 2;

    uint4 aN[4];
    #pragma unroll
    for (int i = 0; i < 4; i++)
        aN[i] = wA[(mw*4 + i)*32 + lane];

    const int NR = 72;
    for (int r = 0; r < NR; r++) {
        uint4 aC[4];
        #pragma unroll
        for (int i = 0; i < 4; i++) aC[i] = aN[i];
        if (r + 1 < NR) {
            const uint4* src = wA + (size_t)(r + 1)*256;
            #pragma unroll
            for (int i = 0; i < 4; i++)
                aN[i] = src[(mw*4 + i)*32 + lane];
        }
        int tap = r >> 3;
        int cw  = ((r & 7) << 3) + q;      // word: c0/2 + q
        int pxb = (nw + c_di[tap] + 1)*34 + c_dj[tap] + 1 + g;
        uint32_t bf[4][2];
        #pragma unroll
        for (int j = 0; j < 4; j++) {
            int off = (pxb + j*8)*TSTRIDE + cw;
            bf[j][0] = tile[off];
            bf[j][1] = tile[off + 4];
        }
        #pragma unroll
        for (int i = 0; i < 4; i++)
            #pragma unroll
            for (int j = 0; j < 4; j++)
                mma_f16(acc[i][j], (const uint32_t*)&aC[i], bf[j]);
    }

    // ---- epilogue ----
    #pragma unroll
    for (int i = 0; i < 4; i++) {
        int m0 = mw*64 + i*16 + g;
        float bb0 = bias[m0], bb1 = bias[m0 + 8];
        size_t ob = ((size_t)(b*C + m0) << 14) + (size_t)(h0 + nw)*W + w0;
        #pragma unroll
        for (int j = 0; j < 4; j++) {
            int co = j*8 + q*2;
            float v0 = acc[i][j][0] + bb0, v1 = acc[i][j][1] + bb0;
            float v2 = acc[i][j][2] + bb1, v3 = acc[i][j][3] + bb1;
            if (SIGM) {
                v0 = 1.f/(1.f + __expf(-v0)); v1 = 1.f/(1.f + __expf(-v1));
                v2 = 1.f/(1.f + __expf(-v2)); v3 = 1.f/(1.f + __expf(-v3));
            }
            *(float2*)(outp + ob + co)             = make_float2(v0, v1);
            *(float2*)(outp + ob + (8 << 14) + co) = make_float2(v2, v3);
            if (WXM) {
                float2 t0 = *(const float2*)(g_t + ob + co);
                float2 t1 = *(const float2*)(g_t + ob + (8 << 14) + co);
                *(float2*)(g_xm + ob + co)             = make_float2(v0*t0.x, v1*t0.y);
                *(float2*)(g_xm + ob + (8 << 14) + co) = make_float2(v2*t1.x, v3*t1.y);
            }
        }
    }
}

// ---------------- merged q/k/v 1x1 GEMM (shared fp16 B staging) --------------
#define BP 136
__global__ void __launch_bounds__(256, 2)
conv_qkv(const float* __restrict__ bq, const float* __restrict__ bk,
         const float* __restrict__ bv_)
{
    __shared__ uint32_t Bsq[8][8*BP];
    __shared__ uint4    Asq[2][256];

    const int tid  = threadIdx.x;
    const int lane = tid & 31, wid = tid >> 5;
    const int mw = wid >> 2, nw = wid & 3;
    const int b  = blockIdx.y;
    const int h0 = (blockIdx.x >> 2) << 2;
    const int w0 = (blockIdx.x & 3) << 5;

    const int sub  = tid >> 7;
    const int nn   = tid & 127;
    const int prow = nn >> 5, pcol = nn & 31;

    const uint32_t aBase = smem_u32(&Asq[0][0]);
    auto cpA = [&](const uint4* wA, int r, int buf) {
        CP_ASYNC16(aBase + ((buf*256 + tid) << 4), wA + (size_t)r*256 + tid);
        CP_COMMIT();
    };

    {
        const float* src0 = (const float*)g_xm + ((size_t)(b*C) << 14)
                          + (size_t)(h0 + prow)*W + (w0 + pcol);
        #pragma unroll
        for (int ks = 0; ks < 8; ks++) {
            const float* src = src0 + ((size_t)(ks*16 + sub*8) << 14);
            float vb[8];
            #pragma unroll
            for (int j = 0; j < 8; j++)
                vb[j] = src[(size_t)j << 14];
            #pragma unroll
            for (int p = 0; p < 4; p++)
                Bsq[ks][(sub*4 + p)*BP + nn] = pk2(vb[2*p], vb[2*p + 1]);
        }
    }

    for (int set = 0; set < 3; set++) {
        const uint4* wA = g_wH1[set];
        const float* bias = (set == 0) ? bq : (set == 1) ? bk : bv_;
        float* out = (set == 0) ? g_q : (set == 1) ? g_k : g_v;

        float acc[4][4][4];
        #pragma unroll
        for (int i = 0; i < 4; i++)
            #pragma unroll
            for (int j = 0; j < 4; j++)
                #pragma unroll
                for (int r = 0; r < 4; r++) acc[i][j][r] = 0.f;

        cpA(wA, 0, 0);
        CP_WAIT0();
        __syncthreads();

        for (int r = 0; r < 8; r++) {
            int buf = r & 1;
            if (r + 1 < 8) cpA(wA, r + 1, buf ^ 1);
            uint4 af[4];
            #pragma unroll
            for (int i = 0; i < 4; i++)
                af[i] = Asq[buf][(mw*4 + i)*32 + lane];
            uint32_t bf[4][2];
            const int q = lane & 3;
            #pragma unroll
            for (int j = 0; j < 4; j++) {
                int n = nw*32 + j*8 + (lane >> 2);
                bf[j][0] = Bsq[r][ q     *BP + n];
                bf[j][1] = Bsq[r][(4 + q)*BP + n];
            }
            #pragma unroll
            for (int i = 0; i < 4; i++)
                #pragma unroll
                for (int j = 0; j < 4; j++)
                    mma_f16(acc[i][j], (const uint32_t*)&af[i], bf[j]);
            if (r + 1 < 8) {
                CP_WAIT0();
                __syncthreads();
            }
        }

        #pragma unroll
        for (int i = 0; i < 4; i++) {
            int m0 = mw*64 + i*16 + (lane >> 2);
            float bb0 = bias[m0], bb1 = bias[m0 + 8];
            size_t ob = ((size_t)(b*C + m0) << 14) + (size_t)(h0 + nw)*W + w0;
            #pragma unroll
            for (int j = 0; j < 4; j++) {
                int co = j*8 + (lane & 3)*2;
                *(float2*)(out + ob + co) =
                    make_float2(acc[i][j][0] + bb0, acc[i][j][1] + bb0);
                *(float2*)(out + ob + (8 << 14) + co) =
                    make_float2(acc[i][j][2] + bb1, acc[i][j][3] + bb1);
            }
        }
        __syncthreads();
    }
}

// ---------------- local 3x3 attention + blend + residual --------------------
// 4-way channel split; edge taps via warp shuffle (1 LDG.128 per row).
__global__ void __launch_bounds__(256)
attn_kernel(const float* __restrict__ x, const float* __restrict__ k_b,
            const float* __restrict__ v_b, float* __restrict__ out)
{
    __shared__ float att[4][2][32][37];

    const int b    = blockIdx.y;
    const int tid  = threadIdx.x;
    const int cg   = tid >> 6;
    const int t    = tid & 63;
    const int row  = t >> 5;
    const int lane = t & 31;
    const int h    = blockIdx.x*2 + row;
    const int wq   = lane*4;
    const size_t bbase = (size_t)b*C*HW;
    const int poff = h*W + wq;
    const int c0 = cg*32;

    float sims[9][4];
    #pragma unroll
    for (int o = 0; o < 9; o++)
        #pragma unroll
        for (int p = 0; p < 4; p++) sims[o][p] = 0.f;

    for (int ci = 0; ci < 32; ci++) {
        int c = c0 + ci;
        const float* kp = g_k + bbase + ((size_t)c << 14);
        float kbv = __ldg(k_b + c);
        float4 qv = *(const float4*)(g_q + bbase + ((size_t)c << 14) + poff);
        float q[4] = {qv.x, qv.y, qv.z, qv.w};
        #pragma unroll
        for (int dr = 0; dr < 3; dr++) {
            int hh = h + dr - 1;
            bool rok = ((unsigned)hh < (unsigned)H);
            float4 mid = rok ? *(const float4*)(kp + hh*W + wq)
                             : make_float4(kbv, kbv, kbv, kbv);
            float lf = __shfl_up_sync(0xffffffffu, mid.w, 1);
            if (lane == 0)  lf = kbv;
            float rt = __shfl_down_sync(0xffffffffu, mid.x, 1);
            if (lane == 31) rt = kbv;
            float val[6] = {lf, mid.x, mid.y, mid.z, mid.w, rt};
            #pragma unroll
            for (int dj = 0; dj < 3; dj++)
                #pragma unroll
                for (int p = 0; p < 4; p++)
                    sims[dr*3 + dj][p] = fmaf(q[p], val[p + dj], sims[dr*3 + dj][p]);
        }
    }

    #pragma unroll
    for (int o = 0; o < 9; o++)
        #pragma unroll
        for (int p = 0; p < 4; p++)
            att[cg][row][lane][o*4 + p] = sims[o][p];
    __syncthreads();

    #pragma unroll
    for (int o = 0; o < 9; o++)
        #pragma unroll
        for (int p = 0; p < 4; p++)
            sims[o][p] = att[0][row][lane][o*4 + p] + att[1][row][lane][o*4 + p]
                       + att[2][row][lane][o*4 + p] + att[3][row][lane][o*4 + p];
    #pragma unroll
    for (int p = 0; p < 4; p++) {
        float mx = sims[0][p];
        #pragma unroll
        for (int o = 1; o < 9; o++) mx = fmaxf(mx, sims[o][p]);
        float se = 0.f;
        #pragma unroll
        for (int o = 0; o < 9; o++) { sims[o][p] = __expf(sims[o][p] - mx); se += sims[o][p]; }
        float inv = 1.f / se;
        #pragma unroll
        for (int o = 0; o < 9; o++) sims[o][p] *= inv;
    }

    for (int ci = 0; ci < 32; ci++) {
        int c = c0 + ci;
        const float* vp = g_v + bbase + ((size_t)c << 14);
        float vbv = __ldg(v_b + c);
        float o2[4] = {0.f, 0.f, 0.f, 0.f};
        #pragma unroll
        for (int dr = 0; dr < 3; dr++) {
            int hh = h + dr - 1;
            bool rok = ((unsigned)hh < (unsigned)H);
            float4 mid = rok ? *(const float4*)(vp + hh*W + wq)
                             : make_float4(vbv, vbv, vbv, vbv);
            float lf = __shfl_up_sync(0xffffffffu, mid.w, 1);
            if (lane == 0)  lf = vbv;
            float rt = __shfl_down_sync(0xffffffffu, mid.x, 1);
            if (lane == 31) rt = vbv;
            float val[6] = {lf, mid.x, mid.y, mid.z, mid.w, rt};
            #pragma unroll
            for (int dj = 0; dj < 3; dj++)
                #pragma unroll
                for (int p = 0; p < 4; p++)
                    o2[p] = fmaf(sims[dr*3 + dj][p], val[p + dj], o2[p]);
        }
        size_t idx = bbase + ((size_t)c << 14) + poff;
        float4 mv = *(const float4*)(g_m    + idx);
        float4 o1 = *(const float4*)(g_out1 + idx);
        float4 xv = *(const float4*)(x      + idx);
        float4 ov;
        ov.x = xv.x + o1.x*mv.x + (1.f - mv.x)*o2[0];
        ov.y = xv.y + o1.y*mv.y + (1.f - mv.y)*o2[1];
        ov.z = xv.z + o1.z*mv.z + (1.f - mv.z)*o2[2];
        ov.w = xv.w + o1.w*mv.w + (1.f - mv.w)*o2[3];
        *(float4*)(out + idx) = ov;
    }
}

// ---------------- launch ----------------------------------------------------
extern "C" void kernel_launch(void* const* d_in, const int* in_sizes, int n_in,
                              void* d_out, int out_size)
{
    const float* x  = (const float*)d_in[0];
    const float* w1 = (const float*)d_in[1];
    const float* b1 = (const float*)d_in[2];
    const float* w2 = (const float*)d_in[3];
    const float* b2 = (const float*)d_in[4];
    const float* wm = (const float*)d_in[5];
    const float* bm = (const float*)d_in[6];
    const float* wq = (const float*)d_in[7];
    const float* bq = (const float*)d_in[8];
    const float* wk = (const float*)d_in[9];
    const float* bk = (const float*)d_in[10];
    const float* wv = (const float*)d_in[11];
    const float* bv = (const float*)d_in[12];
    float* out = (float*)d_out;

    float* y1p;   cudaGetSymbolAddress((void**)&y1p,   g_y1);
    float* tp;    cudaGetSymbolAddress((void**)&tp,    g_t);
    float* out1p; cudaGetSymbolAddress((void**)&out1p, g_out1);
    float* mp;    cudaGetSymbolAddress((void**)&mp,    g_m);

    cudaFuncSetAttribute(conv_tile<false,false>, cudaFuncAttributeMaxDynamicSharedMemorySize, CONV_SMEM);
    cudaFuncSetAttribute(conv_tile<true, true >, cudaFuncAttributeMaxDynamicSharedMemorySize, CONV_SMEM);

    pack_weights<<<216, 256>>>(w1, w2, wm, wq, wk, wv);

    dim3 gc(128, BATCH);
    conv_tile<false,false><<<gc, 256, CONV_SMEM>>>(x,  0, y1p,   b1);
    stats_norm_kernel<<<BATCH*C, 512>>>();
    conv_tile<false,false><<<gc, 256, CONV_SMEM>>>(tp, 1, out1p, b2);
    conv_tile<true, true ><<<gc, 256, CONV_SMEM>>>(tp, 2, mp,    bm);
    conv_qkv<<<gc, 256>>>(bq, bk, bv);

    dim3 ga(H/2, BATCH);
    attn_kernel<<<ga, 256>>>(x, bk, bv, out);
}

// round 11
// speedup vs baseline: 6.4175x; 1.1340x over previous
#include <cuda_runtime.h>
#include <cuda_fp16.h>
#include <cstdint>

#define BATCH 8
#define C 128
#define H 128
#define W 128
#define HW (H*W)

// ---------------- scratch (device globals; no allocation allowed) ----------
__device__ float g_y1  [BATCH*C*HW];   // conv1 raw output
__device__ float g_out1[BATCH*C*HW];
__device__ float g_m   [BATCH*C*HW];
__device__ float g_xm  [BATCH*C*HW];   // t * m
__device__ float g_q   [BATCH*C*HW];
__device__ float g_k   [BATCH*C*HW];
__device__ float g_v   [BATCH*C*HW];
__device__ float g_mu  [BATCH*C];
__device__ float g_rsig[BATCH*C];
// fp16 weights packed in per-thread m16n8k16 fragment order
__device__ uint4 g_wH3[3][72*8*32];    // 3x3 convs: [(ks*8+fr)*32+lane]
__device__ uint4 g_wH1[3][8*8*32];     // 1x1 convs

__constant__ int c_di[9] = {-1,-1,-1, 0,0,0, 1,1,1};
__constant__ int c_dj[9] = {-1, 0, 1,-1,0,1,-1,0,1};

__device__ __forceinline__ void mma_f16(float* d, const uint32_t* a, const uint32_t* b) {
    asm volatile(
        "mma.sync.aligned.m16n8k16.row.col.f32.f16.f16.f32 "
        "{%0,%1,%2,%3}, {%4,%5,%6,%7}, {%8,%9}, {%0,%1,%2,%3};"
        : "+f"(d[0]), "+f"(d[1]), "+f"(d[2]), "+f"(d[3])
        : "r"(a[0]), "r"(a[1]), "r"(a[2]), "r"(a[3]), "r"(b[0]), "r"(b[1]));
}
__device__ __forceinline__ uint32_t smem_u32(const void* p) {
    uint32_t a;
    asm("{ .reg .u64 t; cvta.to.shared.u64 t, %1; cvt.u32.u64 %0, t; }"
        : "=r"(a) : "l"(p));
    return a;
}
__device__ __forceinline__ uint32_t pk2(float lo, float hi) {
    __half2 h = __floats2half2_rn(lo, hi);
    return *(uint32_t*)&h;
}
__device__ __forceinline__ float h2lo(uint32_t w) {
    return __low2float(*(__half2*)&w);
}
__device__ __forceinline__ float h2hi(uint32_t w) {
    return __high2float(*(__half2*)&w);
}
#define CP_ASYNC16(dst, src) \
    asm volatile("cp.async.ca.shared.global [%0], [%1], 16;" :: "r"(dst), "l"(src))
#define CP_COMMIT() asm volatile("cp.async.commit_group;")
#define CP_WAIT0()  asm volatile("cp.async.wait_group 0;" ::: "memory")

// ---------------- weight packing (fp16 fragment order) ----------------------
__global__ void pack_weights(const float* __restrict__ w1, const float* __restrict__ w2,
                             const float* __restrict__ wm, const float* __restrict__ wq,
                             const float* __restrict__ wk, const float* __restrict__ wv)
{
    int idx = blockIdx.x * blockDim.x + threadIdx.x;
    int lane = idx & 31;
    int fr   = (idx >> 5) & 7;
    int rest = idx >> 8;
    {
        int ks   = rest % 72;
        int conv = rest / 72;
        if (conv < 3) {
            const float* w = (conv == 0) ? w1 : (conv == 1) ? w2 : wm;
            int m0  = fr*16 + (lane >> 2);
            int kq  = lane & 3;
            int tap = ks >> 3;
            int cb  = (ks & 7) << 4;
            int ca  = cb + 2*kq;
            int cc  = cb + 8 + 2*kq;
            uint4 o;
            o.x = pk2(w[ m0   *1152 + ca*9 + tap], w[ m0   *1152 + (ca+1)*9 + tap]);
            o.y = pk2(w[(m0+8)*1152 + ca*9 + tap], w[(m0+8)*1152 + (ca+1)*9 + tap]);
            o.z = pk2(w[ m0   *1152 + cc*9 + tap], w[ m0   *1152 + (cc+1)*9 + tap]);
            o.w = pk2(w[(m0+8)*1152 + cc*9 + tap], w[(m0+8)*1152 + (cc+1)*9 + tap]);
            g_wH3[conv][(ks*8 + fr)*32 + lane] = o;
        }
    }
    if (idx < 3*8*8*32) {
        int ks  = rest % 8;
        int set = rest / 8;
        const float* w = (set == 0) ? wq : (set == 1) ? wk : wv;
        int m0 = fr*16 + (lane >> 2);
        int kq = lane & 3;
        int cb = ks << 4;
        int ca = cb + 2*kq;
        int cc = cb + 8 + 2*kq;
        uint4 o;
        o.x = pk2(w[ m0   *128 + ca], w[ m0   *128 + ca+1]);
        o.y = pk2(w[(m0+8)*128 + ca], w[(m0+8)*128 + ca+1]);
        o.z = pk2(w[ m0   *128 + cc], w[ m0   *128 + cc+1]);
        o.w = pk2(w[(m0+8)*128 + cc], w[(m0+8)*128 + cc+1]);
        g_wH1[set][(ks*8 + fr)*32 + lane] = o;
    }
}

// ---------------- stats only (mu, rsig per (b,c)) ----------------------------
__global__ void __launch_bounds__(512)
stats_kernel()
{
    int bc = blockIdx.x;
    const float4* p = (const float4*)(g_y1 + (size_t)bc * HW);
    float s = 0.f, sq = 0.f;
    #pragma unroll
    for (int i = 0; i < 8; i++) {
        float4 v = p[threadIdx.x + 512*i];
        s  += (v.x + v.y) + (v.z + v.w);
        sq += v.x*v.x + v.y*v.y + v.z*v.z + v.w*v.w;
    }
    #pragma unroll
    for (int o = 16; o; o >>= 1) {
        s  += __shfl_xor_sync(0xffffffffu, s,  o);
        sq += __shfl_xor_sync(0xffffffffu, sq, o);
    }
    __shared__ float ss[16], sqq[16];
    int wrp = threadIdx.x >> 5;
    if ((threadIdx.x & 31) == 0) { ss[wrp] = s; sqq[wrp] = sq; }
    __syncthreads();
    if (threadIdx.x == 0) {
        float S = 0.f, Q = 0.f;
        #pragma unroll
        for (int i = 0; i < 16; i++) { S += ss[i]; Q += sqq[i]; }
        float mu  = S / (float)HW;
        float var = Q / (float)HW - mu*mu;
        g_mu[bc]   = mu;
        g_rsig[bc] = rsqrtf(var + 1e-5f);
    }
}

// ---------------- fp16 3x3 conv core (B-stationary tile) ---------------------
#define TPIX 204
#define TSTRIDE 68
#define CONV_SMEM (TPIX*TSTRIDE*4)     // 55488 B

// mainloop over one weight set; acc must be zeroed by caller
__device__ __forceinline__ void conv_pass(const uint32_t* tile, const uint4* wA,
                                          int mw, int nw, int lane,
                                          float acc[4][4][4])
{
    const int q = lane & 3, g = lane >> 2;
    uint4 aN[4];
    #pragma unroll
    for (int i = 0; i < 4; i++)
        aN[i] = wA[(mw*4 + i)*32 + lane];

    const int NR = 72;
    for (int r = 0; r < NR; r++) {
        uint4 aC[4];
        #pragma unroll
        for (int i = 0; i < 4; i++) aC[i] = aN[i];
        if (r + 1 < NR) {
            const uint4* src = wA + (size_t)(r + 1)*256;
            #pragma unroll
            for (int i = 0; i < 4; i++)
                aN[i] = src[(mw*4 + i)*32 + lane];
        }
        int tap = r >> 3;
        int cw  = ((r & 7) << 3) + q;
        int pxb = (nw + c_di[tap] + 1)*34 + c_dj[tap] + 1 + g;
        uint32_t bf[4][2];
        #pragma unroll
        for (int j = 0; j < 4; j++) {
            int off = (pxb + j*8)*TSTRIDE + cw;
            bf[j][0] = tile[off];
            bf[j][1] = tile[off + 4];
        }
        #pragma unroll
        for (int i = 0; i < 4; i++)
            #pragma unroll
            for (int j = 0; j < 4; j++)
                mma_f16(acc[i][j], (const uint32_t*)&aC[i], bf[j]);
    }
}

// ---------------- conv1: raw x -> y1 -----------------------------------------
__global__ void __launch_bounds__(256, 2)
conv1_kernel(const float* __restrict__ in, const float* __restrict__ bias)
{
    extern __shared__ uint32_t tile[];

    const int tid  = threadIdx.x;
    const int lane = tid & 31, wid = tid >> 5;
    const int mw = wid >> 2, nw = wid & 3;
    const int b  = blockIdx.y;
    const int h0 = (blockIdx.x >> 2) << 2;
    const int w0 = (blockIdx.x & 3) << 5;

    #pragma unroll 4
    for (int pp = 0; pp < 51; pp++) {
        int idx  = pp*256 + tid;
        int pair = idx / 204;
        int pix  = idx - pair*204;
        int pr = pix / 34, pc = pix - pr*34;
        int ih = h0 + pr - 1, iw = w0 + pc - 1;
        float v0 = 0.f, v1 = 0.f;
        if (((unsigned)ih < (unsigned)H) && ((unsigned)iw < (unsigned)W)) {
            const float* s = in + ((size_t)(b*C + 2*pair) << 14) + (size_t)ih*W + iw;
            v0 = s[0];
            v1 = s[(size_t)1 << 14];
        }
        tile[pix*TSTRIDE + pair] = pk2(v0, v1);
    }
    __syncthreads();

    float acc[4][4][4];
    #pragma unroll
    for (int i = 0; i < 4; i++)
        #pragma unroll
        for (int j = 0; j < 4; j++)
            #pragma unroll
            for (int r = 0; r < 4; r++) acc[i][j][r] = 0.f;

    conv_pass(tile, g_wH3[0], mw, nw, lane, acc);

    const int q = lane & 3, g = lane >> 2;
    #pragma unroll
    for (int i = 0; i < 4; i++) {
        int m0 = mw*64 + i*16 + g;
        float bb0 = bias[m0], bb1 = bias[m0 + 8];
        size_t ob = ((size_t)(b*C + m0) << 14) + (size_t)(h0 + nw)*W + w0;
        #pragma unroll
        for (int j = 0; j < 4; j++) {
            int co = j*8 + q*2;
            *(float2*)(g_y1 + ob + co) =
                make_float2(acc[i][j][0] + bb0, acc[i][j][1] + bb0);
            *(float2*)(g_y1 + ob + (8 << 14) + co) =
                make_float2(acc[i][j][2] + bb1, acc[i][j][3] + bb1);
        }
    }
}

// ---------------- merged conv2 + mask: one staged t-tile, two passes ---------
__global__ void __launch_bounds__(256, 2)
conv2m_kernel(const float* __restrict__ b2, const float* __restrict__ bm)
{
    extern __shared__ uint32_t tile[];

    const int tid  = threadIdx.x;
    const int lane = tid & 31, wid = tid >> 5;
    const int mw = wid >> 2, nw = wid & 3;
    const int b  = blockIdx.y;
    const int h0 = (blockIdx.x >> 2) << 2;
    const int w0 = (blockIdx.x & 3) << 5;
    const int q = lane & 3, g = lane >> 2;

    const float* mup = g_mu   + b*C;
    const float* rsp = g_rsig + b*C;

    // stage t = leaky(norm(y1)) as fp16
    #pragma unroll 4
    for (int pp = 0; pp < 51; pp++) {
        int idx  = pp*256 + tid;
        int pair = idx / 204;
        int pix  = idx - pair*204;
        int pr = pix / 34, pc = pix - pr*34;
        int ih = h0 + pr - 1, iw = w0 + pc - 1;
        float v0 = 0.f, v1 = 0.f;
        if (((unsigned)ih < (unsigned)H) && ((unsigned)iw < (unsigned)W)) {
            const float* s = g_y1 + ((size_t)(b*C + 2*pair) << 14) + (size_t)ih*W + iw;
            float y0 = s[0], y1v = s[(size_t)1 << 14];
            float t0 = (y0  - mup[2*pair])   * rsp[2*pair];
            float t1 = (y1v - mup[2*pair+1]) * rsp[2*pair+1];
            v0 = (t0 < 0.f) ? 0.2f*t0 : t0;
            v1 = (t1 < 0.f) ? 0.2f*t1 : t1;
        }
        tile[pix*TSTRIDE + pair] = pk2(v0, v1);
    }
    __syncthreads();

    float acc[4][4][4];

    // ---- pass 1: conv2 -> out1 ----
    #pragma unroll
    for (int i = 0; i < 4; i++)
        #pragma unroll
        for (int j = 0; j < 4; j++)
            #pragma unroll
            for (int r = 0; r < 4; r++) acc[i][j][r] = 0.f;
    conv_pass(tile, g_wH3[1], mw, nw, lane, acc);
    #pragma unroll
    for (int i = 0; i < 4; i++) {
        int m0 = mw*64 + i*16 + g;
        float bb0 = b2[m0], bb1 = b2[m0 + 8];
        size_t ob = ((size_t)(b*C + m0) << 14) + (size_t)(h0 + nw)*W + w0;
        #pragma unroll
        for (int j = 0; j < 4; j++) {
            int co = j*8 + q*2;
            *(float2*)(g_out1 + ob + co) =
                make_float2(acc[i][j][0] + bb0, acc[i][j][1] + bb0);
            *(float2*)(g_out1 + ob + (8 << 14) + co) =
                make_float2(acc[i][j][2] + bb1, acc[i][j][3] + bb1);
        }
    }

    // ---- pass 2: mask -> m, xm = t*m (t from staged fp16 tile) ----
    #pragma unroll
    for (int i = 0; i < 4; i++)
        #pragma unroll
        for (int j = 0; j < 4; j++)
            #pragma unroll
            for (int r = 0; r < 4; r++) acc[i][j][r] = 0.f;
    conv_pass(tile, g_wH3[2], mw, nw, lane, acc);
    #pragma unroll
    for (int i = 0; i < 4; i++) {
        int m0 = mw*64 + i*16 + g;
        int mh = m0 >> 1;
        int par = m0 & 1;
        float bb0 = bm[m0], bb1 = bm[m0 + 8];
        size_t ob = ((size_t)(b*C + m0) << 14) + (size_t)(h0 + nw)*W + w0;
        #pragma unroll
        for (int j = 0; j < 4; j++) {
            int co = j*8 + q*2;
            int pix = (nw + 1)*34 + co + 1;
            uint32_t wa0 = tile[ pix     *TSTRIDE + mh];
            uint32_t wa1 = tile[(pix + 1)*TSTRIDE + mh];
            uint32_t wb0 = tile[ pix     *TSTRIDE + mh + 4];
            uint32_t wb1 = tile[(pix + 1)*TSTRIDE + mh + 4];
            float t00 = par ? h2hi(wa0) : h2lo(wa0);
            float t01 = par ? h2hi(wa1) : h2lo(wa1);
            float t10 = par ? h2hi(wb0) : h2lo(wb0);
            float t11 = par ? h2hi(wb1) : h2lo(wb1);
            float s0 = 1.f/(1.f + __expf(-(acc[i][j][0] + bb0)));
            float s1 = 1.f/(1.f + __expf(-(acc[i][j][1] + bb0)));
            float s2 = 1.f/(1.f + __expf(-(acc[i][j][2] + bb1)));
            float s3 = 1.f/(1.f + __expf(-(acc[i][j][3] + bb1)));
            *(float2*)(g_m + ob + co)             = make_float2(s0, s1);
            *(float2*)(g_m + ob + (8 << 14) + co) = make_float2(s2, s3);
            *(float2*)(g_xm + ob + co)             = make_float2(s0*t00, s1*t01);
            *(float2*)(g_xm + ob + (8 << 14) + co) = make_float2(s2*t10, s3*t11);
        }
    }
}

// ---------------- merged q/k/v 1x1 GEMM (shared fp16 B staging) --------------
#define BP 136
__global__ void __launch_bounds__(256, 2)
conv_qkv(const float* __restrict__ bq, const float* __restrict__ bk,
         const float* __restrict__ bv_)
{
    __shared__ uint32_t Bsq[8][8*BP];
    __shared__ uint4    Asq[2][256];

    const int tid  = threadIdx.x;
    const int lane = tid & 31, wid = tid >> 5;
    const int mw = wid >> 2, nw = wid & 3;
    const int b  = blockIdx.y;
    const int h0 = (blockIdx.x >> 2) << 2;
    const int w0 = (blockIdx.x & 3) << 5;

    const int sub  = tid >> 7;
    const int nn   = tid & 127;
    const int prow = nn >> 5, pcol = nn & 31;

    const uint32_t aBase = smem_u32(&Asq[0][0]);
    auto cpA = [&](const uint4* wA, int r, int buf) {
        CP_ASYNC16(aBase + ((buf*256 + tid) << 4), wA + (size_t)r*256 + tid);
        CP_COMMIT();
    };

    {
        const float* src0 = (const float*)g_xm + ((size_t)(b*C) << 14)
                          + (size_t)(h0 + prow)*W + (w0 + pcol);
        #pragma unroll
        for (int ks = 0; ks < 8; ks++) {
            const float* src = src0 + ((size_t)(ks*16 + sub*8) << 14);
            float vb[8];
            #pragma unroll
            for (int j = 0; j < 8; j++)
                vb[j] = src[(size_t)j << 14];
            #pragma unroll
            for (int p = 0; p < 4; p++)
                Bsq[ks][(sub*4 + p)*BP + nn] = pk2(vb[2*p], vb[2*p + 1]);
        }
    }

    for (int set = 0; set < 3; set++) {
        const uint4* wA = g_wH1[set];
        const float* bias = (set == 0) ? bq : (set == 1) ? bk : bv_;
        float* out = (set == 0) ? g_q : (set == 1) ? g_k : g_v;

        float acc[4][4][4];
        #pragma unroll
        for (int i = 0; i < 4; i++)
            #pragma unroll
            for (int j = 0; j < 4; j++)
                #pragma unroll
                for (int r = 0; r < 4; r++) acc[i][j][r] = 0.f;

        cpA(wA, 0, 0);
        CP_WAIT0();
        __syncthreads();

        for (int r = 0; r < 8; r++) {
            int buf = r & 1;
            if (r + 1 < 8) cpA(wA, r + 1, buf ^ 1);
            uint4 af[4];
            #pragma unroll
            for (int i = 0; i < 4; i++)
                af[i] = Asq[buf][(mw*4 + i)*32 + lane];
            uint32_t bf[4][2];
            const int q = lane & 3;
            #pragma unroll
            for (int j = 0; j < 4; j++) {
                int n = nw*32 + j*8 + (lane >> 2);
                bf[j][0] = Bsq[r][ q     *BP + n];
                bf[j][1] = Bsq[r][(4 + q)*BP + n];
            }
            #pragma unroll
            for (int i = 0; i < 4; i++)
                #pragma unroll
                for (int j = 0; j < 4; j++)
                    mma_f16(acc[i][j], (const uint32_t*)&af[i], bf[j]);
            if (r + 1 < 8) {
                CP_WAIT0();
                __syncthreads();
            }
        }

        #pragma unroll
        for (int i = 0; i < 4; i++) {
            int m0 = mw*64 + i*16 + (lane >> 2);
            float bb0 = bias[m0], bb1 = bias[m0 + 8];
            size_t ob = ((size_t)(b*C + m0) << 14) + (size_t)(h0 + nw)*W + w0;
            #pragma unroll
            for (int j = 0; j < 4; j++) {
                int co = j*8 + (lane & 3)*2;
                *(float2*)(out + ob + co) =
                    make_float2(acc[i][j][0] + bb0, acc[i][j][1] + bb0);
                *(float2*)(out + ob + (8 << 14) + co) =
                    make_float2(acc[i][j][2] + bb1, acc[i][j][3] + bb1);
            }
        }
        __syncthreads();
    }
}

// ---------------- local 3x3 attention + blend + residual --------------------
// 8-way channel split (16 ch each), 1 row/CTA (1024 CTAs), edge taps via
// warp shuffle, channel loop unrolled x2 for MLP.
__global__ void __launch_bounds__(256)
attn_kernel(const float* __restrict__ x, const float* __restrict__ k_b,
            const float* __restrict__ v_b, float* __restrict__ out)
{
    __shared__ float att[8][32][37];

    const int b    = blockIdx.y;
    const int tid  = threadIdx.x;
    const int cg   = tid >> 5;
    const int lane = tid & 31;
    const int h    = blockIdx.x;
    const int wq   = lane*4;
    const size_t bbase = (size_t)b*C*HW;
    const int poff = h*W + wq;
    const int c0 = cg*16;

    float sims[9][4];
    #pragma unroll
    for (int o = 0; o < 9; o++)
        #pragma unroll
        for (int p = 0; p < 4; p++) sims[o][p] = 0.f;

    #pragma unroll 2
    for (int ci = 0; ci < 16; ci++) {
        int c = c0 + ci;
        const float* kp = g_k + bbase + ((size_t)c << 14);
        float kbv = __ldg(k_b + c);
        float4 qv = *(const float4*)(g_q + bbase + ((size_t)c << 14) + poff);
        float q[4] = {qv.x, qv.y, qv.z, qv.w};
        #pragma unroll
        for (int dr = 0; dr < 3; dr++) {
            int hh = h + dr - 1;
            bool rok = ((unsigned)hh < (unsigned)H);
            float4 mid = rok ? *(const float4*)(kp + hh*W + wq)
                             : make_float4(kbv, kbv, kbv, kbv);
            float lf = __shfl_up_sync(0xffffffffu, mid.w, 1);
            if (lane == 0)  lf = kbv;
            float rt = __shfl_down_sync(0xffffffffu, mid.x, 1);
            if (lane == 31) rt = kbv;
            float val[6] = {lf, mid.x, mid.y, mid.z, mid.w, rt};
            #pragma unroll
            for (int dj = 0; dj < 3; dj++)
                #pragma unroll
                for (int p = 0; p < 4; p++)
                    sims[dr*3 + dj][p] = fmaf(q[p], val[p + dj], sims[dr*3 + dj][p]);
        }
    }

    #pragma unroll
    for (int o = 0; o < 9; o++)
        #pragma unroll
        for (int p = 0; p < 4; p++)
            att[cg][lane][o*4 + p] = sims[o][p];
    __syncthreads();

    #pragma unroll
    for (int o = 0; o < 9; o++) {
        #pragma unroll
        for (int p = 0; p < 4; p++) {
            float s = 0.f;
            #pragma unroll
            for (int gr = 0; gr < 8; gr++)
                s += att[gr][lane][o*4 + p];
            sims[o][p] = s;
        }
    }
    #pragma unroll
    for (int p = 0; p < 4; p++) {
        float mx = sims[0][p];
        #pragma unroll
        for (int o = 1; o < 9; o++) mx = fmaxf(mx, sims[o][p]);
        float se = 0.f;
        #pragma unroll
        for (int o = 0; o < 9; o++) { sims[o][p] = __expf(sims[o][p] - mx); se += sims[o][p]; }
        float inv = 1.f / se;
        #pragma unroll
        for (int o = 0; o < 9; o++) sims[o][p] *= inv;
    }

    #pragma unroll 2
    for (int ci = 0; ci < 16; ci++) {
        int c = c0 + ci;
        const float* vp = g_v + bbase + ((size_t)c << 14);
        float vbv = __ldg(v_b + c);
        float o2[4] = {0.f, 0.f, 0.f, 0.f};
        #pragma unroll
        for (int dr = 0; dr < 3; dr++) {
            int hh = h + dr - 1;
            bool rok = ((unsigned)hh < (unsigned)H);
            float4 mid = rok ? *(const float4*)(vp + hh*W + wq)
                             : make_float4(vbv, vbv, vbv, vbv);
            float lf = __shfl_up_sync(0xffffffffu, mid.w, 1);
            if (lane == 0)  lf = vbv;
            float rt = __shfl_down_sync(0xffffffffu, mid.x, 1);
            if (lane == 31) rt = vbv;
            float val[6] = {lf, mid.x, mid.y, mid.z, mid.w, rt};
            #pragma unroll
            for (int dj = 0; dj < 3; dj++)
                #pragma unroll
                for (int p = 0; p < 4; p++)
                    o2[p] = fmaf(sims[dr*3 + dj][p], val[p + dj], o2[p]);
        }
        size_t idx = bbase + ((size_t)c << 14) + poff;
        float4 mv = *(const float4*)(g_m    + idx);
        float4 o1 = *(const float4*)(g_out1 + idx);
        float4 xv = *(const float4*)(x      + idx);
        float4 ov;
        ov.x = xv.x + o1.x*mv.x + (1.f - mv.x)*o2[0];
        ov.y = xv.y + o1.y*mv.y + (1.f - mv.y)*o2[1];
        ov.z = xv.z + o1.z*mv.z + (1.f - mv.z)*o2[2];
        ov.w = xv.w + o1.w*mv.w + (1.f - mv.w)*o2[3];
        *(float4*)(out + idx) = ov;
    }
}

// ---------------- launch ----------------------------------------------------
extern "C" void kernel_launch(void* const* d_in, const int* in_sizes, int n_in,
                              void* d_out, int out_size)
{
    const float* x  = (const float*)d_in[0];
    const float* w1 = (const float*)d_in[1];
    const float* b1 = (const float*)d_in[2];
    const float* w2 = (const float*)d_in[3];
    const float* b2 = (const float*)d_in[4];
    const float* wm = (const float*)d_in[5];
    const float* bm = (const float*)d_in[6];
    const float* wq = (const float*)d_in[7];
    const float* bq = (const float*)d_in[8];
    const float* wk = (const float*)d_in[9];
    const float* bk = (const float*)d_in[10];
    const float* wv = (const float*)d_in[11];
    const float* bv = (const float*)d_in[12];
    float* out = (float*)d_out;

    cudaFuncSetAttribute(conv1_kernel,  cudaFuncAttributeMaxDynamicSharedMemorySize, CONV_SMEM);
    cudaFuncSetAttribute(conv2m_kernel, cudaFuncAttributeMaxDynamicSharedMemorySize, CONV_SMEM);

    pack_weights<<<216, 256>>>(w1, w2, wm, wq, wk, wv);

    dim3 gc(128, BATCH);
    conv1_kernel<<<gc, 256, CONV_SMEM>>>(x, b1);
    stats_kernel<<<BATCH*C, 512>>>();
    conv2m_kernel<<<gc, 256, CONV_SMEM>>>(b2, bm);
    conv_qkv<<<gc, 256>>>(bq, bk, bv);

    dim3 ga(H, BATCH);
    attn_kernel<<<ga, 256>>>(x, bk, bv, out);
}